// round 1
// baseline (speedup 1.0000x reference)
#include <cuda_runtime.h>
#include <cuda_bf16.h>
#include <math.h>

// Problem dims
#define BB 256
#define NN 77
#define DD 768
#define KK 16
#define DN 768
#define HID 512
#define NL 2
#define MTOT (BB*KK)          // 4096
#define SCALE 0.10206207261596575f   // (768/8)^-0.5

// ---------------- scratch (device globals; no allocation) ----------------
__device__ float g_Q[KK*DN];        // Q = q@Wq + bq       [16,768]
__device__ float g_Pt[DD*KK];       // P^T: [j][k], P = Q@Wk^T
__device__ float g_c[KK];           // c[k] = Q[k].bk
__device__ float g_U[MTOT*DN];      // S^T w               [4096,768]
__device__ float g_V[MTOT*DN];      // current V           [4096,768]
__device__ float g_rowsum[MTOT];    // sum_n S[n,k] per (b,k)
__device__ float g_H[MTOT*2*HID];   // [m][1024] = hi | hj
__device__ float g_M[MTOT*DN];      // V@Wg[l]+bg[l]
__device__ float g_A[BB*KK*KK];     // edge softmax

// ---------------- kQ: Q = node_queries @ Wq + bq ----------------
// grid 48 x 256 ; block covers one k (768/256=3 blocks per k)
__global__ void kQ(const float* __restrict__ nq, const float* __restrict__ Wq,
                   const float* __restrict__ bq) {
    int k = blockIdx.x / 3;
    int d = (blockIdx.x % 3) * 256 + threadIdx.x;
    float acc = 0.f;
    const float* qrow = nq + k * DN;
    #pragma unroll 4
    for (int e = 0; e < DN; e++) acc += qrow[e] * Wq[e * DN + d];
    g_Q[k * DN + d] = acc + bq[d];
}

// ---------------- kP: P^T[j][k] = Q[k].Wk[j,:] ; c[k] = Q[k].bk ----------
// grid 48 x 256 : j = blk*16 + tid/16 ; k = tid%16
__global__ void kP(const float* __restrict__ Wk, const float* __restrict__ bk) {
    int j = blockIdx.x * 16 + (threadIdx.x >> 4);
    int k = threadIdx.x & 15;
    const float* qrow = g_Q + k * DN;
    const float* wrow = Wk + j * DN;
    float acc = 0.f;
    #pragma unroll 4
    for (int e = 0; e < DN; e++) acc += qrow[e] * wrow[e];
    g_Pt[j * KK + k] = acc;
    if (blockIdx.x == 0 && threadIdx.x < KK) {
        const float* qr = g_Q + threadIdx.x * DN;
        float cc = 0.f;
        for (int e = 0; e < DN; e++) cc += qr[e] * bk[e];
        g_c[threadIdx.x] = cc;
    }
}

// ---------------- kAttn: scores -> softmax(S) -> U = S^T w --------------
// grid = B (256), 256 threads
__global__ void kAttn(const float* __restrict__ w, const int* __restrict__ mask,
                      float* __restrict__ outS) {
    int b = blockIdx.x;
    int tid = threadIdx.x;
    int ty = tid >> 4, tx = tid & 15;   // ty = k in pass1
    __shared__ float sW[NN * 65];       // [n][dd] pitch 65
    __shared__ float sP[64 * KK];       // [dd][k]
    __shared__ float sSc[KK * 80];      // scores [k][n] pitch 80
    __shared__ float sSm[NN * KK];      // S [n][k]

    float acc[5] = {0.f, 0.f, 0.f, 0.f, 0.f};
    for (int d0 = 0; d0 < DD; d0 += 64) {
        for (int idx = tid; idx < NN * 64; idx += 256) {
            int n = idx >> 6, dd = idx & 63;
            sW[n * 65 + dd] = w[(b * NN + n) * DD + d0 + dd];
        }
        for (int idx = tid; idx < 64 * KK; idx += 256)
            sP[idx] = g_Pt[d0 * KK + idx];
        __syncthreads();
        #pragma unroll
        for (int i = 0; i < 5; i++) {
            int n = tx + 16 * i;
            if (n < NN) {
                float a = acc[i];
                #pragma unroll 8
                for (int dd = 0; dd < 64; dd++)
                    a += sP[dd * KK + ty] * sW[n * 65 + dd];
                acc[i] = a;
            }
        }
        __syncthreads();
    }
    float ck = g_c[ty];
    #pragma unroll
    for (int i = 0; i < 5; i++) {
        int n = tx + 16 * i;
        if (n < NN) sSc[ty * 80 + n] = (acc[i] + ck) * SCALE;
    }
    __syncthreads();

    // softmax over k for each token n (threads 0..76)
    if (tid < NN) {
        int n = tid;
        if (mask[b * NN + n] == 0) {
            #pragma unroll
            for (int k = 0; k < KK; k++) sSm[n * KK + k] = 1.0f / 16.0f;
        } else {
            float m = -3.4e38f;
            #pragma unroll
            for (int k = 0; k < KK; k++) m = fmaxf(m, sSc[k * 80 + n]);
            float e[KK]; float s = 0.f;
            #pragma unroll
            for (int k = 0; k < KK; k++) { e[k] = __expf(sSc[k * 80 + n] - m); s += e[k]; }
            float inv = 1.0f / s;
            #pragma unroll
            for (int k = 0; k < KK; k++) sSm[n * KK + k] = e[k] * inv;
        }
        #pragma unroll
        for (int k = 0; k < KK; k++)
            outS[(b * NN + n) * KK + k] = sSm[n * KK + k];
    }
    __syncthreads();
    if (tid < KK) {
        float s = 0.f;
        for (int n = 0; n < NN; n++) s += sSm[n * KK + tid];
        g_rowsum[b * KK + tid] = s;
    }

    // pass2: U[k][d] = sum_n S[n][k] * w[b,n,d]; thread owns d = tid,+256,+512
    float au[KK][3];
    #pragma unroll
    for (int k = 0; k < KK; k++) { au[k][0] = 0.f; au[k][1] = 0.f; au[k][2] = 0.f; }
    for (int n = 0; n < NN; n++) {
        const float* wr = w + (b * NN + n) * DD + tid;
        float w0 = wr[0], w1 = wr[256], w2 = wr[512];
        #pragma unroll
        for (int k = 0; k < KK; k++) {
            float s = sSm[n * KK + k];
            au[k][0] += s * w0; au[k][1] += s * w1; au[k][2] += s * w2;
        }
    }
    #pragma unroll
    for (int k = 0; k < KK; k++) {
        float* ur = g_U + (b * KK + k) * DN + tid;
        ur[0] = au[k][0]; ur[256] = au[k][1]; ur[512] = au[k][2];
    }
}

// ---------------- kGemm: C[4096,N] = A[4096,768] @ B[768,N] + epilogue ----
// mode 0: A=g_V, B=We1 (split 1024 cols), C=g_H
// mode 1: A=g_U, B=Wv, C=g_V  (+ rowsum*bv, gate mix with node_queries)
// mode 2: A=g_V, B=Wg[l], C=g_M (+ bg[l])
__global__ __launch_bounds__(256, 2) void kGemm(
    const float* __restrict__ Bmat, int mode,
    const float* __restrict__ bias, const float* __restrict__ nq,
    const float* __restrict__ gatep) {
    const int m0 = blockIdx.x * 128;
    const int n0 = blockIdx.y * 128;
    const float* A; float* C; int ldb, Ncols;
    if (mode == 0) {
        A = g_V; C = g_H; Ncols = 2 * HID; ldb = HID;
        Bmat += (n0 < HID) ? n0 : (DN * HID + n0 - HID);
    } else if (mode == 1) {
        A = g_U; C = g_V; Ncols = DN; ldb = DN; Bmat += n0;
    } else {
        A = g_V; C = g_M; Ncols = DN; ldb = DN; Bmat += n0;
    }
    __shared__ float sA[128 * 12];   // [row][k] pitch 12
    __shared__ float sB[8 * 132];    // [k][col] pitch 132

    const int tid = threadIdx.x;
    const int tx = tid & 15, ty = tid >> 4;
    const int arow = tid >> 1, acol4 = (tid & 1) * 4;
    const int brow = tid >> 5, bcol4 = (tid & 31) * 4;

    const float* Aptr = A + (m0 + arow) * DN + acol4;
    const float* Bptr = Bmat + brow * ldb + bcol4;
    float4 ra = *(const float4*)Aptr;
    float4 rb = *(const float4*)Bptr;

    float acc[8][8];
    #pragma unroll
    for (int i = 0; i < 8; i++)
        #pragma unroll
        for (int j = 0; j < 8; j++) acc[i][j] = 0.f;

    for (int kt = 0; kt < DN / 8; kt++) {
        *(float4*)(sA + arow * 12 + acol4) = ra;
        *(float4*)(sB + brow * 132 + bcol4) = rb;
        __syncthreads();
        if (kt < DN / 8 - 1) {
            Aptr += 8; Bptr += 8 * ldb;
            ra = *(const float4*)Aptr;
            rb = *(const float4*)Bptr;
        }
        #pragma unroll
        for (int kk = 0; kk < 8; kk++) {
            float a[8], bb[8];
            #pragma unroll
            for (int i = 0; i < 4; i++) {
                a[i]     = sA[(ty * 4 + i) * 12 + kk];
                a[4 + i] = sA[(64 + ty * 4 + i) * 12 + kk];
            }
            float4 b0 = *(float4*)(sB + kk * 132 + tx * 4);
            float4 b1 = *(float4*)(sB + kk * 132 + 64 + tx * 4);
            bb[0] = b0.x; bb[1] = b0.y; bb[2] = b0.z; bb[3] = b0.w;
            bb[4] = b1.x; bb[5] = b1.y; bb[6] = b1.z; bb[7] = b1.w;
            #pragma unroll
            for (int i = 0; i < 8; i++)
                #pragma unroll
                for (int j = 0; j < 8; j++) acc[i][j] += a[i] * bb[j];
        }
        __syncthreads();
    }

    float gate = 0.f;
    if (mode == 1) gate = 1.0f / (1.0f + expf(-gatep[0]));
    #pragma unroll
    for (int i = 0; i < 8; i++) {
        int row = (i < 4) ? (ty * 4 + i) : (64 + ty * 4 + i - 4);
        int m = m0 + row;
        int kq = m & 15;
        #pragma unroll
        for (int j = 0; j < 8; j++) {
            int col = (j < 4) ? (tx * 4 + j) : (64 + tx * 4 + j - 4);
            int n = n0 + col;
            float v = acc[i][j];
            if (mode == 1) {
                v += g_rowsum[m] * bias[n];
                v = (1.0f - gate) * v + gate * nq[kq * DN + n];
            } else if (mode == 2) {
                v += bias[n];
            }
            C[m * Ncols + n] = v;
        }
    }
}

// ---------------- kEdge: E[b,i,j] = sum_h relu(hi+hj+be1)*We2 + be2 ------
// post=0: compute A = softmax_j(E) -> g_A ; post=1: write E to out
__global__ void kEdge(const float* __restrict__ be1, const float* __restrict__ We2,
                      const float* __restrict__ be2, float* __restrict__ outE,
                      int post) {
    int b = blockIdx.x;
    int tid = threadIdx.x;
    int i = tid >> 4, j = tid & 15;
    __shared__ float sHi[KK * 257];
    __shared__ float sHj[KK * 257];
    __shared__ float sW2[256];
    __shared__ float sE[KK * 17];

    float acc = 0.f;
    for (int h0 = 0; h0 < HID; h0 += 256) {
        for (int idx = tid; idx < KK * 256; idx += 256) {
            int r = idx >> 8, c = idx & 255;
            sHi[r * 257 + c] = g_H[(b * KK + r) * (2 * HID) + h0 + c] + be1[h0 + c];
            sHj[r * 257 + c] = g_H[(b * KK + r) * (2 * HID) + HID + h0 + c];
        }
        sW2[tid] = We2[h0 + tid];
        __syncthreads();
        const float* hi = sHi + i * 257;
        const float* hj = sHj + j * 257;
        #pragma unroll 8
        for (int c = 0; c < 256; c++)
            acc += fmaxf(hi[c] + hj[c], 0.f) * sW2[c];
        __syncthreads();
    }
    float E = acc + be2[0];
    if (post) {
        outE[b * 256 + tid] = E;
    } else {
        sE[i * 17 + j] = E;
        __syncthreads();
        float m = -3.4e38f;
        #pragma unroll
        for (int jj = 0; jj < KK; jj++) m = fmaxf(m, sE[i * 17 + jj]);
        float s = 0.f;
        #pragma unroll
        for (int jj = 0; jj < KK; jj++) s += __expf(sE[i * 17 + jj] - m);
        g_A[b * 256 + tid] = __expf(E - m) / s;
    }
}

// ---------------- kMsg: V += relu(A @ M) ------------------------------
__global__ void kMsg() {
    int b = blockIdx.x;
    int tid = threadIdx.x;
    __shared__ float sAm[KK * 17];
    sAm[(tid >> 4) * 17 + (tid & 15)] = g_A[b * 256 + tid];
    __syncthreads();
    float acc[KK][3];
    #pragma unroll
    for (int i = 0; i < KK; i++) { acc[i][0] = 0.f; acc[i][1] = 0.f; acc[i][2] = 0.f; }
    for (int j = 0; j < KK; j++) {
        const float* mr = g_M + (b * KK + j) * DN + tid;
        float m0 = mr[0], m1 = mr[256], m2 = mr[512];
        #pragma unroll
        for (int i = 0; i < KK; i++) {
            float a = sAm[i * 17 + j];
            acc[i][0] += a * m0; acc[i][1] += a * m1; acc[i][2] += a * m2;
        }
    }
    #pragma unroll
    for (int i = 0; i < KK; i++) {
        float* vr = g_V + (b * KK + i) * DN + tid;
        vr[0]   += fmaxf(acc[i][0], 0.f);
        vr[256] += fmaxf(acc[i][1], 0.f);
        vr[512] += fmaxf(acc[i][2], 0.f);
    }
}

// ---------------- kCopyV --------------------------------------------------
__global__ void kCopyV(float* __restrict__ outV) {
    int idx = blockIdx.x * 1024 + threadIdx.x;
    outV[idx] = g_V[idx];
}

// ---------------- host ----------------------------------------------------
extern "C" void kernel_launch(void* const* d_in, const int* in_sizes, int n_in,
                              void* d_out, int out_size) {
    const float* w    = (const float*)d_in[0];
    const int*   mask = (const int*)  d_in[1];
    const float* nq   = (const float*)d_in[2];
    const float* Wq   = (const float*)d_in[3];
    const float* bq   = (const float*)d_in[4];
    const float* Wk   = (const float*)d_in[5];
    const float* bk   = (const float*)d_in[6];
    const float* Wv   = (const float*)d_in[7];
    const float* bv   = (const float*)d_in[8];
    const float* We1  = (const float*)d_in[9];
    const float* be1  = (const float*)d_in[10];
    const float* We2  = (const float*)d_in[11];
    const float* be2  = (const float*)d_in[12];
    const float* fg   = (const float*)d_in[13];
    const float* Wg   = (const float*)d_in[14];
    const float* bg   = (const float*)d_in[15];

    float* outS = (float*)d_out;
    float* outV = outS + (size_t)BB * NN * KK;
    float* outE = outV + (size_t)BB * KK * DN;

    kQ<<<48, 256>>>(nq, Wq, bq);
    kP<<<48, 256>>>(Wk, bk);
    kAttn<<<BB, 256>>>(w, mask, outS);
    kGemm<<<dim3(32, 6), 256>>>(Wv, 1, bv, nq, fg);           // V = U@Wv (+bv term, gate)
    kGemm<<<dim3(32, 8), 256>>>(We1, 0, nullptr, nullptr, nullptr); // H = V@We1 (split)
    kEdge<<<BB, 256>>>(be1, We2, be2, nullptr, 0);            // A = softmax(E)
    for (int l = 0; l < NL; l++) {
        kGemm<<<dim3(32, 6), 256>>>(Wg + (size_t)l * DN * DN, 2, bg + l * DN,
                                    nullptr, nullptr);        // M = V@Wg[l]+bg[l]
        kMsg<<<BB, 256>>>();                                  // V += relu(A@M)
    }
    kGemm<<<dim3(32, 8), 256>>>(We1, 0, nullptr, nullptr, nullptr); // H on final V
    kEdge<<<BB, 256>>>(be1, We2, be2, outE, 1);               // E -> out
    kCopyV<<<(BB * KK * DN) / 1024, 1024>>>(outV);
}

// round 3
// speedup vs baseline: 1.0502x; 1.0502x over previous
#include <cuda_runtime.h>
#include <cuda_bf16.h>
#include <math.h>
#include <stdint.h>

// Problem dims
#define BB 256
#define NN 77
#define DD 768
#define KK 16
#define DN 768
#define HID 512
#define NL 2
#define MTOT (BB*KK)          // 4096
#define SCALE 0.10206207261596575f   // (768/8)^-0.5
#define KSPLIT 2304           // 3*768 (split-K concat)
#define KCH 72                // 2304/32 chunks
#define ROWU4 288             // 2304 bf16 / 8 per uint4

// ---------------- scratch (device globals; no allocation) ----------------
__device__ float g_Q[KK*DN];
__device__ float g_Pt[DD*KK];
__device__ float g_c[KK];
__device__ float g_U[MTOT*DN];
__device__ float g_V[MTOT*DN];
__device__ float g_rowsum[MTOT];
__device__ float g_H[MTOT*2*HID];
__device__ float g_M[MTOT*DN];
__device__ float g_A[BB*KK*KK];
// split-bf16 operand buffers (uint4 for 16B alignment)
__device__ uint4 g_Abf [(size_t)MTOT*KSPLIT/8];   // [4096][2304] bf16
__device__ uint4 g_WbfV [768*KSPLIT/8];           // [768][2304]
__device__ uint4 g_WbfG0[768*KSPLIT/8];
__device__ uint4 g_WbfG1[768*KSPLIT/8];
__device__ uint4 g_WbfE1[1024*KSPLIT/8];          // [1024][2304]

__device__ __forceinline__ uint32_t smem_u32(const void* p) {
    uint32_t a;
    asm("{ .reg .u64 t; cvta.to.shared.u64 t, %1; cvt.u32.u64 %0, t; }"
        : "=r"(a) : "l"(p));
    return a;
}

__device__ __forceinline__ unsigned packbf2(float a, float b) {
    unsigned short lo = __bfloat16_as_ushort(__float2bfloat16(a));
    unsigned short hi = __bfloat16_as_ushort(__float2bfloat16(b));
    return ((unsigned)hi << 16) | lo;
}

// ---------------- kQ: Q = node_queries @ Wq + bq ----------------
__global__ void kQ(const float* __restrict__ nq, const float* __restrict__ Wq,
                   const float* __restrict__ bq) {
    int k = blockIdx.x / 3;
    int d = (blockIdx.x % 3) * 256 + threadIdx.x;
    float acc = 0.f;
    const float* qrow = nq + k * DN;
    #pragma unroll 4
    for (int e = 0; e < DN; e++) acc += qrow[e] * Wq[e * DN + d];
    g_Q[k * DN + d] = acc + bq[d];
}

// ---------------- kP: P^T[j][k] = Q[k].Wk[j,:] ; c[k] = Q[k].bk ----------
__global__ void kP(const float* __restrict__ Wk, const float* __restrict__ bk) {
    int j = blockIdx.x * 16 + (threadIdx.x >> 4);
    int k = threadIdx.x & 15;
    const float* qrow = g_Q + k * DN;
    const float* wrow = Wk + j * DN;
    float acc = 0.f;
    #pragma unroll 4
    for (int e = 0; e < DN; e++) acc += qrow[e] * wrow[e];
    g_Pt[j * KK + k] = acc;
    if (blockIdx.x == 0 && threadIdx.x < KK) {
        const float* qr = g_Q + threadIdx.x * DN;
        float cc = 0.f;
        for (int e = 0; e < DN; e++) cc += qr[e] * bk[e];
        g_c[threadIdx.x] = cc;
    }
}

// ---------------- kAttn: scores -> softmax(S) -> U = S^T w --------------
__global__ void kAttn(const float* __restrict__ w, const int* __restrict__ mask,
                      float* __restrict__ outS) {
    int b = blockIdx.x;
    int tid = threadIdx.x;
    int ty = tid >> 4, tx = tid & 15;
    __shared__ float sW[NN * 65];
    __shared__ float sP[64 * KK];
    __shared__ float sSc[KK * 80];
    __shared__ float sSm[NN * KK];

    float acc[5] = {0.f, 0.f, 0.f, 0.f, 0.f};
    for (int d0 = 0; d0 < DD; d0 += 64) {
        for (int idx = tid; idx < NN * 64; idx += 256) {
            int n = idx >> 6, dd = idx & 63;
            sW[n * 65 + dd] = w[(b * NN + n) * DD + d0 + dd];
        }
        for (int idx = tid; idx < 64 * KK; idx += 256)
            sP[idx] = g_Pt[d0 * KK + idx];
        __syncthreads();
        #pragma unroll
        for (int i = 0; i < 5; i++) {
            int n = tx + 16 * i;
            if (n < NN) {
                float a = acc[i];
                #pragma unroll 8
                for (int dd = 0; dd < 64; dd++)
                    a += sP[dd * KK + ty] * sW[n * 65 + dd];
                acc[i] = a;
            }
        }
        __syncthreads();
    }
    float ck = g_c[ty];
    #pragma unroll
    for (int i = 0; i < 5; i++) {
        int n = tx + 16 * i;
        if (n < NN) sSc[ty * 80 + n] = (acc[i] + ck) * SCALE;
    }
    __syncthreads();

    if (tid < NN) {
        int n = tid;
        if (mask[b * NN + n] == 0) {
            #pragma unroll
            for (int k = 0; k < KK; k++) sSm[n * KK + k] = 1.0f / 16.0f;
        } else {
            float m = -3.4e38f;
            #pragma unroll
            for (int k = 0; k < KK; k++) m = fmaxf(m, sSc[k * 80 + n]);
            float e[KK]; float s = 0.f;
            #pragma unroll
            for (int k = 0; k < KK; k++) { e[k] = __expf(sSc[k * 80 + n] - m); s += e[k]; }
            float inv = 1.0f / s;
            #pragma unroll
            for (int k = 0; k < KK; k++) sSm[n * KK + k] = e[k] * inv;
        }
        #pragma unroll
        for (int k = 0; k < KK; k++)
            outS[(b * NN + n) * KK + k] = sSm[n * KK + k];
    }
    __syncthreads();
    if (tid < KK) {
        float s = 0.f;
        for (int n = 0; n < NN; n++) s += sSm[n * KK + tid];
        g_rowsum[b * KK + tid] = s;
    }

    float au[KK][3];
    #pragma unroll
    for (int k = 0; k < KK; k++) { au[k][0] = 0.f; au[k][1] = 0.f; au[k][2] = 0.f; }
    for (int n = 0; n < NN; n++) {
        const float* wr = w + (b * NN + n) * DD + tid;
        float w0 = wr[0], w1 = wr[256], w2 = wr[512];
        #pragma unroll
        for (int k = 0; k < KK; k++) {
            float s = sSm[n * KK + k];
            au[k][0] += s * w0; au[k][1] += s * w1; au[k][2] += s * w2;
        }
    }
    #pragma unroll
    for (int k = 0; k < KK; k++) {
        float* ur = g_U + (b * KK + k) * DN + tid;
        ur[0] = au[k][0]; ur[256] = au[k][1]; ur[512] = au[k][2];
    }
}

// ---------------- kSplitA: fp32 X -> g_Abf = [Ah|Ah|Al] per row ----------
__global__ void kSplitA(int asel) {
    const float* X = asel ? g_V : g_U;
    int gid = blockIdx.x * 128 + threadIdx.x;   // 4096*96 total
    int m = gid / 96, seg = gid % 96, e0 = seg * 8;
    const float4* src = (const float4*)(X + (size_t)m * DN + e0);
    float4 x0 = src[0], x1 = src[1];
    float xs[8] = {x0.x, x0.y, x0.z, x0.w, x1.x, x1.y, x1.z, x1.w};
    unsigned h[4], l[4];
    #pragma unroll
    for (int i = 0; i < 4; i++) {
        float a = xs[2*i], b = xs[2*i+1];
        float ah = __bfloat162float(__float2bfloat16(a));
        float bh = __bfloat162float(__float2bfloat16(b));
        h[i] = packbf2(a, b);
        l[i] = packbf2(a - ah, b - bh);
    }
    __nv_bfloat16* out = (__nv_bfloat16*)g_Abf + (size_t)m * KSPLIT;
    *(uint4*)(out + e0)        = *(uint4*)h;
    *(uint4*)(out + 768 + e0)  = *(uint4*)h;
    *(uint4*)(out + 1536 + e0) = *(uint4*)l;
}

// ---------------- kSplitW: W[768,768] col n -> out[n][ [Wh|Wl|Wh] ] ------
__global__ void kSplitW(const float* __restrict__ W, int wsel) {
    uint4* out4 = (wsel == 0) ? g_WbfV : (wsel == 1) ? g_WbfG0 : g_WbfG1;
    int n = blockIdx.x * 128 + threadIdx.x;
    __nv_bfloat16* out = (__nv_bfloat16*)out4 + (size_t)n * KSPLIT;
    for (int e0 = 0; e0 < DN; e0 += 8) {
        unsigned h[4], l[4];
        #pragma unroll
        for (int i = 0; i < 4; i++) {
            float a = W[(size_t)(e0 + 2*i) * DN + n];
            float b = W[(size_t)(e0 + 2*i + 1) * DN + n];
            float ah = __bfloat162float(__float2bfloat16(a));
            float bh = __bfloat162float(__float2bfloat16(b));
            h[i] = packbf2(a, b);
            l[i] = packbf2(a - ah, b - bh);
        }
        *(uint4*)(out + e0)        = *(uint4*)h;
        *(uint4*)(out + 768 + e0)  = *(uint4*)l;
        *(uint4*)(out + 1536 + e0) = *(uint4*)h;
    }
}

// ---------------- kSplitWe1: combined edge-MLP weight [1024 cols] --------
__global__ void kSplitWe1(const float* __restrict__ We1) {
    int n = blockIdx.x * 128 + threadIdx.x;    // 0..1023
    __nv_bfloat16* out = (__nv_bfloat16*)g_WbfE1 + (size_t)n * KSPLIT;
    size_t base = (n < HID) ? (size_t)n : ((size_t)768 * HID + (n - HID));
    for (int e0 = 0; e0 < DN; e0 += 8) {
        unsigned h[4], l[4];
        #pragma unroll
        for (int i = 0; i < 4; i++) {
            float a = We1[base + (size_t)(e0 + 2*i) * HID];
            float b = We1[base + (size_t)(e0 + 2*i + 1) * HID];
            float ah = __bfloat162float(__float2bfloat16(a));
            float bh = __bfloat162float(__float2bfloat16(b));
            h[i] = packbf2(a, b);
            l[i] = packbf2(a - ah, b - bh);
        }
        *(uint4*)(out + e0)        = *(uint4*)h;
        *(uint4*)(out + 768 + e0)  = *(uint4*)l;
        *(uint4*)(out + 1536 + e0) = *(uint4*)h;
    }
}

// ---------------- kTGemm: mma.sync bf16-split GEMM -----------------------
// C[4096, Ncols] = A'[4096,2304] @ W'[Ncols,2304]^T + epilogue(mode)
// wsel: 0=WbfV, 1=WbfG0, 2=WbfG1, 3=WbfE1
// mode: 0 -> C=g_H (Ncols=1024); 1 -> C=g_V (+rowsum*bv, gate mix);
//       2 -> C=g_M (+bg)
__global__ __launch_bounds__(256, 2) void kTGemm(
    int wsel, int mode, const float* __restrict__ bias,
    const float* __restrict__ nq, const float* __restrict__ gatep)
{
    __shared__ __align__(1024) __nv_bfloat16 sA[2][128 * 32];
    __shared__ __align__(1024) __nv_bfloat16 sB[2][128 * 32];

    const __nv_bfloat16* Ag = (const __nv_bfloat16*)g_Abf;
    const uint4* B4 = (wsel == 0) ? g_WbfV : (wsel == 1) ? g_WbfG0
                    : (wsel == 2) ? g_WbfG1 : g_WbfE1;
    const __nv_bfloat16* Bg = (const __nv_bfloat16*)B4;
    float* C; int Ncols;
    if (mode == 0)      { C = g_H; Ncols = 2 * HID; }
    else if (mode == 1) { C = g_V; Ncols = DN; }
    else                { C = g_M; Ncols = DN; }

    const int tid = threadIdx.x;
    const int lane = tid & 31, warp = tid >> 5;
    const int wm = warp >> 2, wn = warp & 3;          // warps 2x4, tile 64x32
    const int m0 = blockIdx.x * 128, n0 = blockIdx.y * 128;

    const uint32_t sAu = smem_u32(sA), sBu = smem_u32(sB);

    // cp.async slots: 2 quads each for A and B
    uint32_t soff[2];
    const __nv_bfloat16* gA[2];
    const __nv_bfloat16* gB[2];
    #pragma unroll
    for (int i = 0; i < 2; i++) {
        int v = tid * 2 + i, row = v >> 2, q = v & 3;
        soff[i] = row * 64 + ((q ^ ((row >> 1) & 3)) << 4);
        gA[i] = Ag + (size_t)(m0 + row) * KSPLIT + q * 8;
        gB[i] = Bg + (size_t)(n0 + row) * KSPLIT + q * 8;
    }

    float acc[4][4][4];
    #pragma unroll
    for (int a = 0; a < 4; a++)
        #pragma unroll
        for (int b = 0; b < 4; b++)
            #pragma unroll
            for (int r = 0; r < 4; r++) acc[a][b][r] = 0.f;

    // issue chunk 0
    #pragma unroll
    for (int i = 0; i < 2; i++) {
        asm volatile("cp.async.ca.shared.global [%0], [%1], 16;"
                     :: "r"(sAu + soff[i]), "l"(gA[i]));
        asm volatile("cp.async.ca.shared.global [%0], [%1], 16;"
                     :: "r"(sBu + soff[i]), "l"(gB[i]));
    }
    asm volatile("cp.async.commit_group;");

    const int r16 = lane & 15, hh = lane >> 4;

    for (int c = 0; c < KCH; c++) {
        const int buf = c & 1;
        if (c < KCH - 1) {
            const uint32_t da = sAu + (buf ^ 1) * 8192;
            const uint32_t db = sBu + (buf ^ 1) * 8192;
            #pragma unroll
            for (int i = 0; i < 2; i++) {
                asm volatile("cp.async.ca.shared.global [%0], [%1], 16;"
                             :: "r"(da + soff[i]), "l"(gA[i] + (c + 1) * 32));
                asm volatile("cp.async.ca.shared.global [%0], [%1], 16;"
                             :: "r"(db + soff[i]), "l"(gB[i] + (c + 1) * 32));
            }
            asm volatile("cp.async.commit_group;");
            asm volatile("cp.async.wait_group 1;");
        } else {
            asm volatile("cp.async.wait_group 0;");
        }
        __syncthreads();

        const uint32_t baseA = sAu + buf * 8192;
        const uint32_t baseB = sBu + buf * 8192;
        #pragma unroll
        for (int s = 0; s < 2; s++) {
            uint32_t afr[4][4];
            #pragma unroll
            for (int mt = 0; mt < 4; mt++) {
                int row = wm * 64 + mt * 16 + r16;
                int quad = 2 * s + hh;
                uint32_t ad = baseA + row * 64 + ((quad ^ ((row >> 1) & 3)) << 4);
                asm volatile("ldmatrix.sync.aligned.m8n8.x4.shared.b16 "
                             "{%0,%1,%2,%3}, [%4];"
                             : "=r"(afr[mt][0]), "=r"(afr[mt][1]),
                               "=r"(afr[mt][2]), "=r"(afr[mt][3]) : "r"(ad));
            }
            uint32_t bfr[4][2];
            #pragma unroll
            for (int nb = 0; nb < 2; nb++) {
                int row = wn * 32 + nb * 16 + r16;
                int quad = 2 * s + hh;
                uint32_t ad = baseB + row * 64 + ((quad ^ ((row >> 1) & 3)) << 4);
                uint32_t r0, r1, r2, r3;
                asm volatile("ldmatrix.sync.aligned.m8n8.x4.shared.b16 "
                             "{%0,%1,%2,%3}, [%4];"
                             : "=r"(r0), "=r"(r1), "=r"(r2), "=r"(r3) : "r"(ad));
                bfr[nb * 2][0] = r0;     bfr[nb * 2][1] = r2;
                bfr[nb * 2 + 1][0] = r1; bfr[nb * 2 + 1][1] = r3;
            }
            #pragma unroll
            for (int mt = 0; mt < 4; mt++)
                #pragma unroll
                for (int nt = 0; nt < 4; nt++) {
                    asm volatile(
                        "mma.sync.aligned.m16n8k16.row.col.f32.bf16.bf16.f32 "
                        "{%0,%1,%2,%3}, {%4,%5,%6,%7}, {%8,%9}, {%0,%1,%2,%3};"
                        : "+f"(acc[mt][nt][0]), "+f"(acc[mt][nt][1]),
                          "+f"(acc[mt][nt][2]), "+f"(acc[mt][nt][3])
                        : "r"(afr[mt][0]), "r"(afr[mt][1]),
                          "r"(afr[mt][2]), "r"(afr[mt][3]),
                          "r"(bfr[nt][0]), "r"(bfr[nt][1]));
                }
        }
        __syncthreads();
    }

    // epilogue
    float gate = 0.f, omg = 1.f;
    if (mode == 1) {
        gate = 1.0f / (1.0f + expf(-gatep[0]));
        omg = 1.0f - gate;
    }
    #pragma unroll
    for (int mt = 0; mt < 4; mt++) {
        #pragma unroll
        for (int half = 0; half < 2; half++) {
            int row = m0 + wm * 64 + mt * 16 + (lane >> 2) + 8 * half;
            float rsv = 0.f; const float* nqr = nullptr;
            if (mode == 1) { rsv = g_rowsum[row]; nqr = nq + (size_t)(row & 15) * DN; }
            float* crow = C + (size_t)row * Ncols;
            #pragma unroll
            for (int nt = 0; nt < 4; nt++) {
                int col = n0 + wn * 32 + nt * 8 + (lane & 3) * 2;
                float v0 = acc[mt][nt][half * 2 + 0];
                float v1 = acc[mt][nt][half * 2 + 1];
                if (mode == 1) {
                    v0 += rsv * __ldg(&bias[col]);
                    v1 += rsv * __ldg(&bias[col + 1]);
                    v0 = omg * v0 + gate * __ldg(&nqr[col]);
                    v1 = omg * v1 + gate * __ldg(&nqr[col + 1]);
                } else if (mode == 2) {
                    v0 += __ldg(&bias[col]);
                    v1 += __ldg(&bias[col + 1]);
                }
                float2 o; o.x = v0; o.y = v1;
                *(float2*)(crow + col) = o;
            }
        }
    }
}

// ---------------- kEdge ----------------------------------------------
__global__ void kEdge(const float* __restrict__ be1, const float* __restrict__ We2,
                      const float* __restrict__ be2, float* __restrict__ outE,
                      int post) {
    int b = blockIdx.x;
    int tid = threadIdx.x;
    int i = tid >> 4, j = tid & 15;
    __shared__ float sHi[KK * 257];
    __shared__ float sHj[KK * 257];
    __shared__ float sW2[256];
    __shared__ float sE[KK * 17];

    float acc = 0.f;
    for (int h0 = 0; h0 < HID; h0 += 256) {
        for (int idx = tid; idx < KK * 256; idx += 256) {
            int r = idx >> 8, c = idx & 255;
            sHi[r * 257 + c] = g_H[(size_t)(b * KK + r) * (2 * HID) + h0 + c] + be1[h0 + c];
            sHj[r * 257 + c] = g_H[(size_t)(b * KK + r) * (2 * HID) + HID + h0 + c];
        }
        sW2[tid] = We2[h0 + tid];
        __syncthreads();
        const float* hi = sHi + i * 257;
        const float* hj = sHj + j * 257;
        #pragma unroll 8
        for (int c = 0; c < 256; c++)
            acc += fmaxf(hi[c] + hj[c], 0.f) * sW2[c];
        __syncthreads();
    }
    float E = acc + be2[0];
    if (post) {
        outE[b * 256 + tid] = E;
    } else {
        sE[i * 17 + j] = E;
        __syncthreads();
        float m = -3.4e38f;
        #pragma unroll
        for (int jj = 0; jj < KK; jj++) m = fmaxf(m, sE[i * 17 + jj]);
        float s = 0.f;
        #pragma unroll
        for (int jj = 0; jj < KK; jj++) s += __expf(sE[i * 17 + jj] - m);
        g_A[b * 256 + tid] = __expf(E - m) / s;
    }
}

// ---------------- kMsg: V += relu(A @ M) ------------------------------
__global__ void kMsg() {
    int b = blockIdx.x;
    int tid = threadIdx.x;
    __shared__ float sAm[KK * 17];
    sAm[(tid >> 4) * 17 + (tid & 15)] = g_A[b * 256 + tid];
    __syncthreads();
    float acc[KK][3];
    #pragma unroll
    for (int i = 0; i < KK; i++) { acc[i][0] = 0.f; acc[i][1] = 0.f; acc[i][2] = 0.f; }
    for (int j = 0; j < KK; j++) {
        const float* mr = g_M + (size_t)(b * KK + j) * DN + tid;
        float m0 = mr[0], m1 = mr[256], m2 = mr[512];
        #pragma unroll
        for (int i = 0; i < KK; i++) {
            float a = sAm[i * 17 + j];
            acc[i][0] += a * m0; acc[i][1] += a * m1; acc[i][2] += a * m2;
        }
    }
    #pragma unroll
    for (int i = 0; i < KK; i++) {
        float* vr = g_V + (size_t)(b * KK + i) * DN + tid;
        vr[0]   += fmaxf(acc[i][0], 0.f);
        vr[256] += fmaxf(acc[i][1], 0.f);
        vr[512] += fmaxf(acc[i][2], 0.f);
    }
}

// ---------------- kCopyV --------------------------------------------------
__global__ void kCopyV(float* __restrict__ outV) {
    int idx = blockIdx.x * 1024 + threadIdx.x;
    outV[idx] = g_V[idx];
}

// ---------------- host ----------------------------------------------------
extern "C" void kernel_launch(void* const* d_in, const int* in_sizes, int n_in,
                              void* d_out, int out_size) {
    const float* w    = (const float*)d_in[0];
    const int*   mask = (const int*)  d_in[1];
    const float* nq   = (const float*)d_in[2];
    const float* Wq   = (const float*)d_in[3];
    const float* bq   = (const float*)d_in[4];
    const float* Wk   = (const float*)d_in[5];
    const float* bk   = (const float*)d_in[6];
    const float* Wv   = (const float*)d_in[7];
    const float* bv   = (const float*)d_in[8];
    const float* We1  = (const float*)d_in[9];
    const float* be1  = (const float*)d_in[10];
    const float* We2  = (const float*)d_in[11];
    const float* be2  = (const float*)d_in[12];
    const float* fg   = (const float*)d_in[13];
    const float* Wg   = (const float*)d_in[14];
    const float* bg   = (const float*)d_in[15];

    float* outS = (float*)d_out;
    float* outV = outS + (size_t)BB * NN * KK;
    float* outE = outV + (size_t)BB * KK * DN;

    // weight splits (independent of data path)
    kSplitW<<<6, 128>>>(Wv, 0);
    kSplitW<<<6, 128>>>(Wg, 1);
    kSplitW<<<6, 128>>>(Wg + (size_t)DN * DN, 2);
    kSplitWe1<<<8, 128>>>(We1);

    kQ<<<48, 256>>>(nq, Wq, bq);
    kP<<<48, 256>>>(Wk, bk);
    kAttn<<<BB, 256>>>(w, mask, outS);

    kSplitA<<<3072, 128>>>(0);                                 // U -> Abf
    kTGemm<<<dim3(32, 6), 256>>>(0, 1, bv, nq, fg);            // V = U@Wv (+gate)
    kSplitA<<<3072, 128>>>(1);                                 // V0 -> Abf
    kTGemm<<<dim3(32, 8), 256>>>(3, 0, nullptr, nullptr, nullptr); // H = V@We1
    kEdge<<<BB, 256>>>(be1, We2, be2, nullptr, 0);             // A = softmax(E)
    kTGemm<<<dim3(32, 6), 256>>>(1, 2, bg, nullptr, nullptr);  // M = V@Wg0+bg0
    kMsg<<<BB, 256>>>();                                       // V += relu(A@M)
    kSplitA<<<3072, 128>>>(1);                                 // V1 -> Abf
    kTGemm<<<dim3(32, 6), 256>>>(2, 2, bg + DN, nullptr, nullptr); // M = V@Wg1+bg1
    kMsg<<<BB, 256>>>();
    kSplitA<<<3072, 128>>>(1);                                 // V2 -> Abf
    kTGemm<<<dim3(32, 8), 256>>>(3, 0, nullptr, nullptr, nullptr); // H on final V
    kEdge<<<BB, 256>>>(be1, We2, be2, outE, 1);                // E -> out
    kCopyV<<<(BB * KK * DN) / 1024, 1024>>>(outV);
}

// round 4
// speedup vs baseline: 1.4076x; 1.3403x over previous
#include <cuda_runtime.h>
#include <cuda_bf16.h>
#include <math.h>
#include <stdint.h>

// Problem dims
#define BB 256
#define NN 77
#define DD 768
#define KK 16
#define DN 768
#define HID 512
#define NL 2
#define MTOT (BB*KK)          // 4096
#define SCALE 0.10206207261596575f   // (768/8)^-0.5
#define KSPLIT 2304           // 3*768 (split-K concat)
#define KCH 72                // 2304/32 chunks

// ---------------- scratch (device globals; no allocation) ----------------
__device__ float g_Q[KK*DN];
__device__ float g_Pt[DD*KK];
__device__ float g_c[KK];
__device__ float g_V[MTOT*DN];
__device__ float g_rowsum[MTOT];
__device__ float g_H[MTOT*2*HID];
__device__ float g_M[MTOT*DN];
__device__ float g_A[BB*KK*KK];
// split-bf16 operand buffers (uint4 for 16B alignment)
__device__ uint4 g_Abf [(size_t)MTOT*KSPLIT/8];   // [4096][2304] split-U
__device__ uint4 g_Abf2[(size_t)MTOT*KSPLIT/8];   // [4096][2304] split-V
__device__ uint4 g_WbfV [768*KSPLIT/8];
__device__ uint4 g_WbfG0[768*KSPLIT/8];
__device__ uint4 g_WbfG1[768*KSPLIT/8];
__device__ uint4 g_WbfE1[1024*KSPLIT/8];

__device__ __forceinline__ uint32_t smem_u32(const void* p) {
    uint32_t a;
    asm("{ .reg .u64 t; cvta.to.shared.u64 t, %1; cvt.u32.u64 %0, t; }"
        : "=r"(a) : "l"(p));
    return a;
}

__device__ __forceinline__ unsigned packbf2(float a, float b) {
    unsigned short lo = __bfloat16_as_ushort(__float2bfloat16(a));
    unsigned short hi = __bfloat16_as_ushort(__float2bfloat16(b));
    return ((unsigned)hi << 16) | lo;
}

// ---------------- kQ: Q = node_queries @ Wq + bq ----------------
__global__ void kQ(const float* __restrict__ nq, const float* __restrict__ Wq,
                   const float* __restrict__ bq) {
    int k = blockIdx.x / 3;
    int d = (blockIdx.x % 3) * 256 + threadIdx.x;
    float acc = 0.f;
    const float* qrow = nq + k * DN;
    #pragma unroll 4
    for (int e = 0; e < DN; e++) acc += qrow[e] * Wq[e * DN + d];
    g_Q[k * DN + d] = acc + bq[d];
}

// ---------------- kP: P^T[j][k] = Q[k].Wk[j,:] ; c[k] = Q[k].bk ----------
__global__ void kP(const float* __restrict__ Wk, const float* __restrict__ bk) {
    int j = blockIdx.x * 16 + (threadIdx.x >> 4);
    int k = threadIdx.x & 15;
    const float* qrow = g_Q + k * DN;
    const float* wrow = Wk + j * DN;
    float acc = 0.f;
    #pragma unroll 4
    for (int e = 0; e < DN; e++) acc += qrow[e] * wrow[e];
    g_Pt[j * KK + k] = acc;
    if (blockIdx.x == 0 && threadIdx.x < KK) {
        const float* qr = g_Q + threadIdx.x * DN;
        float cc = 0.f;
        for (int e = 0; e < DN; e++) cc += qr[e] * bk[e];
        g_c[threadIdx.x] = cc;
    }
}

// ---------------- kSplitAllW: all 4 weight splits, one launch ------------
// jobs 0..2: W[768,768] (Wv, Wg0, Wg1) -> [Wh|Wl|Wh] rows per output col n
// job 3: We1 [1536,512] -> combined 1024-col edge weight
__global__ void kSplitAllW(const float* __restrict__ Wv,
                           const float* __restrict__ Wg,
                           const float* __restrict__ We1) {
    int sid = blockIdx.x * 256 + threadIdx.x;   // 0..319487
    float a[8];
    __nv_bfloat16* out;
    int e0;
    if (sid < 221184) {
        int job = sid / 73728, s = sid % 73728;
        int n = s % 768, seg = s / 768;
        e0 = seg * 8;
        const float* Wp = (job == 0) ? Wv : (job == 1) ? Wg : (Wg + 768 * 768);
        uint4* o4 = (job == 0) ? g_WbfV : (job == 1) ? g_WbfG0 : g_WbfG1;
        out = (__nv_bfloat16*)o4 + (size_t)n * KSPLIT;
        #pragma unroll
        for (int i = 0; i < 8; i++) a[i] = Wp[(size_t)(e0 + i) * 768 + n];
    } else {
        int s = sid - 221184;
        int n = s % 1024, seg = s / 1024;
        e0 = seg * 8;
        out = (__nv_bfloat16*)g_WbfE1 + (size_t)n * KSPLIT;
        size_t base = (n < HID) ? (size_t)n : ((size_t)768 * HID + (n - HID));
        #pragma unroll
        for (int i = 0; i < 8; i++) a[i] = We1[base + (size_t)(e0 + i) * HID];
    }
    unsigned h[4], l[4];
    #pragma unroll
    for (int i = 0; i < 4; i++) {
        float x = a[2 * i], y = a[2 * i + 1];
        float xh = __bfloat162float(__float2bfloat16(x));
        float yh = __bfloat162float(__float2bfloat16(y));
        h[i] = packbf2(x, y);
        l[i] = packbf2(x - xh, y - yh);
    }
    *(uint4*)(out + e0)        = *(uint4*)h;
    *(uint4*)(out + 768 + e0)  = *(uint4*)l;
    *(uint4*)(out + 1536 + e0) = *(uint4*)h;
}

// ---------------- kAttn: scores -> softmax(S) -> split-U -> g_Abf -------
__global__ void kAttn(const float* __restrict__ w, const int* __restrict__ mask,
                      float* __restrict__ outS) {
    int b = blockIdx.x;
    int tid = threadIdx.x;
    int ty = tid >> 4, tx = tid & 15;
    __shared__ float sW[NN * 65];
    __shared__ float sP[64 * KK];
    __shared__ float sSc[KK * 80];
    __shared__ float sSm[NN * KK];

    float acc[5] = {0.f, 0.f, 0.f, 0.f, 0.f};
    for (int d0 = 0; d0 < DD; d0 += 64) {
        for (int idx = tid; idx < NN * 64; idx += 256) {
            int n = idx >> 6, dd = idx & 63;
            sW[n * 65 + dd] = w[(b * NN + n) * DD + d0 + dd];
        }
        for (int idx = tid; idx < 64 * KK; idx += 256)
            sP[idx] = g_Pt[d0 * KK + idx];
        __syncthreads();
        #pragma unroll
        for (int i = 0; i < 5; i++) {
            int n = tx + 16 * i;
            if (n < NN) {
                float a = acc[i];
                #pragma unroll 8
                for (int dd = 0; dd < 64; dd++)
                    a += sP[dd * KK + ty] * sW[n * 65 + dd];
                acc[i] = a;
            }
        }
        __syncthreads();
    }
    float ck = g_c[ty];
    #pragma unroll
    for (int i = 0; i < 5; i++) {
        int n = tx + 16 * i;
        if (n < NN) sSc[ty * 80 + n] = (acc[i] + ck) * SCALE;
    }
    __syncthreads();

    if (tid < NN) {
        int n = tid;
        if (mask[b * NN + n] == 0) {
            #pragma unroll
            for (int k = 0; k < KK; k++) sSm[n * KK + k] = 1.0f / 16.0f;
        } else {
            float m = -3.4e38f;
            #pragma unroll
            for (int k = 0; k < KK; k++) m = fmaxf(m, sSc[k * 80 + n]);
            float e[KK]; float s = 0.f;
            #pragma unroll
            for (int k = 0; k < KK; k++) { e[k] = __expf(sSc[k * 80 + n] - m); s += e[k]; }
            float inv = 1.0f / s;
            #pragma unroll
            for (int k = 0; k < KK; k++) sSm[n * KK + k] = e[k] * inv;
        }
        #pragma unroll
        for (int k = 0; k < KK; k++)
            outS[(b * NN + n) * KK + k] = sSm[n * KK + k];
    }
    __syncthreads();
    if (tid < KK) {
        float s = 0.f;
        for (int n = 0; n < NN; n++) s += sSm[n * KK + tid];
        g_rowsum[b * KK + tid] = s;
    }

    float au[KK][3];
    #pragma unroll
    for (int k = 0; k < KK; k++) { au[k][0] = 0.f; au[k][1] = 0.f; au[k][2] = 0.f; }
    for (int n = 0; n < NN; n++) {
        const float* wr = w + (b * NN + n) * DD + tid;
        float w0 = wr[0], w1 = wr[256], w2 = wr[512];
        #pragma unroll
        for (int k = 0; k < KK; k++) {
            float s = sSm[n * KK + k];
            au[k][0] += s * w0; au[k][1] += s * w1; au[k][2] += s * w2;
        }
    }
    // write split-U directly to g_Abf ([Ah|Ah|Al])
    #pragma unroll
    for (int k = 0; k < KK; k++) {
        __nv_bfloat16* ur = (__nv_bfloat16*)g_Abf + (size_t)(b * KK + k) * KSPLIT;
        #pragma unroll
        for (int c3 = 0; c3 < 3; c3++) {
            int d = tid + c3 * 256;
            float x = au[k][c3];
            __nv_bfloat16 h = __float2bfloat16(x);
            __nv_bfloat16 l = __float2bfloat16(x - __bfloat162float(h));
            ur[d] = h; ur[768 + d] = h; ur[1536 + d] = l;
        }
    }
}

// ---------------- kTGemm: mma.sync bf16-split GEMM -----------------------
// C[4096, Ncols] = A'[4096,2304] @ W'[Ncols,2304]^T + epilogue(mode)
// asel: 0 = g_Abf (split U), 1 = g_Abf2 (split V)
// wsel: 0=WbfV, 1=WbfG0, 2=WbfG1, 3=WbfE1
// mode: 0 -> C=g_H (Ncols=1024); 1 -> C=g_V + split-V into g_Abf2;
//       2 -> C=g_M (+bg)
__global__ __launch_bounds__(256, 2) void kTGemm(
    int asel, int wsel, int mode, const float* __restrict__ bias,
    const float* __restrict__ nq, const float* __restrict__ gatep)
{
    __shared__ __align__(1024) __nv_bfloat16 sA[2][128 * 32];
    __shared__ __align__(1024) __nv_bfloat16 sB[2][128 * 32];

    const __nv_bfloat16* Ag = (const __nv_bfloat16*)(asel ? g_Abf2 : g_Abf);
    const uint4* B4 = (wsel == 0) ? g_WbfV : (wsel == 1) ? g_WbfG0
                    : (wsel == 2) ? g_WbfG1 : g_WbfE1;
    const __nv_bfloat16* Bg = (const __nv_bfloat16*)B4;
    float* C; int Ncols;
    if (mode == 0)      { C = g_H; Ncols = 2 * HID; }
    else if (mode == 1) { C = g_V; Ncols = DN; }
    else                { C = g_M; Ncols = DN; }

    const int tid = threadIdx.x;
    const int lane = tid & 31, warp = tid >> 5;
    const int wm = warp >> 2, wn = warp & 3;          // warps 2x4, tile 64x32
    const int m0 = blockIdx.x * 128, n0 = blockIdx.y * 128;

    const uint32_t sAu = smem_u32(sA), sBu = smem_u32(sB);

    uint32_t soff[2];
    const __nv_bfloat16* gA[2];
    const __nv_bfloat16* gB[2];
    #pragma unroll
    for (int i = 0; i < 2; i++) {
        int v = tid * 2 + i, row = v >> 2, q = v & 3;
        soff[i] = row * 64 + ((q ^ ((row >> 1) & 3)) << 4);
        gA[i] = Ag + (size_t)(m0 + row) * KSPLIT + q * 8;
        gB[i] = Bg + (size_t)(n0 + row) * KSPLIT + q * 8;
    }

    float acc[4][4][4];
    #pragma unroll
    for (int a = 0; a < 4; a++)
        #pragma unroll
        for (int b = 0; b < 4; b++)
            #pragma unroll
            for (int r = 0; r < 4; r++) acc[a][b][r] = 0.f;

    #pragma unroll
    for (int i = 0; i < 2; i++) {
        asm volatile("cp.async.ca.shared.global [%0], [%1], 16;"
                     :: "r"(sAu + soff[i]), "l"(gA[i]));
        asm volatile("cp.async.ca.shared.global [%0], [%1], 16;"
                     :: "r"(sBu + soff[i]), "l"(gB[i]));
    }
    asm volatile("cp.async.commit_group;");

    const int r16 = lane & 15, hh = lane >> 4;

    for (int c = 0; c < KCH; c++) {
        const int buf = c & 1;
        if (c < KCH - 1) {
            const uint32_t da = sAu + (buf ^ 1) * 8192;
            const uint32_t db = sBu + (buf ^ 1) * 8192;
            #pragma unroll
            for (int i = 0; i < 2; i++) {
                asm volatile("cp.async.ca.shared.global [%0], [%1], 16;"
                             :: "r"(da + soff[i]), "l"(gA[i] + (c + 1) * 32));
                asm volatile("cp.async.ca.shared.global [%0], [%1], 16;"
                             :: "r"(db + soff[i]), "l"(gB[i] + (c + 1) * 32));
            }
            asm volatile("cp.async.commit_group;");
            asm volatile("cp.async.wait_group 1;");
        } else {
            asm volatile("cp.async.wait_group 0;");
        }
        __syncthreads();

        const uint32_t baseA = sAu + buf * 8192;
        const uint32_t baseB = sBu + buf * 8192;
        #pragma unroll
        for (int s = 0; s < 2; s++) {
            uint32_t afr[4][4];
            #pragma unroll
            for (int mt = 0; mt < 4; mt++) {
                int row = wm * 64 + mt * 16 + r16;
                int quad = 2 * s + hh;
                uint32_t ad = baseA + row * 64 + ((quad ^ ((row >> 1) & 3)) << 4);
                asm volatile("ldmatrix.sync.aligned.m8n8.x4.shared.b16 "
                             "{%0,%1,%2,%3}, [%4];"
                             : "=r"(afr[mt][0]), "=r"(afr[mt][1]),
                               "=r"(afr[mt][2]), "=r"(afr[mt][3]) : "r"(ad));
            }
            uint32_t bfr[4][2];
            #pragma unroll
            for (int nb = 0; nb < 2; nb++) {
                int row = wn * 32 + nb * 16 + r16;
                int quad = 2 * s + hh;
                uint32_t ad = baseB + row * 64 + ((quad ^ ((row >> 1) & 3)) << 4);
                uint32_t r0, r1, r2, r3;
                asm volatile("ldmatrix.sync.aligned.m8n8.x4.shared.b16 "
                             "{%0,%1,%2,%3}, [%4];"
                             : "=r"(r0), "=r"(r1), "=r"(r2), "=r"(r3) : "r"(ad));
                bfr[nb * 2][0] = r0;     bfr[nb * 2][1] = r2;
                bfr[nb * 2 + 1][0] = r1; bfr[nb * 2 + 1][1] = r3;
            }
            #pragma unroll
            for (int mt = 0; mt < 4; mt++)
                #pragma unroll
                for (int nt = 0; nt < 4; nt++) {
                    asm volatile(
                        "mma.sync.aligned.m16n8k16.row.col.f32.bf16.bf16.f32 "
                        "{%0,%1,%2,%3}, {%4,%5,%6,%7}, {%8,%9}, {%0,%1,%2,%3};"
                        : "+f"(acc[mt][nt][0]), "+f"(acc[mt][nt][1]),
                          "+f"(acc[mt][nt][2]), "+f"(acc[mt][nt][3])
                        : "r"(afr[mt][0]), "r"(afr[mt][1]),
                          "r"(afr[mt][2]), "r"(afr[mt][3]),
                          "r"(bfr[nt][0]), "r"(bfr[nt][1]));
                }
        }
        __syncthreads();
    }

    // epilogue
    float gate = 0.f, omg = 1.f;
    if (mode == 1) {
        gate = 1.0f / (1.0f + expf(-gatep[0]));
        omg = 1.0f - gate;
    }
    #pragma unroll
    for (int mt = 0; mt < 4; mt++) {
        #pragma unroll
        for (int half = 0; half < 2; half++) {
            int row = m0 + wm * 64 + mt * 16 + (lane >> 2) + 8 * half;
            float rsv = 0.f; const float* nqr = nullptr;
            __nv_bfloat16* arow = nullptr;
            if (mode == 1) {
                rsv = g_rowsum[row];
                nqr = nq + (size_t)(row & 15) * DN;
                arow = (__nv_bfloat16*)g_Abf2 + (size_t)row * KSPLIT;
            }
            float* crow = C + (size_t)row * Ncols;
            #pragma unroll
            for (int nt = 0; nt < 4; nt++) {
                int col = n0 + wn * 32 + nt * 8 + (lane & 3) * 2;
                float v0 = acc[mt][nt][half * 2 + 0];
                float v1 = acc[mt][nt][half * 2 + 1];
                if (mode == 1) {
                    v0 += rsv * __ldg(&bias[col]);
                    v1 += rsv * __ldg(&bias[col + 1]);
                    v0 = omg * v0 + gate * __ldg(&nqr[col]);
                    v1 = omg * v1 + gate * __ldg(&nqr[col + 1]);
                    // split-V write
                    float h0 = __bfloat162float(__float2bfloat16(v0));
                    float h1 = __bfloat162float(__float2bfloat16(v1));
                    unsigned hp = packbf2(v0, v1);
                    unsigned lp = packbf2(v0 - h0, v1 - h1);
                    *(unsigned*)(arow + col) = hp;
                    *(unsigned*)(arow + 768 + col) = hp;
                    *(unsigned*)(arow + 1536 + col) = lp;
                } else if (mode == 2) {
                    v0 += __ldg(&bias[col]);
                    v1 += __ldg(&bias[col + 1]);
                }
                float2 o; o.x = v0; o.y = v1;
                *(float2*)(crow + col) = o;
            }
        }
    }
}

// ---------------- kEdge ----------------------------------------------
__global__ void kEdge(const float* __restrict__ be1, const float* __restrict__ We2,
                      const float* __restrict__ be2, float* __restrict__ outE,
                      int post) {
    int b = blockIdx.x;
    int tid = threadIdx.x;
    int i = tid >> 4, j = tid & 15;
    __shared__ float sHi[KK * 257];
    __shared__ float sHj[KK * 257];
    __shared__ float sW2[256];
    __shared__ float sE[KK * 17];

    float acc = 0.f;
    for (int h0 = 0; h0 < HID; h0 += 256) {
        for (int idx = tid; idx < KK * 256; idx += 256) {
            int r = idx >> 8, c = idx & 255;
            sHi[r * 257 + c] = g_H[(size_t)(b * KK + r) * (2 * HID) + h0 + c] + be1[h0 + c];
            sHj[r * 257 + c] = g_H[(size_t)(b * KK + r) * (2 * HID) + HID + h0 + c];
        }
        sW2[tid] = We2[h0 + tid];
        __syncthreads();
        const float* hi = sHi + i * 257;
        const float* hj = sHj + j * 257;
        #pragma unroll 8
        for (int c = 0; c < 256; c++)
            acc += fmaxf(hi[c] + hj[c], 0.f) * sW2[c];
        __syncthreads();
    }
    float E = acc + be2[0];
    if (post) {
        outE[b * 256 + tid] = E;
    } else {
        sE[i * 17 + j] = E;
        __syncthreads();
        float m = -3.4e38f;
        #pragma unroll
        for (int jj = 0; jj < KK; jj++) m = fmaxf(m, sE[i * 17 + jj]);
        float s = 0.f;
        #pragma unroll
        for (int jj = 0; jj < KK; jj++) s += __expf(sE[i * 17 + jj] - m);
        g_A[b * 256 + tid] = __expf(E - m) / s;
    }
}

// ---------------- kMsg: V += relu(A @ M), write split-V (+optional outV) --
__global__ void kMsg(float* __restrict__ outV) {
    int b = blockIdx.x;
    int tid = threadIdx.x;
    __shared__ float sAm[KK * 17];
    sAm[(tid >> 4) * 17 + (tid & 15)] = g_A[b * 256 + tid];
    __syncthreads();
    float acc[KK][3];
    #pragma unroll
    for (int i = 0; i < KK; i++) { acc[i][0] = 0.f; acc[i][1] = 0.f; acc[i][2] = 0.f; }
    for (int j = 0; j < KK; j++) {
        const float* mr = g_M + (size_t)(b * KK + j) * DN + tid;
        float m0 = mr[0], m1 = mr[256], m2 = mr[512];
        #pragma unroll
        for (int i = 0; i < KK; i++) {
            float a = sAm[i * 17 + j];
            acc[i][0] += a * m0; acc[i][1] += a * m1; acc[i][2] += a * m2;
        }
    }
    #pragma unroll
    for (int i = 0; i < KK; i++) {
        int row = b * KK + i;
        float* vr = g_V + (size_t)row * DN;
        __nv_bfloat16* ar = (__nv_bfloat16*)g_Abf2 + (size_t)row * KSPLIT;
        float* ovr = outV ? (outV + (size_t)row * DN) : nullptr;
        #pragma unroll
        for (int c3 = 0; c3 < 3; c3++) {
            int d = tid + c3 * 256;
            float nv = vr[d] + fmaxf(acc[i][c3], 0.f);
            vr[d] = nv;
            __nv_bfloat16 h = __float2bfloat16(nv);
            __nv_bfloat16 l = __float2bfloat16(nv - __bfloat162float(h));
            ar[d] = h; ar[768 + d] = h; ar[1536 + d] = l;
            if (ovr) ovr[d] = nv;
        }
    }
}

// ---------------- host ----------------------------------------------------
extern "C" void kernel_launch(void* const* d_in, const int* in_sizes, int n_in,
                              void* d_out, int out_size) {
    const float* w    = (const float*)d_in[0];
    const int*   mask = (const int*)  d_in[1];
    const float* nq   = (const float*)d_in[2];
    const float* Wq   = (const float*)d_in[3];
    const float* bq   = (const float*)d_in[4];
    const float* Wk   = (const float*)d_in[5];
    const float* bk   = (const float*)d_in[6];
    const float* Wv   = (const float*)d_in[7];
    const float* bv   = (const float*)d_in[8];
    const float* We1  = (const float*)d_in[9];
    const float* be1  = (const float*)d_in[10];
    const float* We2  = (const float*)d_in[11];
    const float* be2  = (const float*)d_in[12];
    const float* fg   = (const float*)d_in[13];
    const float* Wg   = (const float*)d_in[14];
    const float* bg   = (const float*)d_in[15];

    float* outS = (float*)d_out;
    float* outV = outS + (size_t)BB * NN * KK;
    float* outE = outV + (size_t)BB * KK * DN;

    kSplitAllW<<<1248, 256>>>(Wv, Wg, We1);
    kQ<<<48, 256>>>(nq, Wq, bq);
    kP<<<48, 256>>>(Wk, bk);
    kAttn<<<BB, 256>>>(w, mask, outS);                         // split-U -> g_Abf

    kTGemm<<<dim3(32, 6), 256>>>(0, 0, 1, bv, nq, fg);         // V = U@Wv; split-V -> Abf2
    kTGemm<<<dim3(32, 8), 256>>>(1, 3, 0, nullptr, nullptr, nullptr); // H = V@We1
    kEdge<<<BB, 256>>>(be1, We2, be2, nullptr, 0);             // A = softmax(E)
    kTGemm<<<dim3(32, 6), 256>>>(1, 1, 2, bg, nullptr, nullptr);      // M = V@Wg0+bg0
    kMsg<<<BB, 256>>>(nullptr);                                // V += relu(A@M); Abf2
    kTGemm<<<dim3(32, 6), 256>>>(1, 2, 2, bg + DN, nullptr, nullptr); // M = V@Wg1+bg1
    kMsg<<<BB, 256>>>(outV);                                   // final V; Abf2; outV
    kTGemm<<<dim3(32, 8), 256>>>(1, 3, 0, nullptr, nullptr, nullptr); // H on final V
    kEdge<<<BB, 256>>>(be1, We2, be2, outE, 1);                // E -> out
}

// round 5
// speedup vs baseline: 1.5109x; 1.0734x over previous
#include <cuda_runtime.h>
#include <cuda_bf16.h>
#include <math.h>
#include <stdint.h>

// Problem dims
#define BB 256
#define NN 77
#define DD 768
#define KK 16
#define DN 768
#define HID 512
#define MTOT (BB*KK)          // 4096
#define SCALE 0.10206207261596575f   // (768/8)^-0.5
#define KSPLIT 2304           // 3*768 (split-K concat)
#define KCH 72                // 2304/32 chunks

// ---------------- scratch (device globals; no allocation) ----------------
__device__ float g_Q[KK*DN];
__device__ float g_Qp[4][KK*DN];
__device__ float g_Pt[DD*KK];
__device__ float g_Pp[4][DD*KK];
__device__ float g_c[KK];
__device__ float g_cp[4][KK];
__device__ float g_V[MTOT*DN];
__device__ float g_rowsum[MTOT];
__device__ float g_H[MTOT*2*HID];
__device__ float g_M[MTOT*DN];
__device__ float g_A[BB*KK*KK];
// split-bf16 operand buffers (uint4 for 16B alignment)
__device__ uint4 g_Abf [(size_t)MTOT*KSPLIT/8];   // split-U
__device__ uint4 g_Abf2[(size_t)MTOT*KSPLIT/8];   // split-V
__device__ uint4 g_WbfV [768*KSPLIT/8];
__device__ uint4 g_WbfG0[768*KSPLIT/8];
__device__ uint4 g_WbfG1[768*KSPLIT/8];
__device__ uint4 g_WbfE1[1024*KSPLIT/8];

__device__ __forceinline__ uint32_t smem_u32(const void* p) {
    uint32_t a;
    asm("{ .reg .u64 t; cvta.to.shared.u64 t, %1; cvt.u32.u64 %0, t; }"
        : "=r"(a) : "l"(p));
    return a;
}

__device__ __forceinline__ unsigned packbf2(float a, float b) {
    unsigned short lo = __bfloat16_as_ushort(__float2bfloat16(a));
    unsigned short hi = __bfloat16_as_ushort(__float2bfloat16(b));
    return ((unsigned)hi << 16) | lo;
}

// ---------------- kQ: partial Q = nq @ Wq over e-slice --------------------
__global__ void kQ(const float* __restrict__ nq, const float* __restrict__ Wq) {
    int k = blockIdx.x / 3;
    int d = (blockIdx.x % 3) * 256 + threadIdx.x;
    int e0 = blockIdx.y * 192;
    const float* qrow = nq + k * DN + e0;
    const float* wcol = Wq + (size_t)e0 * DN + d;
    float acc = 0.f;
    #pragma unroll 8
    for (int e = 0; e < 192; e++) acc += qrow[e] * wcol[(size_t)e * DN];
    g_Qp[blockIdx.y][k * DN + d] = acc;
}
__global__ void kQr(const float* __restrict__ bq) {
    int i = blockIdx.x * 256 + threadIdx.x;   // 12288
    g_Q[i] = g_Qp[0][i] + g_Qp[1][i] + g_Qp[2][i] + g_Qp[3][i] + bq[i % DN];
}

// ---------------- kP: partial P^T[j][k] = Q[k].Wk[j,:] over e-slice ------
__global__ void kP(const float* __restrict__ Wk, const float* __restrict__ bk) {
    int tid = threadIdx.x;
    int j = blockIdx.x * 16 + (tid >> 4);
    int k = tid & 15;
    int e0 = blockIdx.y * 192;
    const float* qrow = g_Q + k * DN + e0;
    const float* wrow = Wk + (size_t)j * DN + e0;
    float acc = 0.f;
    #pragma unroll 8
    for (int e = 0; e < 192; e++) acc += qrow[e] * wrow[e];
    g_Pp[blockIdx.y][j * KK + k] = acc;
    if (blockIdx.x == 0 && tid < KK) {
        const float* qr = g_Q + tid * DN + e0;
        float cc = 0.f;
        for (int e = 0; e < 192; e++) cc += qr[e] * bk[e0 + e];
        g_cp[blockIdx.y][tid] = cc;
    }
}
__global__ void kPr() {
    int i = blockIdx.x * 256 + threadIdx.x;   // 12288
    g_Pt[i] = g_Pp[0][i] + g_Pp[1][i] + g_Pp[2][i] + g_Pp[3][i];
    if (i < KK) g_c[i] = g_cp[0][i] + g_cp[1][i] + g_cp[2][i] + g_cp[3][i];
}

// ---------------- kSplitAllW: all 4 weight splits, one launch ------------
__global__ void kSplitAllW(const float* __restrict__ Wv,
                           const float* __restrict__ Wg,
                           const float* __restrict__ We1) {
    int sid = blockIdx.x * 256 + threadIdx.x;   // 0..319487
    float a[8];
    __nv_bfloat16* out;
    int e0;
    if (sid < 221184) {
        int job = sid / 73728, s = sid % 73728;
        int n = s % 768, seg = s / 768;
        e0 = seg * 8;
        const float* Wp = (job == 0) ? Wv : (job == 1) ? Wg : (Wg + 768 * 768);
        uint4* o4 = (job == 0) ? g_WbfV : (job == 1) ? g_WbfG0 : g_WbfG1;
        out = (__nv_bfloat16*)o4 + (size_t)n * KSPLIT;
        #pragma unroll
        for (int i = 0; i < 8; i++) a[i] = Wp[(size_t)(e0 + i) * 768 + n];
    } else {
        int s = sid - 221184;
        int n = s % 1024, seg = s / 1024;
        e0 = seg * 8;
        out = (__nv_bfloat16*)g_WbfE1 + (size_t)n * KSPLIT;
        size_t base = (n < HID) ? (size_t)n : ((size_t)768 * HID + (n - HID));
        #pragma unroll
        for (int i = 0; i < 8; i++) a[i] = We1[base + (size_t)(e0 + i) * HID];
    }
    unsigned h[4], l[4];
    #pragma unroll
    for (int i = 0; i < 4; i++) {
        float x = a[2 * i], y = a[2 * i + 1];
        float xh = __bfloat162float(__float2bfloat16(x));
        float yh = __bfloat162float(__float2bfloat16(y));
        h[i] = packbf2(x, y);
        l[i] = packbf2(x - xh, y - yh);
    }
    *(uint4*)(out + e0)        = *(uint4*)h;
    *(uint4*)(out + 768 + e0)  = *(uint4*)l;
    *(uint4*)(out + 1536 + e0) = *(uint4*)h;
}

// ---------------- kScore: scores -> softmax -> outS + rowsum --------------
__global__ void kScore(const float* __restrict__ w, const int* __restrict__ mask,
                       float* __restrict__ outS) {
    int b = blockIdx.x;
    int tid = threadIdx.x;
    int ty = tid >> 4, tx = tid & 15;   // ty = k
    __shared__ float sW[80 * 65];       // [n][dd], rows 77..79 zero
    __shared__ float sP[64 * KK];
    __shared__ float sSc[KK * 80];
    __shared__ float sSm[NN * KK];

    float acc[5] = {0.f, 0.f, 0.f, 0.f, 0.f};
    for (int d0 = 0; d0 < DD; d0 += 64) {
        for (int idx = tid; idx < 80 * 64; idx += 256) {
            int n = idx >> 6, dd = idx & 63;
            sW[n * 65 + dd] = (n < NN) ? w[(b * NN + n) * DD + d0 + dd] : 0.f;
        }
        for (int idx = tid; idx < 64 * KK; idx += 256)
            sP[idx] = g_Pt[d0 * KK + idx];
        __syncthreads();
        #pragma unroll 4
        for (int dd = 0; dd < 64; dd++) {
            float p = sP[dd * KK + ty];
            #pragma unroll
            for (int i = 0; i < 5; i++)
                acc[i] += p * sW[(tx + 16 * i) * 65 + dd];
        }
        __syncthreads();
    }
    float ck = g_c[ty];
    #pragma unroll
    for (int i = 0; i < 5; i++) {
        int n = tx + 16 * i;
        if (n < NN) sSc[ty * 80 + n] = (acc[i] + ck) * SCALE;
    }
    __syncthreads();

    if (tid < NN) {
        int n = tid;
        if (mask[b * NN + n] == 0) {
            #pragma unroll
            for (int k = 0; k < KK; k++) sSm[n * KK + k] = 1.0f / 16.0f;
        } else {
            float m = -3.4e38f;
            #pragma unroll
            for (int k = 0; k < KK; k++) m = fmaxf(m, sSc[k * 80 + n]);
            float e[KK]; float s = 0.f;
            #pragma unroll
            for (int k = 0; k < KK; k++) { e[k] = __expf(sSc[k * 80 + n] - m); s += e[k]; }
            float inv = 1.0f / s;
            #pragma unroll
            for (int k = 0; k < KK; k++) sSm[n * KK + k] = e[k] * inv;
        }
        #pragma unroll
        for (int k = 0; k < KK; k++)
            outS[(b * NN + n) * KK + k] = sSm[n * KK + k];
    }
    __syncthreads();
    if (tid < KK) {
        float s = 0.f;
        for (int n = 0; n < NN; n++) s += sSm[n * KK + tid];
        g_rowsum[b * KK + tid] = s;
    }
}

// ---------------- kU: U = S^T w, write split-U -> g_Abf -------------------
// grid (BB, 2), 96 threads; thread owns 4 adjacent d
__global__ void kU(const float* __restrict__ w, const float* __restrict__ S) {
    int b = blockIdx.x, dh = blockIdx.y;
    int tid = threadIdx.x;
    int d0 = dh * 384 + tid * 4;
    __shared__ float sS[NN * KK];
    for (int idx = tid; idx < NN * KK; idx += 96)
        sS[idx] = S[b * NN * KK + idx];
    __syncthreads();

    float4 acc[KK];
    #pragma unroll
    for (int k = 0; k < KK; k++) { acc[k].x = 0.f; acc[k].y = 0.f; acc[k].z = 0.f; acc[k].w = 0.f; }
    const float* wp = w + (size_t)b * NN * DD + d0;
    #pragma unroll 2
    for (int n = 0; n < NN; n++) {
        float4 wv = *(const float4*)(wp + (size_t)n * DD);
        const float* srow = sS + n * KK;
        #pragma unroll
        for (int k = 0; k < KK; k++) {
            float s = srow[k];
            acc[k].x += s * wv.x; acc[k].y += s * wv.y;
            acc[k].z += s * wv.z; acc[k].w += s * wv.w;
        }
    }
    #pragma unroll
    for (int k = 0; k < KK; k++) {
        float4 v = acc[k];
        float hx = __bfloat162float(__float2bfloat16(v.x));
        float hy = __bfloat162float(__float2bfloat16(v.y));
        float hz = __bfloat162float(__float2bfloat16(v.z));
        float hw = __bfloat162float(__float2bfloat16(v.w));
        uint2 hp, lp;
        hp.x = packbf2(v.x, v.y); hp.y = packbf2(v.z, v.w);
        lp.x = packbf2(v.x - hx, v.y - hy); lp.y = packbf2(v.z - hz, v.w - hw);
        __nv_bfloat16* ur = (__nv_bfloat16*)g_Abf + (size_t)(b * KK + k) * KSPLIT;
        *(uint2*)(ur + d0) = hp;
        *(uint2*)(ur + 768 + d0) = hp;
        *(uint2*)(ur + 1536 + d0) = lp;
    }
}

// ---------------- kTGemm: mma.sync bf16-split GEMM, 3-stage pipeline ------
// asel: 0 = g_Abf (split U), 1 = g_Abf2 (split V)
// wsel: 0=WbfV, 1=WbfG0, 2=WbfG1, 3=WbfE1
// mode: 0 -> C=g_H (Ncols=1024); 1 -> C=g_V + split-V into g_Abf2; 2 -> C=g_M (+bg)
__global__ __launch_bounds__(256, 2) void kTGemm(
    int asel, int wsel, int mode, const float* __restrict__ bias,
    const float* __restrict__ nq, const float* __restrict__ gatep)
{
    __shared__ __align__(1024) __nv_bfloat16 sA[3][128 * 32];
    __shared__ __align__(1024) __nv_bfloat16 sB[3][128 * 32];

    const __nv_bfloat16* Ag = (const __nv_bfloat16*)(asel ? g_Abf2 : g_Abf);
    const uint4* B4 = (wsel == 0) ? g_WbfV : (wsel == 1) ? g_WbfG0
                    : (wsel == 2) ? g_WbfG1 : g_WbfE1;
    const __nv_bfloat16* Bg = (const __nv_bfloat16*)B4;
    float* C; int Ncols;
    if (mode == 0)      { C = g_H; Ncols = 2 * HID; }
    else if (mode == 1) { C = g_V; Ncols = DN; }
    else                { C = g_M; Ncols = DN; }

    const int tid = threadIdx.x;
    const int lane = tid & 31, warp = tid >> 5;
    const int wm = warp >> 2, wn = warp & 3;          // warps 2x4, tile 64x32
    const int m0 = blockIdx.x * 128, n0 = blockIdx.y * 128;

    const uint32_t sAu = smem_u32(sA), sBu = smem_u32(sB);

    uint32_t soff[2];
    const __nv_bfloat16* gA[2];
    const __nv_bfloat16* gB[2];
    #pragma unroll
    for (int i = 0; i < 2; i++) {
        int v = tid * 2 + i, row = v >> 2, q = v & 3;
        soff[i] = row * 64 + ((q ^ ((row >> 1) & 3)) << 4);
        gA[i] = Ag + (size_t)(m0 + row) * KSPLIT + q * 8;
        gB[i] = Bg + (size_t)(n0 + row) * KSPLIT + q * 8;
    }

    // precomputed ldmatrix offsets (relative to stage base)
    const int r16 = lane & 15, hh = lane >> 4;
    uint32_t aoff[2][4], boff[2][2];
    #pragma unroll
    for (int s = 0; s < 2; s++) {
        int quad = 2 * s + hh;
        #pragma unroll
        for (int mt = 0; mt < 4; mt++) {
            int row = wm * 64 + mt * 16 + r16;
            aoff[s][mt] = row * 64 + ((quad ^ ((row >> 1) & 3)) << 4);
        }
        #pragma unroll
        for (int nb = 0; nb < 2; nb++) {
            int row = wn * 32 + nb * 16 + r16;
            boff[s][nb] = row * 64 + ((quad ^ ((row >> 1) & 3)) << 4);
        }
    }

    float acc[4][4][4];
    #pragma unroll
    for (int a = 0; a < 4; a++)
        #pragma unroll
        for (int b = 0; b < 4; b++)
            #pragma unroll
            for (int r = 0; r < 4; r++) acc[a][b][r] = 0.f;

    // prologue: stages 0,1
    #pragma unroll
    for (int st = 0; st < 2; st++) {
        uint32_t da = sAu + st * 8192, db = sBu + st * 8192;
        #pragma unroll
        for (int i = 0; i < 2; i++) {
            asm volatile("cp.async.ca.shared.global [%0], [%1], 16;"
                         :: "r"(da + soff[i]), "l"(gA[i] + st * 32));
            asm volatile("cp.async.ca.shared.global [%0], [%1], 16;"
                         :: "r"(db + soff[i]), "l"(gB[i] + st * 32));
        }
        asm volatile("cp.async.commit_group;");
    }

    for (int c = 0; c < KCH; c++) {
        const int buf = c % 3;
        if (c + 1 < KCH) asm volatile("cp.async.wait_group 1;");
        else             asm volatile("cp.async.wait_group 0;");
        __syncthreads();
        if (c + 2 < KCH) {
            const int wb = (c + 2) % 3;
            const uint32_t da = sAu + wb * 8192, db = sBu + wb * 8192;
            #pragma unroll
            for (int i = 0; i < 2; i++) {
                asm volatile("cp.async.ca.shared.global [%0], [%1], 16;"
                             :: "r"(da + soff[i]), "l"(gA[i] + (c + 2) * 32));
                asm volatile("cp.async.ca.shared.global [%0], [%1], 16;"
                             :: "r"(db + soff[i]), "l"(gB[i] + (c + 2) * 32));
            }
            asm volatile("cp.async.commit_group;");
        }

        const uint32_t baseA = sAu + buf * 8192;
        const uint32_t baseB = sBu + buf * 8192;
        #pragma unroll
        for (int s = 0; s < 2; s++) {
            uint32_t afr[4][4];
            #pragma unroll
            for (int mt = 0; mt < 4; mt++) {
                asm volatile("ldmatrix.sync.aligned.m8n8.x4.shared.b16 "
                             "{%0,%1,%2,%3}, [%4];"
                             : "=r"(afr[mt][0]), "=r"(afr[mt][1]),
                               "=r"(afr[mt][2]), "=r"(afr[mt][3])
                             : "r"(baseA + aoff[s][mt]));
            }
            uint32_t bfr[4][2];
            #pragma unroll
            for (int nb = 0; nb < 2; nb++) {
                uint32_t r0, r1, r2, r3;
                asm volatile("ldmatrix.sync.aligned.m8n8.x4.shared.b16 "
                             "{%0,%1,%2,%3}, [%4];"
                             : "=r"(r0), "=r"(r1), "=r"(r2), "=r"(r3)
                             : "r"(baseB + boff[s][nb]));
                bfr[nb * 2][0] = r0;     bfr[nb * 2][1] = r2;
                bfr[nb * 2 + 1][0] = r1; bfr[nb * 2 + 1][1] = r3;
            }
            #pragma unroll
            for (int mt = 0; mt < 4; mt++)
                #pragma unroll
                for (int nt = 0; nt < 4; nt++) {
                    asm volatile(
                        "mma.sync.aligned.m16n8k16.row.col.f32.bf16.bf16.f32 "
                        "{%0,%1,%2,%3}, {%4,%5,%6,%7}, {%8,%9}, {%0,%1,%2,%3};"
                        : "+f"(acc[mt][nt][0]), "+f"(acc[mt][nt][1]),
                          "+f"(acc[mt][nt][2]), "+f"(acc[mt][nt][3])
                        : "r"(afr[mt][0]), "r"(afr[mt][1]),
                          "r"(afr[mt][2]), "r"(afr[mt][3]),
                          "r"(bfr[nt][0]), "r"(bfr[nt][1]));
                }
        }
    }

    // epilogue
    float gate = 0.f, omg = 1.f;
    if (mode == 1) {
        gate = 1.0f / (1.0f + expf(-gatep[0]));
        omg = 1.0f - gate;
    }
    #pragma unroll
    for (int mt = 0; mt < 4; mt++) {
        #pragma unroll
        for (int half = 0; half < 2; half++) {
            int row = m0 + wm * 64 + mt * 16 + (lane >> 2) + 8 * half;
            float rsv = 0.f; const float* nqr = nullptr;
            __nv_bfloat16* arow = nullptr;
            if (mode == 1) {
                rsv = g_rowsum[row];
                nqr = nq + (size_t)(row & 15) * DN;
                arow = (__nv_bfloat16*)g_Abf2 + (size_t)row * KSPLIT;
            }
            float* crow = C + (size_t)row * Ncols;
            #pragma unroll
            for (int nt = 0; nt < 4; nt++) {
                int col = n0 + wn * 32 + nt * 8 + (lane & 3) * 2;
                float v0 = acc[mt][nt][half * 2 + 0];
                float v1 = acc[mt][nt][half * 2 + 1];
                if (mode == 1) {
                    v0 += rsv * __ldg(&bias[col]);
                    v1 += rsv * __ldg(&bias[col + 1]);
                    v0 = omg * v0 + gate * __ldg(&nqr[col]);
                    v1 = omg * v1 + gate * __ldg(&nqr[col + 1]);
                    float h0 = __bfloat162float(__float2bfloat16(v0));
                    float h1 = __bfloat162float(__float2bfloat16(v1));
                    unsigned hp = packbf2(v0, v1);
                    unsigned lp = packbf2(v0 - h0, v1 - h1);
                    *(unsigned*)(arow + col) = hp;
                    *(unsigned*)(arow + 768 + col) = hp;
                    *(unsigned*)(arow + 1536 + col) = lp;
                } else if (mode == 2) {
                    v0 += __ldg(&bias[col]);
                    v1 += __ldg(&bias[col + 1]);
                }
                float2 o; o.x = v0; o.y = v1;
                *(float2*)(crow + col) = o;
            }
        }
    }
}

// ---------------- kEdge ----------------------------------------------
__global__ void kEdge(const float* __restrict__ be1, const float* __restrict__ We2,
                      const float* __restrict__ be2, float* __restrict__ outE,
                      int post) {
    int b = blockIdx.x;
    int tid = threadIdx.x;
    int i = tid >> 4, j = tid & 15;
    __shared__ float sHi[KK * 257];
    __shared__ float sHj[KK * 257];
    __shared__ float sW2[256];
    __shared__ float sE[KK * 17];

    float acc = 0.f;
    for (int h0 = 0; h0 < HID; h0 += 256) {
        for (int idx = tid; idx < KK * 256; idx += 256) {
            int r = idx >> 8, c = idx & 255;
            sHi[r * 257 + c] = g_H[(size_t)(b * KK + r) * (2 * HID) + h0 + c] + be1[h0 + c];
            sHj[r * 257 + c] = g_H[(size_t)(b * KK + r) * (2 * HID) + HID + h0 + c];
        }
        sW2[tid] = We2[h0 + tid];
        __syncthreads();
        const float* hi = sHi + i * 257;
        const float* hj = sHj + j * 257;
        float a0 = 0.f, a1 = 0.f, a2 = 0.f, a3 = 0.f;
        #pragma unroll 4
        for (int c = 0; c < 256; c += 4) {
            a0 += fmaxf(hi[c]     + hj[c],     0.f) * sW2[c];
            a1 += fmaxf(hi[c + 1] + hj[c + 1], 0.f) * sW2[c + 1];
            a2 += fmaxf(hi[c + 2] + hj[c + 2], 0.f) * sW2[c + 2];
            a3 += fmaxf(hi[c + 3] + hj[c + 3], 0.f) * sW2[c + 3];
        }
        acc += (a0 + a1) + (a2 + a3);
        __syncthreads();
    }
    float E = acc + be2[0];
    if (post) {
        outE[b * 256 + tid] = E;
    } else {
        sE[i * 17 + j] = E;
        __syncthreads();
        float m = -3.4e38f;
        #pragma unroll
        for (int jj = 0; jj < KK; jj++) m = fmaxf(m, sE[i * 17 + jj]);
        float s = 0.f;
        #pragma unroll
        for (int jj = 0; jj < KK; jj++) s += __expf(sE[i * 17 + jj] - m);
        g_A[b * 256 + tid] = __expf(E - m) / s;
    }
}

// ---------------- kMsg: V += relu(A @ M), write split-V (+optional outV) --
__global__ void kMsg(float* __restrict__ outV) {
    int b = blockIdx.x;
    int tid = threadIdx.x;
    __shared__ float sAm[KK * 17];
    sAm[(tid >> 4) * 17 + (tid & 15)] = g_A[b * 256 + tid];
    __syncthreads();
    float acc[KK][3];
    #pragma unroll
    for (int i = 0; i < KK; i++) { acc[i][0] = 0.f; acc[i][1] = 0.f; acc[i][2] = 0.f; }
    for (int j = 0; j < KK; j++) {
        const float* mr = g_M + (size_t)(b * KK + j) * DN + tid;
        float m0 = mr[0], m1 = mr[256], m2 = mr[512];
        #pragma unroll
        for (int i = 0; i < KK; i++) {
            float a = sAm[i * 17 + j];
            acc[i][0] += a * m0; acc[i][1] += a * m1; acc[i][2] += a * m2;
        }
    }
    #pragma unroll
    for (int i = 0; i < KK; i++) {
        int row = b * KK + i;
        float* vr = g_V + (size_t)row * DN;
        __nv_bfloat16* ar = (__nv_bfloat16*)g_Abf2 + (size_t)row * KSPLIT;
        float* ovr = outV ? (outV + (size_t)row * DN) : nullptr;
        #pragma unroll
        for (int c3 = 0; c3 < 3; c3++) {
            int d = tid + c3 * 256;
            float nv = vr[d] + fmaxf(acc[i][c3], 0.f);
            vr[d] = nv;
            __nv_bfloat16 h = __float2bfloat16(nv);
            __nv_bfloat16 l = __float2bfloat16(nv - __bfloat162float(h));
            ar[d] = h; ar[768 + d] = h; ar[1536 + d] = l;
            if (ovr) ovr[d] = nv;
        }
    }
}

// ---------------- host ----------------------------------------------------
extern "C" void kernel_launch(void* const* d_in, const int* in_sizes, int n_in,
                              void* d_out, int out_size) {
    const float* w    = (const float*)d_in[0];
    const int*   mask = (const int*)  d_in[1];
    const float* nq   = (const float*)d_in[2];
    const float* Wq   = (const float*)d_in[3];
    const float* bq   = (const float*)d_in[4];
    const float* Wk   = (const float*)d_in[5];
    const float* bk   = (const float*)d_in[6];
    const float* Wv   = (const float*)d_in[7];
    const float* bv   = (const float*)d_in[8];
    const float* We1  = (const float*)d_in[9];
    const float* be1  = (const float*)d_in[10];
    const float* We2  = (const float*)d_in[11];
    const float* be2  = (const float*)d_in[12];
    const float* fg   = (const float*)d_in[13];
    const float* Wg   = (const float*)d_in[14];
    const float* bg   = (const float*)d_in[15];

    float* outS = (float*)d_out;
    float* outV = outS + (size_t)BB * NN * KK;
    float* outE = outV + (size_t)BB * KK * DN;

    kSplitAllW<<<1248, 256>>>(Wv, Wg, We1);
    kQ<<<dim3(48, 4), 256>>>(nq, Wq);
    kQr<<<48, 256>>>(bq);
    kP<<<dim3(48, 4), 256>>>(Wk, bk);
    kPr<<<48, 256>>>();
    kScore<<<BB, 256>>>(w, mask, outS);
    kU<<<dim3(BB, 2), 96>>>(w, outS);                          // split-U -> g_Abf

    kTGemm<<<dim3(32, 6), 256>>>(0, 0, 1, bv, nq, fg);         // V = U@Wv; split-V -> Abf2
    kTGemm<<<dim3(32, 8), 256>>>(1, 3, 0, nullptr, nullptr, nullptr); // H = V@We1
    kEdge<<<BB, 256>>>(be1, We2, be2, nullptr, 0);             // A = softmax(E)
    kTGemm<<<dim3(32, 6), 256>>>(1, 1, 2, bg, nullptr, nullptr);      // M = V@Wg0+bg0
    kMsg<<<BB, 256>>>(nullptr);                                // V += relu(A@M); Abf2
    kTGemm<<<dim3(32, 6), 256>>>(1, 2, 2, bg + DN, nullptr, nullptr); // M = V@Wg1+bg1
    kMsg<<<BB, 256>>>(outV);                                   // final V; Abf2; outV
    kTGemm<<<dim3(32, 8), 256>>>(1, 3, 0, nullptr, nullptr, nullptr); // H on final V
    kEdge<<<BB, 256>>>(be1, We2, be2, outE, 1);                // E -> out
}

// round 6
// speedup vs baseline: 1.7662x; 1.1689x over previous
#include <cuda_runtime.h>
#include <cuda_bf16.h>
#include <math.h>
#include <stdint.h>

// Problem dims
#define BB 256
#define NN 77
#define DD 768
#define KK 16
#define DN 768
#define HID 512
#define MTOT (BB*KK)          // 4096
#define SCALE 0.10206207261596575f   // (768/8)^-0.5
#define KSPLIT 2304           // 3*768 (split-K concat)
#define KCH 72                // 2304/32 chunks

// ---------------- scratch (device globals; no allocation) ----------------
__device__ float g_Q[KK*DN];
__device__ float g_Qp[8][KK*DN];
__device__ float g_Pt[DD*KK];
__device__ float g_c[KK];
__device__ float g_V[MTOT*DN];
__device__ float g_rowsum[MTOT];
__device__ float g_H[MTOT*2*HID];
__device__ float g_M[MTOT*DN];
__device__ float g_A[BB*KK*KK];
// split-bf16 operand buffers (uint4 for 16B alignment)
__device__ uint4 g_Abf [(size_t)MTOT*KSPLIT/8];   // split-U
__device__ uint4 g_Abf2[(size_t)MTOT*KSPLIT/8];   // split-V
__device__ uint4 g_WbfV [768*KSPLIT/8];
__device__ uint4 g_WbfG0[768*KSPLIT/8];
__device__ uint4 g_WbfG1[768*KSPLIT/8];
__device__ uint4 g_WbfE1[1024*KSPLIT/8];

__device__ __forceinline__ uint32_t smem_u32(const void* p) {
    uint32_t a;
    asm("{ .reg .u64 t; cvta.to.shared.u64 t, %1; cvt.u32.u64 %0, t; }"
        : "=r"(a) : "l"(p));
    return a;
}

__device__ __forceinline__ unsigned packbf2(float a, float b) {
    unsigned short lo = __bfloat16_as_ushort(__float2bfloat16(a));
    unsigned short hi = __bfloat16_as_ushort(__float2bfloat16(b));
    return ((unsigned)hi << 16) | lo;
}

// ---------------- kQ: partial Q = nq @ Wq (Wq read once) ------------------
// grid (3, 8): d-chunk 256, e-slice 96
__global__ void kQ(const float* __restrict__ nq, const float* __restrict__ Wq) {
    int d = blockIdx.x * 256 + threadIdx.x;
    int sl = blockIdx.y;
    int e0 = sl * 96;
    __shared__ float snq[KK][96];
    for (int idx = threadIdx.x; idx < KK * 96; idx += 256)
        snq[idx / 96][idx % 96] = nq[(idx / 96) * DN + e0 + idx % 96];
    __syncthreads();
    float acc[KK];
    #pragma unroll
    for (int k = 0; k < KK; k++) acc[k] = 0.f;
    const float* wp = Wq + (size_t)e0 * DN + d;
    #pragma unroll 4
    for (int e = 0; e < 96; e++) {
        float wv = wp[(size_t)e * DN];
        #pragma unroll
        for (int k = 0; k < KK; k++) acc[k] += snq[k][e] * wv;
    }
    #pragma unroll
    for (int k = 0; k < KK; k++) g_Qp[sl][k * DN + d] = acc[k];
}
__global__ void kQr(const float* __restrict__ bq) {
    int i = blockIdx.x * 256 + threadIdx.x;   // 12288
    float s = bq[i % DN];
    #pragma unroll
    for (int sl = 0; sl < 8; sl++) s += g_Qp[sl][i];
    g_Q[i] = s;
}

// ---------------- kP: P^T[j][k] = Wk[j,:].Q[k,:] (warp per j) -------------
// grid 96 x 256; blocks 94,95 additionally compute c[k] = Q[k].bk
__global__ void kP(const float* __restrict__ Wk, const float* __restrict__ bk) {
    __shared__ float sQ[KK][DN];   // 48 KB
    int tid = threadIdx.x;
    int lane = tid & 31, warp = tid >> 5;
    for (int idx = tid; idx < KK * DN; idx += 256)
        sQ[idx / DN][idx % DN] = g_Q[idx];
    __syncthreads();

    int j = blockIdx.x * 8 + warp;
    const float4* wr = (const float4*)(Wk + (size_t)j * DN);
    float acc[KK];
    #pragma unroll
    for (int k = 0; k < KK; k++) acc[k] = 0.f;
    #pragma unroll
    for (int it = 0; it < 6; it++) {
        int e = it * 128 + lane * 4;
        float4 wv = wr[it * 32 + lane];
        #pragma unroll
        for (int k = 0; k < KK; k++) {
            float4 qv = *(const float4*)&sQ[k][e];
            acc[k] += wv.x * qv.x + wv.y * qv.y + wv.z * qv.z + wv.w * qv.w;
        }
    }
    float out = 0.f;
    #pragma unroll
    for (int k = 0; k < KK; k++) {
        float v = acc[k];
        v += __shfl_xor_sync(0xFFFFFFFFu, v, 16);
        v += __shfl_xor_sync(0xFFFFFFFFu, v, 8);
        v += __shfl_xor_sync(0xFFFFFFFFu, v, 4);
        v += __shfl_xor_sync(0xFFFFFFFFu, v, 2);
        v += __shfl_xor_sync(0xFFFFFFFFu, v, 1);
        if (lane == k) out = v;
    }
    if (lane < KK) g_Pt[j * KK + lane] = out;

    if (blockIdx.x >= 94) {
        int k = (blockIdx.x - 94) * 8 + warp;
        float cc = 0.f;
        #pragma unroll
        for (int it = 0; it < 6; it++) {
            int e = it * 128 + lane * 4;
            float4 bv = *(const float4*)(bk + e);
            float4 qv = *(const float4*)&sQ[k][e];
            cc += bv.x * qv.x + bv.y * qv.y + bv.z * qv.z + bv.w * qv.w;
        }
        cc += __shfl_xor_sync(0xFFFFFFFFu, cc, 16);
        cc += __shfl_xor_sync(0xFFFFFFFFu, cc, 8);
        cc += __shfl_xor_sync(0xFFFFFFFFu, cc, 4);
        cc += __shfl_xor_sync(0xFFFFFFFFu, cc, 2);
        cc += __shfl_xor_sync(0xFFFFFFFFu, cc, 1);
        if (lane == 0) g_c[k] = cc;
    }
}

// ---------------- kSplitAllW: all 4 weight splits, one launch ------------
__global__ void kSplitAllW(const float* __restrict__ Wv,
                           const float* __restrict__ Wg,
                           const float* __restrict__ We1) {
    int sid = blockIdx.x * 256 + threadIdx.x;   // 0..319487
    float a[8];
    __nv_bfloat16* out;
    int e0;
    if (sid < 221184) {
        int job = sid / 73728, s = sid % 73728;
        int n = s % 768, seg = s / 768;
        e0 = seg * 8;
        const float* Wp = (job == 0) ? Wv : (job == 1) ? Wg : (Wg + 768 * 768);
        uint4* o4 = (job == 0) ? g_WbfV : (job == 1) ? g_WbfG0 : g_WbfG1;
        out = (__nv_bfloat16*)o4 + (size_t)n * KSPLIT;
        #pragma unroll
        for (int i = 0; i < 8; i++) a[i] = Wp[(size_t)(e0 + i) * 768 + n];
    } else {
        int s = sid - 221184;
        int n = s % 1024, seg = s / 1024;
        e0 = seg * 8;
        out = (__nv_bfloat16*)g_WbfE1 + (size_t)n * KSPLIT;
        size_t base = (n < HID) ? (size_t)n : ((size_t)768 * HID + (n - HID));
        #pragma unroll
        for (int i = 0; i < 8; i++) a[i] = We1[base + (size_t)(e0 + i) * HID];
    }
    unsigned h[4], l[4];
    #pragma unroll
    for (int i = 0; i < 4; i++) {
        float x = a[2 * i], y = a[2 * i + 1];
        float xh = __bfloat162float(__float2bfloat16(x));
        float yh = __bfloat162float(__float2bfloat16(y));
        h[i] = packbf2(x, y);
        l[i] = packbf2(x - xh, y - yh);
    }
    *(uint4*)(out + e0)        = *(uint4*)h;
    *(uint4*)(out + 768 + e0)  = *(uint4*)l;
    *(uint4*)(out + 1536 + e0) = *(uint4*)h;
}

// ---------------- kScore: scores -> softmax -> outS + rowsum --------------
__global__ void kScore(const float* __restrict__ w, const int* __restrict__ mask,
                       float* __restrict__ outS) {
    int b = blockIdx.x;
    int tid = threadIdx.x;
    int ty = tid >> 4, tx = tid & 15;   // ty = k
    __shared__ float sW[80 * 68];       // [n][dd] pitch 68 (16B aligned rows)
    __shared__ float sP[64 * KK];
    __shared__ float sSc[KK * 80];
    __shared__ float sSm[NN * KK];

    float acc[5] = {0.f, 0.f, 0.f, 0.f, 0.f};
    for (int d0 = 0; d0 < DD; d0 += 64) {
        for (int idx = tid; idx < 80 * 64; idx += 256) {
            int n = idx >> 6, dd = idx & 63;
            sW[n * 68 + dd] = (n < NN) ? w[(b * NN + n) * DD + d0 + dd] : 0.f;
        }
        for (int idx = tid; idx < 64 * KK; idx += 256)
            sP[idx] = g_Pt[d0 * KK + idx];
        __syncthreads();
        #pragma unroll 2
        for (int dd = 0; dd < 64; dd += 4) {
            float p0 = sP[(dd + 0) * KK + ty];
            float p1 = sP[(dd + 1) * KK + ty];
            float p2 = sP[(dd + 2) * KK + ty];
            float p3 = sP[(dd + 3) * KK + ty];
            #pragma unroll
            for (int i = 0; i < 5; i++) {
                float4 wv = *(const float4*)&sW[(tx + 16 * i) * 68 + dd];
                acc[i] += p0 * wv.x + p1 * wv.y + p2 * wv.z + p3 * wv.w;
            }
        }
        __syncthreads();
    }
    float ck = g_c[ty];
    #pragma unroll
    for (int i = 0; i < 5; i++) {
        int n = tx + 16 * i;
        if (n < NN) sSc[ty * 80 + n] = (acc[i] + ck) * SCALE;
    }
    __syncthreads();

    if (tid < NN) {
        int n = tid;
        if (mask[b * NN + n] == 0) {
            #pragma unroll
            for (int k = 0; k < KK; k++) sSm[n * KK + k] = 1.0f / 16.0f;
        } else {
            float m = -3.4e38f;
            #pragma unroll
            for (int k = 0; k < KK; k++) m = fmaxf(m, sSc[k * 80 + n]);
            float e[KK]; float s = 0.f;
            #pragma unroll
            for (int k = 0; k < KK; k++) { e[k] = __expf(sSc[k * 80 + n] - m); s += e[k]; }
            float inv = 1.0f / s;
            #pragma unroll
            for (int k = 0; k < KK; k++) sSm[n * KK + k] = e[k] * inv;
        }
        #pragma unroll
        for (int k = 0; k < KK; k++)
            outS[(b * NN + n) * KK + k] = sSm[n * KK + k];
    }
    __syncthreads();
    if (tid < KK) {
        float s = 0.f;
        for (int n = 0; n < NN; n++) s += sSm[n * KK + tid];
        g_rowsum[b * KK + tid] = s;
    }
}

// ---------------- kU: U = S^T w, write split-U -> g_Abf -------------------
__global__ void kU(const float* __restrict__ w, const float* __restrict__ S) {
    int b = blockIdx.x, dh = blockIdx.y;
    int tid = threadIdx.x;
    int d0 = dh * 384 + tid * 4;
    __shared__ float sS[NN * KK];
    for (int idx = tid; idx < NN * KK; idx += 96)
        sS[idx] = S[b * NN * KK + idx];
    __syncthreads();

    float4 acc[KK];
    #pragma unroll
    for (int k = 0; k < KK; k++) { acc[k].x = 0.f; acc[k].y = 0.f; acc[k].z = 0.f; acc[k].w = 0.f; }
    const float* wp = w + (size_t)b * NN * DD + d0;
    #pragma unroll 2
    for (int n = 0; n < NN; n++) {
        float4 wv = *(const float4*)(wp + (size_t)n * DD);
        const float* srow = sS + n * KK;
        #pragma unroll
        for (int k = 0; k < KK; k++) {
            float s = srow[k];
            acc[k].x += s * wv.x; acc[k].y += s * wv.y;
            acc[k].z += s * wv.z; acc[k].w += s * wv.w;
        }
    }
    #pragma unroll
    for (int k = 0; k < KK; k++) {
        float4 v = acc[k];
        float hx = __bfloat162float(__float2bfloat16(v.x));
        float hy = __bfloat162float(__float2bfloat16(v.y));
        float hz = __bfloat162float(__float2bfloat16(v.z));
        float hw = __bfloat162float(__float2bfloat16(v.w));
        uint2 hp, lp;
        hp.x = packbf2(v.x, v.y); hp.y = packbf2(v.z, v.w);
        lp.x = packbf2(v.x - hx, v.y - hy); lp.y = packbf2(v.z - hz, v.w - hw);
        __nv_bfloat16* ur = (__nv_bfloat16*)g_Abf + (size_t)(b * KK + k) * KSPLIT;
        *(uint2*)(ur + d0) = hp;
        *(uint2*)(ur + 768 + d0) = hp;
        *(uint2*)(ur + 1536 + d0) = lp;
    }
}

// ---------------- kTGemm: mma.sync bf16-split GEMM, 3-stage pipeline ------
__global__ __launch_bounds__(256, 2) void kTGemm(
    int asel, int wsel, int mode, const float* __restrict__ bias,
    const float* __restrict__ nq, const float* __restrict__ gatep)
{
    __shared__ __align__(1024) __nv_bfloat16 sA[3][128 * 32];
    __shared__ __align__(1024) __nv_bfloat16 sB[3][128 * 32];

    const __nv_bfloat16* Ag = (const __nv_bfloat16*)(asel ? g_Abf2 : g_Abf);
    const uint4* B4 = (wsel == 0) ? g_WbfV : (wsel == 1) ? g_WbfG0
                    : (wsel == 2) ? g_WbfG1 : g_WbfE1;
    const __nv_bfloat16* Bg = (const __nv_bfloat16*)B4;
    float* C; int Ncols;
    if (mode == 0)      { C = g_H; Ncols = 2 * HID; }
    else if (mode == 1) { C = g_V; Ncols = DN; }
    else                { C = g_M; Ncols = DN; }

    const int tid = threadIdx.x;
    const int lane = tid & 31, warp = tid >> 5;
    const int wm = warp >> 2, wn = warp & 3;
    const int m0 = blockIdx.x * 128, n0 = blockIdx.y * 128;

    const uint32_t sAu = smem_u32(sA), sBu = smem_u32(sB);

    uint32_t soff[2];
    const __nv_bfloat16* gA[2];
    const __nv_bfloat16* gB[2];
    #pragma unroll
    for (int i = 0; i < 2; i++) {
        int v = tid * 2 + i, row = v >> 2, q = v & 3;
        soff[i] = row * 64 + ((q ^ ((row >> 1) & 3)) << 4);
        gA[i] = Ag + (size_t)(m0 + row) * KSPLIT + q * 8;
        gB[i] = Bg + (size_t)(n0 + row) * KSPLIT + q * 8;
    }

    const int r16 = lane & 15, hh = lane >> 4;
    uint32_t aoff[2][4], boff[2][2];
    #pragma unroll
    for (int s = 0; s < 2; s++) {
        int quad = 2 * s + hh;
        #pragma unroll
        for (int mt = 0; mt < 4; mt++) {
            int row = wm * 64 + mt * 16 + r16;
            aoff[s][mt] = row * 64 + ((quad ^ ((row >> 1) & 3)) << 4);
        }
        #pragma unroll
        for (int nb = 0; nb < 2; nb++) {
            int row = wn * 32 + nb * 16 + r16;
            boff[s][nb] = row * 64 + ((quad ^ ((row >> 1) & 3)) << 4);
        }
    }

    float acc[4][4][4];
    #pragma unroll
    for (int a = 0; a < 4; a++)
        #pragma unroll
        for (int b = 0; b < 4; b++)
            #pragma unroll
            for (int r = 0; r < 4; r++) acc[a][b][r] = 0.f;

    #pragma unroll
    for (int st = 0; st < 2; st++) {
        uint32_t da = sAu + st * 8192, db = sBu + st * 8192;
        #pragma unroll
        for (int i = 0; i < 2; i++) {
            asm volatile("cp.async.ca.shared.global [%0], [%1], 16;"
                         :: "r"(da + soff[i]), "l"(gA[i] + st * 32));
            asm volatile("cp.async.ca.shared.global [%0], [%1], 16;"
                         :: "r"(db + soff[i]), "l"(gB[i] + st * 32));
        }
        asm volatile("cp.async.commit_group;");
    }

    for (int c = 0; c < KCH; c++) {
        const int buf = c % 3;
        if (c + 1 < KCH) asm volatile("cp.async.wait_group 1;");
        else             asm volatile("cp.async.wait_group 0;");
        __syncthreads();
        if (c + 2 < KCH) {
            const int wb = (c + 2) % 3;
            const uint32_t da = sAu + wb * 8192, db = sBu + wb * 8192;
            #pragma unroll
            for (int i = 0; i < 2; i++) {
                asm volatile("cp.async.ca.shared.global [%0], [%1], 16;"
                             :: "r"(da + soff[i]), "l"(gA[i] + (c + 2) * 32));
                asm volatile("cp.async.ca.shared.global [%0], [%1], 16;"
                             :: "r"(db + soff[i]), "l"(gB[i] + (c + 2) * 32));
            }
            asm volatile("cp.async.commit_group;");
        }

        const uint32_t baseA = sAu + buf * 8192;
        const uint32_t baseB = sBu + buf * 8192;
        #pragma unroll
        for (int s = 0; s < 2; s++) {
            uint32_t afr[4][4];
            #pragma unroll
            for (int mt = 0; mt < 4; mt++) {
                asm volatile("ldmatrix.sync.aligned.m8n8.x4.shared.b16 "
                             "{%0,%1,%2,%3}, [%4];"
                             : "=r"(afr[mt][0]), "=r"(afr[mt][1]),
                               "=r"(afr[mt][2]), "=r"(afr[mt][3])
                             : "r"(baseA + aoff[s][mt]));
            }
            uint32_t bfr[4][2];
            #pragma unroll
            for (int nb = 0; nb < 2; nb++) {
                uint32_t r0, r1, r2, r3;
                asm volatile("ldmatrix.sync.aligned.m8n8.x4.shared.b16 "
                             "{%0,%1,%2,%3}, [%4];"
                             : "=r"(r0), "=r"(r1), "=r"(r2), "=r"(r3)
                             : "r"(baseB + boff[s][nb]));
                bfr[nb * 2][0] = r0;     bfr[nb * 2][1] = r2;
                bfr[nb * 2 + 1][0] = r1; bfr[nb * 2 + 1][1] = r3;
            }
            #pragma unroll
            for (int mt = 0; mt < 4; mt++)
                #pragma unroll
                for (int nt = 0; nt < 4; nt++) {
                    asm volatile(
                        "mma.sync.aligned.m16n8k16.row.col.f32.bf16.bf16.f32 "
                        "{%0,%1,%2,%3}, {%4,%5,%6,%7}, {%8,%9}, {%0,%1,%2,%3};"
                        : "+f"(acc[mt][nt][0]), "+f"(acc[mt][nt][1]),
                          "+f"(acc[mt][nt][2]), "+f"(acc[mt][nt][3])
                        : "r"(afr[mt][0]), "r"(afr[mt][1]),
                          "r"(afr[mt][2]), "r"(afr[mt][3]),
                          "r"(bfr[nt][0]), "r"(bfr[nt][1]));
                }
        }
    }

    float gate = 0.f, omg = 1.f;
    if (mode == 1) {
        gate = 1.0f / (1.0f + expf(-gatep[0]));
        omg = 1.0f - gate;
    }
    #pragma unroll
    for (int mt = 0; mt < 4; mt++) {
        #pragma unroll
        for (int half = 0; half < 2; half++) {
            int row = m0 + wm * 64 + mt * 16 + (lane >> 2) + 8 * half;
            float rsv = 0.f; const float* nqr = nullptr;
            __nv_bfloat16* arow = nullptr;
            if (mode == 1) {
                rsv = g_rowsum[row];
                nqr = nq + (size_t)(row & 15) * DN;
                arow = (__nv_bfloat16*)g_Abf2 + (size_t)row * KSPLIT;
            }
            float* crow = C + (size_t)row * Ncols;
            #pragma unroll
            for (int nt = 0; nt < 4; nt++) {
                int col = n0 + wn * 32 + nt * 8 + (lane & 3) * 2;
                float v0 = acc[mt][nt][half * 2 + 0];
                float v1 = acc[mt][nt][half * 2 + 1];
                if (mode == 1) {
                    v0 += rsv * __ldg(&bias[col]);
                    v1 += rsv * __ldg(&bias[col + 1]);
                    v0 = omg * v0 + gate * __ldg(&nqr[col]);
                    v1 = omg * v1 + gate * __ldg(&nqr[col + 1]);
                    float h0 = __bfloat162float(__float2bfloat16(v0));
                    float h1 = __bfloat162float(__float2bfloat16(v1));
                    unsigned hp = packbf2(v0, v1);
                    unsigned lp = packbf2(v0 - h0, v1 - h1);
                    *(unsigned*)(arow + col) = hp;
                    *(unsigned*)(arow + 768 + col) = hp;
                    *(unsigned*)(arow + 1536 + col) = lp;
                } else if (mode == 2) {
                    v0 += __ldg(&bias[col]);
                    v1 += __ldg(&bias[col + 1]);
                }
                float2 o; o.x = v0; o.y = v1;
                *(float2*)(crow + col) = o;
            }
        }
    }
}

// ---------------- kEdge ----------------------------------------------
__global__ void kEdge(const float* __restrict__ be1, const float* __restrict__ We2,
                      const float* __restrict__ be2, float* __restrict__ outE,
                      int post) {
    int b = blockIdx.x;
    int tid = threadIdx.x;
    int i = tid >> 4, j = tid & 15;
    __shared__ float sHi[KK * 257];
    __shared__ float sHj[KK * 257];
    __shared__ float sW2[256];
    __shared__ float sE[KK * 17];

    float acc = 0.f;
    for (int h0 = 0; h0 < HID; h0 += 256) {
        for (int idx = tid; idx < KK * 256; idx += 256) {
            int r = idx >> 8, c = idx & 255;
            sHi[r * 257 + c] = g_H[(size_t)(b * KK + r) * (2 * HID) + h0 + c] + be1[h0 + c];
            sHj[r * 257 + c] = g_H[(size_t)(b * KK + r) * (2 * HID) + HID + h0 + c];
        }
        sW2[tid] = We2[h0 + tid];
        __syncthreads();
        const float* hi = sHi + i * 257;
        const float* hj = sHj + j * 257;
        float a0 = 0.f, a1 = 0.f, a2 = 0.f, a3 = 0.f;
        #pragma unroll 4
        for (int c = 0; c < 256; c += 4) {
            a0 += fmaxf(hi[c]     + hj[c],     0.f) * sW2[c];
            a1 += fmaxf(hi[c + 1] + hj[c + 1], 0.f) * sW2[c + 1];
            a2 += fmaxf(hi[c + 2] + hj[c + 2], 0.f) * sW2[c + 2];
            a3 += fmaxf(hi[c + 3] + hj[c + 3], 0.f) * sW2[c + 3];
        }
        acc += (a0 + a1) + (a2 + a3);
        __syncthreads();
    }
    float E = acc + be2[0];
    if (post) {
        outE[b * 256 + tid] = E;
    } else {
        sE[i * 17 + j] = E;
        __syncthreads();
        float m = -3.4e38f;
        #pragma unroll
        for (int jj = 0; jj < KK; jj++) m = fmaxf(m, sE[i * 17 + jj]);
        float s = 0.f;
        #pragma unroll
        for (int jj = 0; jj < KK; jj++) s += __expf(sE[i * 17 + jj] - m);
        g_A[b * 256 + tid] = __expf(E - m) / s;
    }
}

// ---------------- kMsg: V += relu(A @ M), write split-V (+optional outV) --
__global__ void kMsg(float* __restrict__ outV) {
    int b = blockIdx.x;
    int tid = threadIdx.x;
    __shared__ float sAm[KK * 17];
    sAm[(tid >> 4) * 17 + (tid & 15)] = g_A[b * 256 + tid];
    __syncthreads();
    float acc[KK][3];
    #pragma unroll
    for (int i = 0; i < KK; i++) { acc[i][0] = 0.f; acc[i][1] = 0.f; acc[i][2] = 0.f; }
    for (int j = 0; j < KK; j++) {
        const float* mr = g_M + (size_t)(b * KK + j) * DN + tid;
        float m0 = mr[0], m1 = mr[256], m2 = mr[512];
        #pragma unroll
        for (int i = 0; i < KK; i++) {
            float a = sAm[i * 17 + j];
            acc[i][0] += a * m0; acc[i][1] += a * m1; acc[i][2] += a * m2;
        }
    }
    #pragma unroll
    for (int i = 0; i < KK; i++) {
        int row = b * KK + i;
        float* vr = g_V + (size_t)row * DN;
        __nv_bfloat16* ar = (__nv_bfloat16*)g_Abf2 + (size_t)row * KSPLIT;
        float* ovr = outV ? (outV + (size_t)row * DN) : nullptr;
        #pragma unroll
        for (int c3 = 0; c3 < 3; c3++) {
            int d = tid + c3 * 256;
            float nv = vr[d] + fmaxf(acc[i][c3], 0.f);
            vr[d] = nv;
            __nv_bfloat16 h = __float2bfloat16(nv);
            __nv_bfloat16 l = __float2bfloat16(nv - __bfloat162float(h));
            ar[d] = h; ar[768 + d] = h; ar[1536 + d] = l;
            if (ovr) ovr[d] = nv;
        }
    }
}

// ---------------- host ----------------------------------------------------
extern "C" void kernel_launch(void* const* d_in, const int* in_sizes, int n_in,
                              void* d_out, int out_size) {
    const float* w    = (const float*)d_in[0];
    const int*   mask = (const int*)  d_in[1];
    const float* nq   = (const float*)d_in[2];
    const float* Wq   = (const float*)d_in[3];
    const float* bq   = (const float*)d_in[4];
    const float* Wk   = (const float*)d_in[5];
    const float* bk   = (const float*)d_in[6];
    const float* Wv   = (const float*)d_in[7];
    const float* bv   = (const float*)d_in[8];
    const float* We1  = (const float*)d_in[9];
    const float* be1  = (const float*)d_in[10];
    const float* We2  = (const float*)d_in[11];
    const float* be2  = (const float*)d_in[12];
    const float* fg   = (const float*)d_in[13];
    const float* Wg   = (const float*)d_in[14];
    const float* bg   = (const float*)d_in[15];

    float* outS = (float*)d_out;
    float* outV = outS + (size_t)BB * NN * KK;
    float* outE = outV + (size_t)BB * KK * DN;

    kSplitAllW<<<1248, 256>>>(Wv, Wg, We1);
    kQ<<<dim3(3, 8), 256>>>(nq, Wq);
    kQr<<<48, 256>>>(bq);
    kP<<<96, 256>>>(Wk, bk);
    kScore<<<BB, 256>>>(w, mask, outS);
    kU<<<dim3(BB, 2), 96>>>(w, outS);                          // split-U -> g_Abf

    kTGemm<<<dim3(32, 6), 256>>>(0, 0, 1, bv, nq, fg);         // V = U@Wv; split-V -> Abf2
    kTGemm<<<dim3(32, 8), 256>>>(1, 3, 0, nullptr, nullptr, nullptr); // H = V@We1
    kEdge<<<BB, 256>>>(be1, We2, be2, nullptr, 0);             // A = softmax(E)
    kTGemm<<<dim3(32, 6), 256>>>(1, 1, 2, bg, nullptr, nullptr);      // M = V@Wg0+bg0
    kMsg<<<BB, 256>>>(nullptr);                                // V += relu(A@M); Abf2
    kTGemm<<<dim3(32, 6), 256>>>(1, 2, 2, bg + DN, nullptr, nullptr); // M = V@Wg1+bg1
    kMsg<<<BB, 256>>>(outV);                                   // final V; Abf2; outV
    kTGemm<<<dim3(32, 8), 256>>>(1, 3, 0, nullptr, nullptr, nullptr); // H on final V
    kEdge<<<BB, 256>>>(be1, We2, be2, outE, 1);                // E -> out
}

// round 7
// speedup vs baseline: 1.7742x; 1.0046x over previous
#include <cuda_runtime.h>
#include <cuda_bf16.h>
#include <math.h>
#include <stdint.h>

// Problem dims
#define BB 256
#define NN 77
#define DD 768
#define KK 16
#define DN 768
#define HID 512
#define MTOT (BB*KK)          // 4096
#define SCALE 0.10206207261596575f   // (768/8)^-0.5
#define KSPLIT 2304           // 3*768 (split-K concat)
#define KCH 72                // 2304/32 chunks

// ---------------- scratch (device globals; no allocation) ----------------
__device__ float g_Q[KK*DN];
__device__ float g_Qp[8][KK*DN];
__device__ float g_Pt[DD*KK];
__device__ float g_c[KK];
__device__ float g_V[MTOT*DN];
__device__ float g_rowsum[MTOT];
__device__ float g_H[MTOT*2*HID];
__device__ float g_M[MTOT*DN];
__device__ float g_A[BB*KK*KK];
// split-bf16 operand buffers (uint4 for 16B alignment)
__device__ uint4 g_Abf [(size_t)MTOT*KSPLIT/8];   // split-U
__device__ uint4 g_Abf2[(size_t)MTOT*KSPLIT/8];   // split-V
__device__ uint4 g_WbfV [768*KSPLIT/8];
__device__ uint4 g_WbfG0[768*KSPLIT/8];
__device__ uint4 g_WbfG1[768*KSPLIT/8];
__device__ uint4 g_WbfE1[1024*KSPLIT/8];

__device__ __forceinline__ uint32_t smem_u32(const void* p) {
    uint32_t a;
    asm("{ .reg .u64 t; cvta.to.shared.u64 t, %1; cvt.u32.u64 %0, t; }"
        : "=r"(a) : "l"(p));
    return a;
}

__device__ __forceinline__ unsigned packbf2(float a, float b) {
    unsigned short lo = __bfloat16_as_ushort(__float2bfloat16(a));
    unsigned short hi = __bfloat16_as_ushort(__float2bfloat16(b));
    return ((unsigned)hi << 16) | lo;
}

// ---------------- kQ: partial Q = nq @ Wq (Wq read once) ------------------
__global__ void kQ(const float* __restrict__ nq, const float* __restrict__ Wq) {
    int d = blockIdx.x * 256 + threadIdx.x;
    int sl = blockIdx.y;
    int e0 = sl * 96;
    __shared__ float snq[KK][96];
    for (int idx = threadIdx.x; idx < KK * 96; idx += 256)
        snq[idx / 96][idx % 96] = nq[(idx / 96) * DN + e0 + idx % 96];
    __syncthreads();
    float acc[KK];
    #pragma unroll
    for (int k = 0; k < KK; k++) acc[k] = 0.f;
    const float* wp = Wq + (size_t)e0 * DN + d;
    #pragma unroll 4
    for (int e = 0; e < 96; e++) {
        float wv = wp[(size_t)e * DN];
        #pragma unroll
        for (int k = 0; k < KK; k++) acc[k] += snq[k][e] * wv;
    }
    #pragma unroll
    for (int k = 0; k < KK; k++) g_Qp[sl][k * DN + d] = acc[k];
}
__global__ void kQr(const float* __restrict__ bq) {
    int i = blockIdx.x * 256 + threadIdx.x;   // 12288
    float s = bq[i % DN];
    #pragma unroll
    for (int sl = 0; sl < 8; sl++) s += g_Qp[sl][i];
    g_Q[i] = s;
}

// ---------------- kP: P^T[j][k] = Wk[j,:].Q[k,:] (warp per j) -------------
__global__ void kP(const float* __restrict__ Wk, const float* __restrict__ bk) {
    __shared__ float sQ[KK][DN];   // 48 KB
    int tid = threadIdx.x;
    int lane = tid & 31, warp = tid >> 5;
    for (int idx = tid; idx < KK * DN; idx += 256)
        sQ[idx / DN][idx % DN] = g_Q[idx];
    __syncthreads();

    int j = blockIdx.x * 8 + warp;
    const float4* wr = (const float4*)(Wk + (size_t)j * DN);
    float acc[KK];
    #pragma unroll
    for (int k = 0; k < KK; k++) acc[k] = 0.f;
    #pragma unroll
    for (int it = 0; it < 6; it++) {
        int e = it * 128 + lane * 4;
        float4 wv = wr[it * 32 + lane];
        #pragma unroll
        for (int k = 0; k < KK; k++) {
            float4 qv = *(const float4*)&sQ[k][e];
            acc[k] += wv.x * qv.x + wv.y * qv.y + wv.z * qv.z + wv.w * qv.w;
        }
    }
    float out = 0.f;
    #pragma unroll
    for (int k = 0; k < KK; k++) {
        float v = acc[k];
        v += __shfl_xor_sync(0xFFFFFFFFu, v, 16);
        v += __shfl_xor_sync(0xFFFFFFFFu, v, 8);
        v += __shfl_xor_sync(0xFFFFFFFFu, v, 4);
        v += __shfl_xor_sync(0xFFFFFFFFu, v, 2);
        v += __shfl_xor_sync(0xFFFFFFFFu, v, 1);
        if (lane == k) out = v;
    }
    if (lane < KK) g_Pt[j * KK + lane] = out;

    if (blockIdx.x >= 94) {
        int k = (blockIdx.x - 94) * 8 + warp;
        float cc = 0.f;
        #pragma unroll
        for (int it = 0; it < 6; it++) {
            int e = it * 128 + lane * 4;
            float4 bv = *(const float4*)(bk + e);
            float4 qv = *(const float4*)&sQ[k][e];
            cc += bv.x * qv.x + bv.y * qv.y + bv.z * qv.z + bv.w * qv.w;
        }
        cc += __shfl_xor_sync(0xFFFFFFFFu, cc, 16);
        cc += __shfl_xor_sync(0xFFFFFFFFu, cc, 8);
        cc += __shfl_xor_sync(0xFFFFFFFFu, cc, 4);
        cc += __shfl_xor_sync(0xFFFFFFFFu, cc, 2);
        cc += __shfl_xor_sync(0xFFFFFFFFu, cc, 1);
        if (lane == 0) g_c[k] = cc;
    }
}

// ---------------- kSplitAllW: all 4 weight splits, one launch ------------
__global__ void kSplitAllW(const float* __restrict__ Wv,
                           const float* __restrict__ Wg,
                           const float* __restrict__ We1) {
    int sid = blockIdx.x * 256 + threadIdx.x;   // 0..319487
    float a[8];
    __nv_bfloat16* out;
    int e0;
    if (sid < 221184) {
        int job = sid / 73728, s = sid % 73728;
        int n = s % 768, seg = s / 768;
        e0 = seg * 8;
        const float* Wp = (job == 0) ? Wv : (job == 1) ? Wg : (Wg + 768 * 768);
        uint4* o4 = (job == 0) ? g_WbfV : (job == 1) ? g_WbfG0 : g_WbfG1;
        out = (__nv_bfloat16*)o4 + (size_t)n * KSPLIT;
        #pragma unroll
        for (int i = 0; i < 8; i++) a[i] = Wp[(size_t)(e0 + i) * 768 + n];
    } else {
        int s = sid - 221184;
        int n = s % 1024, seg = s / 1024;
        e0 = seg * 8;
        out = (__nv_bfloat16*)g_WbfE1 + (size_t)n * KSPLIT;
        size_t base = (n < HID) ? (size_t)n : ((size_t)768 * HID + (n - HID));
        #pragma unroll
        for (int i = 0; i < 8; i++) a[i] = We1[base + (size_t)(e0 + i) * HID];
    }
    unsigned h[4], l[4];
    #pragma unroll
    for (int i = 0; i < 4; i++) {
        float x = a[2 * i], y = a[2 * i + 1];
        float xh = __bfloat162float(__float2bfloat16(x));
        float yh = __bfloat162float(__float2bfloat16(y));
        h[i] = packbf2(x, y);
        l[i] = packbf2(x - xh, y - yh);
    }
    *(uint4*)(out + e0)        = *(uint4*)h;
    *(uint4*)(out + 768 + e0)  = *(uint4*)l;
    *(uint4*)(out + 1536 + e0) = *(uint4*)h;
}

// ---------------- kScore: scores -> softmax -> outS + rowsum --------------
__global__ void kScore(const float* __restrict__ w, const int* __restrict__ mask,
                       float* __restrict__ outS) {
    int b = blockIdx.x;
    int tid = threadIdx.x;
    int ty = tid >> 4, tx = tid & 15;   // ty = k
    __shared__ float sW[80 * 68];       // [n][dd] pitch 68
    __shared__ float sP[64 * KK];
    __shared__ float sSc[KK * 80];
    __shared__ float sSm[NN * KK];

    float acc[5] = {0.f, 0.f, 0.f, 0.f, 0.f};
    for (int d0 = 0; d0 < DD; d0 += 64) {
        for (int idx = tid; idx < 80 * 64; idx += 256) {
            int n = idx >> 6, dd = idx & 63;
            sW[n * 68 + dd] = (n < NN) ? w[(b * NN + n) * DD + d0 + dd] : 0.f;
        }
        for (int idx = tid; idx < 64 * KK; idx += 256)
            sP[idx] = g_Pt[d0 * KK + idx];
        __syncthreads();
        #pragma unroll 2
        for (int dd = 0; dd < 64; dd += 4) {
            float p0 = sP[(dd + 0) * KK + ty];
            float p1 = sP[(dd + 1) * KK + ty];
            float p2 = sP[(dd + 2) * KK + ty];
            float p3 = sP[(dd + 3) * KK + ty];
            #pragma unroll
            for (int i = 0; i < 5; i++) {
                float4 wv = *(const float4*)&sW[(tx + 16 * i) * 68 + dd];
                acc[i] += p0 * wv.x + p1 * wv.y + p2 * wv.z + p3 * wv.w;
            }
        }
        __syncthreads();
    }
    float ck = g_c[ty];
    #pragma unroll
    for (int i = 0; i < 5; i++) {
        int n = tx + 16 * i;
        if (n < NN) sSc[ty * 80 + n] = (acc[i] + ck) * SCALE;
    }
    __syncthreads();

    if (tid < NN) {
        int n = tid;
        if (mask[b * NN + n] == 0) {
            #pragma unroll
            for (int k = 0; k < KK; k++) sSm[n * KK + k] = 1.0f / 16.0f;
        } else {
            float m = -3.4e38f;
            #pragma unroll
            for (int k = 0; k < KK; k++) m = fmaxf(m, sSc[k * 80 + n]);
            float e[KK]; float s = 0.f;
            #pragma unroll
            for (int k = 0; k < KK; k++) { e[k] = __expf(sSc[k * 80 + n] - m); s += e[k]; }
            float inv = 1.0f / s;
            #pragma unroll
            for (int k = 0; k < KK; k++) sSm[n * KK + k] = e[k] * inv;
        }
        #pragma unroll
        for (int k = 0; k < KK; k++)
            outS[(b * NN + n) * KK + k] = sSm[n * KK + k];
    }
    __syncthreads();
    if (tid < KK) {
        float s = 0.f;
        for (int n = 0; n < NN; n++) s += sSm[n * KK + tid];
        g_rowsum[b * KK + tid] = s;
    }
}

// ---------------- kU: U = S^T w, write split-U -> g_Abf -------------------
__global__ void kU(const float* __restrict__ w, const float* __restrict__ S) {
    int b = blockIdx.x, dh = blockIdx.y;
    int tid = threadIdx.x;
    int d0 = dh * 384 + tid * 4;
    __shared__ float sS[NN * KK];
    for (int idx = tid; idx < NN * KK; idx += 96)
        sS[idx] = S[b * NN * KK + idx];
    __syncthreads();

    float4 acc[KK];
    #pragma unroll
    for (int k = 0; k < KK; k++) { acc[k].x = 0.f; acc[k].y = 0.f; acc[k].z = 0.f; acc[k].w = 0.f; }
    const float* wp = w + (size_t)b * NN * DD + d0;
    #pragma unroll 2
    for (int n = 0; n < NN; n++) {
        float4 wv = *(const float4*)(wp + (size_t)n * DD);
        const float* srow = sS + n * KK;
        #pragma unroll
        for (int k = 0; k < KK; k++) {
            float s = srow[k];
            acc[k].x += s * wv.x; acc[k].y += s * wv.y;
            acc[k].z += s * wv.z; acc[k].w += s * wv.w;
        }
    }
    #pragma unroll
    for (int k = 0; k < KK; k++) {
        float4 v = acc[k];
        float hx = __bfloat162float(__float2bfloat16(v.x));
        float hy = __bfloat162float(__float2bfloat16(v.y));
        float hz = __bfloat162float(__float2bfloat16(v.z));
        float hw = __bfloat162float(__float2bfloat16(v.w));
        uint2 hp, lp;
        hp.x = packbf2(v.x, v.y); hp.y = packbf2(v.z, v.w);
        lp.x = packbf2(v.x - hx, v.y - hy); lp.y = packbf2(v.z - hz, v.w - hw);
        __nv_bfloat16* ur = (__nv_bfloat16*)g_Abf + (size_t)(b * KK + k) * KSPLIT;
        *(uint2*)(ur + d0) = hp;
        *(uint2*)(ur + 768 + d0) = hp;
        *(uint2*)(ur + 1536 + d0) = lp;
    }
}

// ---------------- kTGemm: mma.sync bf16-split GEMM, 64x128 tile -----------
// asel: 0 = g_Abf (split U), 1 = g_Abf2 (split V)
// wsel: 0=WbfV, 1=WbfG0, 2=WbfG1, 3=WbfE1 (ignored for mode 3)
// mode: 0 -> C=g_H; 1 -> C=g_V + split-V; 2 -> C=g_M (+bias);
//       3 -> merged: by<8 H=V@We1, by>=8 M=V@Wg0 (+bias)
__global__ __launch_bounds__(256, 3) void kTGemm(
    int asel, int wsel, int mode, const float* __restrict__ bias,
    const float* __restrict__ nq, const float* __restrict__ gatep)
{
    __shared__ __align__(1024) __nv_bfloat16 sA[3][64 * 32];
    __shared__ __align__(1024) __nv_bfloat16 sB[3][128 * 32];

    const __nv_bfloat16* Ag = (const __nv_bfloat16*)(asel ? g_Abf2 : g_Abf);
    const int m0 = blockIdx.x * 64;
    int n0 = blockIdx.y * 128;
    const __nv_bfloat16* Bg;
    float* C; int Ncols; int emode = mode;
    if (mode == 3) {
        if (blockIdx.y < 8) {
            Bg = (const __nv_bfloat16*)g_WbfE1; C = g_H; Ncols = 2 * HID; emode = 0;
        } else {
            n0 = (blockIdx.y - 8) * 128;
            Bg = (const __nv_bfloat16*)g_WbfG0; C = g_M; Ncols = DN; emode = 2;
        }
    } else {
        const uint4* B4 = (wsel == 0) ? g_WbfV : (wsel == 1) ? g_WbfG0
                        : (wsel == 2) ? g_WbfG1 : g_WbfE1;
        Bg = (const __nv_bfloat16*)B4;
        if (mode == 0)      { C = g_H; Ncols = 2 * HID; }
        else if (mode == 1) { C = g_V; Ncols = DN; }
        else                { C = g_M; Ncols = DN; }
    }

    const int tid = threadIdx.x;
    const int lane = tid & 31, warp = tid >> 5;
    const int wm = warp >> 2, wn = warp & 3;   // 2 x 4 warps, warp tile 32x32

    const uint32_t sAu = smem_u32(sA), sBu = smem_u32(sB);

    // cp.async slots: A 1/thread (64 rows x 4 quads), B 2/thread (128 x 4)
    const int arow = tid >> 2, aq = tid & 3;
    const uint32_t soffA = arow * 64 + ((aq ^ ((arow >> 1) & 3)) << 4);
    const __nv_bfloat16* gAp = Ag + (size_t)(m0 + arow) * KSPLIT + aq * 8;
    uint32_t soffB[2];
    const __nv_bfloat16* gBp[2];
    #pragma unroll
    for (int i = 0; i < 2; i++) {
        int v = tid * 2 + i, row = v >> 2, q = v & 3;
        soffB[i] = row * 64 + ((q ^ ((row >> 1) & 3)) << 4);
        gBp[i] = Bg + (size_t)(n0 + row) * KSPLIT + q * 8;
    }

    // ldmatrix offsets
    const int r16 = lane & 15, hh = lane >> 4;
    uint32_t aoff[2][2], boff[2][2];
    #pragma unroll
    for (int s = 0; s < 2; s++) {
        int quad = 2 * s + hh;
        #pragma unroll
        for (int mt = 0; mt < 2; mt++) {
            int row = wm * 32 + mt * 16 + r16;
            aoff[s][mt] = row * 64 + ((quad ^ ((row >> 1) & 3)) << 4);
        }
        #pragma unroll
        for (int nb = 0; nb < 2; nb++) {
            int row = wn * 32 + nb * 16 + r16;
            boff[s][nb] = row * 64 + ((quad ^ ((row >> 1) & 3)) << 4);
        }
    }

    float acc[2][4][4];
    #pragma unroll
    for (int a = 0; a < 2; a++)
        #pragma unroll
        for (int b = 0; b < 4; b++)
            #pragma unroll
            for (int r = 0; r < 4; r++) acc[a][b][r] = 0.f;

    #pragma unroll
    for (int st = 0; st < 2; st++) {
        asm volatile("cp.async.ca.shared.global [%0], [%1], 16;"
                     :: "r"(sAu + st * 4096 + soffA), "l"(gAp + st * 32));
        #pragma unroll
        for (int i = 0; i < 2; i++)
            asm volatile("cp.async.ca.shared.global [%0], [%1], 16;"
                         :: "r"(sBu + st * 8192 + soffB[i]), "l"(gBp[i] + st * 32));
        asm volatile("cp.async.commit_group;");
    }

    for (int c = 0; c < KCH; c++) {
        const int buf = c % 3;
        if (c + 1 < KCH) asm volatile("cp.async.wait_group 1;");
        else             asm volatile("cp.async.wait_group 0;");
        __syncthreads();
        if (c + 2 < KCH) {
            const int wb = (c + 2) % 3;
            asm volatile("cp.async.ca.shared.global [%0], [%1], 16;"
                         :: "r"(sAu + wb * 4096 + soffA), "l"(gAp + (c + 2) * 32));
            #pragma unroll
            for (int i = 0; i < 2; i++)
                asm volatile("cp.async.ca.shared.global [%0], [%1], 16;"
                             :: "r"(sBu + wb * 8192 + soffB[i]), "l"(gBp[i] + (c + 2) * 32));
            asm volatile("cp.async.commit_group;");
        }

        const uint32_t baseA = sAu + buf * 4096;
        const uint32_t baseB = sBu + buf * 8192;
        #pragma unroll
        for (int s = 0; s < 2; s++) {
            uint32_t afr[2][4];
            #pragma unroll
            for (int mt = 0; mt < 2; mt++) {
                asm volatile("ldmatrix.sync.aligned.m8n8.x4.shared.b16 "
                             "{%0,%1,%2,%3}, [%4];"
                             : "=r"(afr[mt][0]), "=r"(afr[mt][1]),
                               "=r"(afr[mt][2]), "=r"(afr[mt][3])
                             : "r"(baseA + aoff[s][mt]));
            }
            uint32_t bfr[4][2];
            #pragma unroll
            for (int nb = 0; nb < 2; nb++) {
                uint32_t r0, r1, r2, r3;
                asm volatile("ldmatrix.sync.aligned.m8n8.x4.shared.b16 "
                             "{%0,%1,%2,%3}, [%4];"
                             : "=r"(r0), "=r"(r1), "=r"(r2), "=r"(r3)
                             : "r"(baseB + boff[s][nb]));
                bfr[nb * 2][0] = r0;     bfr[nb * 2][1] = r2;
                bfr[nb * 2 + 1][0] = r1; bfr[nb * 2 + 1][1] = r3;
            }
            #pragma unroll
            for (int mt = 0; mt < 2; mt++)
                #pragma unroll
                for (int nt = 0; nt < 4; nt++) {
                    asm volatile(
                        "mma.sync.aligned.m16n8k16.row.col.f32.bf16.bf16.f32 "
                        "{%0,%1,%2,%3}, {%4,%5,%6,%7}, {%8,%9}, {%0,%1,%2,%3};"
                        : "+f"(acc[mt][nt][0]), "+f"(acc[mt][nt][1]),
                          "+f"(acc[mt][nt][2]), "+f"(acc[mt][nt][3])
                        : "r"(afr[mt][0]), "r"(afr[mt][1]),
                          "r"(afr[mt][2]), "r"(afr[mt][3]),
                          "r"(bfr[nt][0]), "r"(bfr[nt][1]));
                }
        }
    }

    float gate = 0.f, omg = 1.f;
    if (emode == 1) {
        gate = 1.0f / (1.0f + expf(-gatep[0]));
        omg = 1.0f - gate;
    }
    #pragma unroll
    for (int mt = 0; mt < 2; mt++) {
        #pragma unroll
        for (int half = 0; half < 2; half++) {
            int row = m0 + wm * 32 + mt * 16 + (lane >> 2) + 8 * half;
            float rsv = 0.f; const float* nqr = nullptr;
            __nv_bfloat16* arow2 = nullptr;
            if (emode == 1) {
                rsv = g_rowsum[row];
                nqr = nq + (size_t)(row & 15) * DN;
                arow2 = (__nv_bfloat16*)g_Abf2 + (size_t)row * KSPLIT;
            }
            float* crow = C + (size_t)row * Ncols;
            #pragma unroll
            for (int nt = 0; nt < 4; nt++) {
                int col = n0 + wn * 32 + nt * 8 + (lane & 3) * 2;
                float v0 = acc[mt][nt][half * 2 + 0];
                float v1 = acc[mt][nt][half * 2 + 1];
                if (emode == 1) {
                    v0 += rsv * __ldg(&bias[col]);
                    v1 += rsv * __ldg(&bias[col + 1]);
                    v0 = omg * v0 + gate * __ldg(&nqr[col]);
                    v1 = omg * v1 + gate * __ldg(&nqr[col + 1]);
                    float h0 = __bfloat162float(__float2bfloat16(v0));
                    float h1 = __bfloat162float(__float2bfloat16(v1));
                    unsigned hp = packbf2(v0, v1);
                    unsigned lp = packbf2(v0 - h0, v1 - h1);
                    *(unsigned*)(arow2 + col) = hp;
                    *(unsigned*)(arow2 + 768 + col) = hp;
                    *(unsigned*)(arow2 + 1536 + col) = lp;
                } else if (emode == 2) {
                    v0 += __ldg(&bias[col]);
                    v1 += __ldg(&bias[col + 1]);
                }
                float2 o; o.x = v0; o.y = v1;
                *(float2*)(crow + col) = o;
            }
        }
    }
}

// ---------------- kEdge ----------------------------------------------
__global__ void kEdge(const float* __restrict__ be1, const float* __restrict__ We2,
                      const float* __restrict__ be2, float* __restrict__ outE,
                      int post) {
    int b = blockIdx.x;
    int tid = threadIdx.x;
    int i = tid >> 4, j = tid & 15;
    __shared__ float sHi[KK * 257];
    __shared__ float sHj[KK * 257];
    __shared__ float sW2[256];
    __shared__ float sE[KK * 17];

    float acc = 0.f;
    for (int h0 = 0; h0 < HID; h0 += 256) {
        for (int idx = tid; idx < KK * 256; idx += 256) {
            int r = idx >> 8, c = idx & 255;
            sHi[r * 257 + c] = g_H[(size_t)(b * KK + r) * (2 * HID) + h0 + c] + be1[h0 + c];
            sHj[r * 257 + c] = g_H[(size_t)(b * KK + r) * (2 * HID) + HID + h0 + c];
        }
        sW2[tid] = We2[h0 + tid];
        __syncthreads();
        const float* hi = sHi + i * 257;
        const float* hj = sHj + j * 257;
        float a0 = 0.f, a1 = 0.f, a2 = 0.f, a3 = 0.f;
        #pragma unroll 4
        for (int c = 0; c < 256; c += 4) {
            a0 += fmaxf(hi[c]     + hj[c],     0.f) * sW2[c];
            a1 += fmaxf(hi[c + 1] + hj[c + 1], 0.f) * sW2[c + 1];
            a2 += fmaxf(hi[c + 2] + hj[c + 2], 0.f) * sW2[c + 2];
            a3 += fmaxf(hi[c + 3] + hj[c + 3], 0.f) * sW2[c + 3];
        }
        acc += (a0 + a1) + (a2 + a3);
        __syncthreads();
    }
    float E = acc + be2[0];
    if (post) {
        outE[b * 256 + tid] = E;
    } else {
        sE[i * 17 + j] = E;
        __syncthreads();
        float m = -3.4e38f;
        #pragma unroll
        for (int jj = 0; jj < KK; jj++) m = fmaxf(m, sE[i * 17 + jj]);
        float s = 0.f;
        #pragma unroll
        for (int jj = 0; jj < KK; jj++) s += __expf(sE[i * 17 + jj] - m);
        g_A[b * 256 + tid] = __expf(E - m) / s;
    }
}

// ---------------- kMsg: V += relu(A @ M), write split-V (+optional outV) --
__global__ void kMsg(float* __restrict__ outV) {
    int b = blockIdx.x;
    int tid = threadIdx.x;
    __shared__ float sAm[KK * 17];
    sAm[(tid >> 4) * 17 + (tid & 15)] = g_A[b * 256 + tid];
    __syncthreads();
    float acc[KK][3];
    #pragma unroll
    for (int i = 0; i < KK; i++) { acc[i][0] = 0.f; acc[i][1] = 0.f; acc[i][2] = 0.f; }
    for (int j = 0; j < KK; j++) {
        const float* mr = g_M + (size_t)(b * KK + j) * DN + tid;
        float m0 = mr[0], m1 = mr[256], m2 = mr[512];
        #pragma unroll
        for (int i = 0; i < KK; i++) {
            float a = sAm[i * 17 + j];
            acc[i][0] += a * m0; acc[i][1] += a * m1; acc[i][2] += a * m2;
        }
    }
    #pragma unroll
    for (int i = 0; i < KK; i++) {
        int row = b * KK + i;
        float* vr = g_V + (size_t)row * DN;
        __nv_bfloat16* ar = (__nv_bfloat16*)g_Abf2 + (size_t)row * KSPLIT;
        float* ovr = outV ? (outV + (size_t)row * DN) : nullptr;
        #pragma unroll
        for (int c3 = 0; c3 < 3; c3++) {
            int d = tid + c3 * 256;
            float nv = vr[d] + fmaxf(acc[i][c3], 0.f);
            vr[d] = nv;
            __nv_bfloat16 h = __float2bfloat16(nv);
            __nv_bfloat16 l = __float2bfloat16(nv - __bfloat162float(h));
            ar[d] = h; ar[768 + d] = h; ar[1536 + d] = l;
            if (ovr) ovr[d] = nv;
        }
    }
}

// ---------------- host ----------------------------------------------------
extern "C" void kernel_launch(void* const* d_in, const int* in_sizes, int n_in,
                              void* d_out, int out_size) {
    const float* w    = (const float*)d_in[0];
    const int*   mask = (const int*)  d_in[1];
    const float* nq   = (const float*)d_in[2];
    const float* Wq   = (const float*)d_in[3];
    const float* bq   = (const float*)d_in[4];
    const float* Wk   = (const float*)d_in[5];
    const float* bk   = (const float*)d_in[6];
    const float* Wv   = (const float*)d_in[7];
    const float* bv   = (const float*)d_in[8];
    const float* We1  = (const float*)d_in[9];
    const float* be1  = (const float*)d_in[10];
    const float* We2  = (const float*)d_in[11];
    const float* be2  = (const float*)d_in[12];
    const float* fg   = (const float*)d_in[13];
    const float* Wg   = (const float*)d_in[14];
    const float* bg   = (const float*)d_in[15];

    float* outS = (float*)d_out;
    float* outV = outS + (size_t)BB * NN * KK;
    float* outE = outV + (size_t)BB * KK * DN;

    kSplitAllW<<<1248, 256>>>(Wv, Wg, We1);
    kQ<<<dim3(3, 8), 256>>>(nq, Wq);
    kQr<<<48, 256>>>(bq);
    kP<<<96, 256>>>(Wk, bk);
    kScore<<<BB, 256>>>(w, mask, outS);
    kU<<<dim3(BB, 2), 96>>>(w, outS);                          // split-U -> g_Abf

    kTGemm<<<dim3(64, 6), 256>>>(0, 0, 1, bv, nq, fg);         // V = U@Wv; split-V -> Abf2
    kTGemm<<<dim3(64, 14), 256>>>(1, 0, 3, bg, nullptr, nullptr);   // H = V@We1 AND M = V@Wg0+bg0
    kEdge<<<BB, 256>>>(be1, We2, be2, nullptr, 0);             // A = softmax(E)
    kMsg<<<BB, 256>>>(nullptr);                                // V += relu(A@M); Abf2
    kTGemm<<<dim3(64, 6), 256>>>(1, 2, 2, bg + DN, nullptr, nullptr); // M = V@Wg1+bg1
    kMsg<<<BB, 256>>>(outV);                                   // final V; Abf2; outV
    kTGemm<<<dim3(64, 8), 256>>>(1, 3, 0, nullptr, nullptr, nullptr); // H on final V
    kEdge<<<BB, 256>>>(be1, We2, be2, outE, 1);                // E -> out
}

// round 8
// speedup vs baseline: 1.8394x; 1.0367x over previous
#include <cuda_runtime.h>
#include <cuda_bf16.h>
#include <math.h>
#include <stdint.h>

// Problem dims
#define BB 256
#define NN 77
#define DD 768
#define KK 16
#define DN 768
#define HID 512
#define MTOT (BB*KK)          // 4096
#define SCALE 0.10206207261596575f   // (768/8)^-0.5
#define KSPLIT 2304           // 3*768 (split-K concat)
#define KCH 72                // 2304/32 chunks

// ---------------- scratch (device globals; no allocation) ----------------
__device__ float g_Qp[8][KK*DN];
__device__ float g_Pt[DD*KK];
__device__ float g_c[KK];
__device__ float g_V[MTOT*DN];
__device__ float g_rowsum[MTOT];
__device__ float g_H[MTOT*2*HID];
__device__ float g_M[MTOT*DN];
__device__ float g_A[BB*KK*KK];
// split-bf16 operand buffers (uint4 for 16B alignment)
__device__ uint4 g_Abf [(size_t)MTOT*KSPLIT/8];   // split-U
__device__ uint4 g_Abf2[(size_t)MTOT*KSPLIT/8];   // split-V
__device__ uint4 g_WbfV [768*KSPLIT/8];
__device__ uint4 g_WbfG0[768*KSPLIT/8];
__device__ uint4 g_WbfG1[768*KSPLIT/8];
__device__ uint4 g_WbfE1[1024*KSPLIT/8];

__device__ __forceinline__ uint32_t smem_u32(const void* p) {
    uint32_t a;
    asm("{ .reg .u64 t; cvta.to.shared.u64 t, %1; cvt.u32.u64 %0, t; }"
        : "=r"(a) : "l"(p));
    return a;
}

__device__ __forceinline__ unsigned packbf2(float a, float b) {
    unsigned short lo = __bfloat16_as_ushort(__float2bfloat16(a));
    unsigned short hi = __bfloat16_as_ushort(__float2bfloat16(b));
    return ((unsigned)hi << 16) | lo;
}

// ---------------- kQ: partial Q = nq @ Wq (Wq read once) ------------------
__global__ void kQ(const float* __restrict__ nq, const float* __restrict__ Wq) {
    int d = blockIdx.x * 256 + threadIdx.x;
    int sl = blockIdx.y;
    int e0 = sl * 96;
    __shared__ float snq[KK][96];
    for (int idx = threadIdx.x; idx < KK * 96; idx += 256)
        snq[idx / 96][idx % 96] = nq[(idx / 96) * DN + e0 + idx % 96];
    __syncthreads();
    float acc[KK];
    #pragma unroll
    for (int k = 0; k < KK; k++) acc[k] = 0.f;
    const float* wp = Wq + (size_t)e0 * DN + d;
    #pragma unroll 4
    for (int e = 0; e < 96; e++) {
        float wv = wp[(size_t)e * DN];
        #pragma unroll
        for (int k = 0; k < KK; k++) acc[k] += snq[k][e] * wv;
    }
    #pragma unroll
    for (int k = 0; k < KK; k++) g_Qp[sl][k * DN + d] = acc[k];
}

// ---------------- kP: P^T[j][k] = Wk[j,:].Q[k,:] (warp per j) -------------
// sums the 8 kQ partials + bq inline (kQr folded in)
__global__ void kP(const float* __restrict__ Wk, const float* __restrict__ bk,
                   const float* __restrict__ bq) {
    __shared__ float sQ[KK][DN];   // 48 KB
    int tid = threadIdx.x;
    int lane = tid & 31, warp = tid >> 5;
    for (int idx = tid; idx < KK * DN; idx += 256) {
        float s = bq[idx % DN];
        #pragma unroll
        for (int sl = 0; sl < 8; sl++) s += g_Qp[sl][idx];
        sQ[idx / DN][idx % DN] = s;
    }
    __syncthreads();

    int j = blockIdx.x * 8 + warp;
    const float4* wr = (const float4*)(Wk + (size_t)j * DN);
    float acc[KK];
    #pragma unroll
    for (int k = 0; k < KK; k++) acc[k] = 0.f;
    #pragma unroll
    for (int it = 0; it < 6; it++) {
        int e = it * 128 + lane * 4;
        float4 wv = wr[it * 32 + lane];
        #pragma unroll
        for (int k = 0; k < KK; k++) {
            float4 qv = *(const float4*)&sQ[k][e];
            acc[k] += wv.x * qv.x + wv.y * qv.y + wv.z * qv.z + wv.w * qv.w;
        }
    }
    float out = 0.f;
    #pragma unroll
    for (int k = 0; k < KK; k++) {
        float v = acc[k];
        v += __shfl_xor_sync(0xFFFFFFFFu, v, 16);
        v += __shfl_xor_sync(0xFFFFFFFFu, v, 8);
        v += __shfl_xor_sync(0xFFFFFFFFu, v, 4);
        v += __shfl_xor_sync(0xFFFFFFFFu, v, 2);
        v += __shfl_xor_sync(0xFFFFFFFFu, v, 1);
        if (lane == k) out = v;
    }
    if (lane < KK) g_Pt[j * KK + lane] = out;

    if (blockIdx.x >= 94) {
        int k = (blockIdx.x - 94) * 8 + warp;
        float cc = 0.f;
        #pragma unroll
        for (int it = 0; it < 6; it++) {
            int e = it * 128 + lane * 4;
            float4 bv = *(const float4*)(bk + e);
            float4 qv = *(const float4*)&sQ[k][e];
            cc += bv.x * qv.x + bv.y * qv.y + bv.z * qv.z + bv.w * qv.w;
        }
        cc += __shfl_xor_sync(0xFFFFFFFFu, cc, 16);
        cc += __shfl_xor_sync(0xFFFFFFFFu, cc, 8);
        cc += __shfl_xor_sync(0xFFFFFFFFu, cc, 4);
        cc += __shfl_xor_sync(0xFFFFFFFFu, cc, 2);
        cc += __shfl_xor_sync(0xFFFFFFFFu, cc, 1);
        if (lane == 0) g_c[k] = cc;
    }
}

// ---------------- kSplitAllW: all 4 weight splits, one launch ------------
__global__ void kSplitAllW(const float* __restrict__ Wv,
                           const float* __restrict__ Wg,
                           const float* __restrict__ We1) {
    int sid = blockIdx.x * 256 + threadIdx.x;   // 0..319487
    float a[8];
    __nv_bfloat16* out;
    int e0;
    if (sid < 221184) {
        int job = sid / 73728, s = sid % 73728;
        int n = s % 768, seg = s / 768;
        e0 = seg * 8;
        const float* Wp = (job == 0) ? Wv : (job == 1) ? Wg : (Wg + 768 * 768);
        uint4* o4 = (job == 0) ? g_WbfV : (job == 1) ? g_WbfG0 : g_WbfG1;
        out = (__nv_bfloat16*)o4 + (size_t)n * KSPLIT;
        #pragma unroll
        for (int i = 0; i < 8; i++) a[i] = Wp[(size_t)(e0 + i) * 768 + n];
    } else {
        int s = sid - 221184;
        int n = s % 1024, seg = s / 1024;
        e0 = seg * 8;
        out = (__nv_bfloat16*)g_WbfE1 + (size_t)n * KSPLIT;
        size_t base = (n < HID) ? (size_t)n : ((size_t)768 * HID + (n - HID));
        #pragma unroll
        for (int i = 0; i < 8; i++) a[i] = We1[base + (size_t)(e0 + i) * HID];
    }
    unsigned h[4], l[4];
    #pragma unroll
    for (int i = 0; i < 4; i++) {
        float x = a[2 * i], y = a[2 * i + 1];
        float xh = __bfloat162float(__float2bfloat16(x));
        float yh = __bfloat162float(__float2bfloat16(y));
        h[i] = packbf2(x, y);
        l[i] = packbf2(x - xh, y - yh);
    }
    *(uint4*)(out + e0)        = *(uint4*)h;
    *(uint4*)(out + 768 + e0)  = *(uint4*)l;
    *(uint4*)(out + 1536 + e0) = *(uint4*)h;
}

// ---------------- kScore: scores -> softmax -> outS + rowsum --------------
__global__ void kScore(const float* __restrict__ w, const int* __restrict__ mask,
                       float* __restrict__ outS) {
    int b = blockIdx.x;
    int tid = threadIdx.x;
    int ty = tid >> 4, tx = tid & 15;   // ty = k
    __shared__ float sW[80 * 68];       // [n][dd] pitch 68
    __shared__ float sP[64 * KK];
    __shared__ float sSc[KK * 80];
    __shared__ float sSm[NN * KK];

    float acc[5] = {0.f, 0.f, 0.f, 0.f, 0.f};
    for (int d0 = 0; d0 < DD; d0 += 64) {
        for (int idx = tid; idx < 80 * 64; idx += 256) {
            int n = idx >> 6, dd = idx & 63;
            sW[n * 68 + dd] = (n < NN) ? w[(b * NN + n) * DD + d0 + dd] : 0.f;
        }
        for (int idx = tid; idx < 64 * KK; idx += 256)
            sP[idx] = g_Pt[d0 * KK + idx];
        __syncthreads();
        #pragma unroll 2
        for (int dd = 0; dd < 64; dd += 4) {
            float p0 = sP[(dd + 0) * KK + ty];
            float p1 = sP[(dd + 1) * KK + ty];
            float p2 = sP[(dd + 2) * KK + ty];
            float p3 = sP[(dd + 3) * KK + ty];
            #pragma unroll
            for (int i = 0; i < 5; i++) {
                float4 wv = *(const float4*)&sW[(tx + 16 * i) * 68 + dd];
                acc[i] += p0 * wv.x + p1 * wv.y + p2 * wv.z + p3 * wv.w;
            }
        }
        __syncthreads();
    }
    float ck = g_c[ty];
    #pragma unroll
    for (int i = 0; i < 5; i++) {
        int n = tx + 16 * i;
        if (n < NN) sSc[ty * 80 + n] = (acc[i] + ck) * SCALE;
    }
    __syncthreads();

    if (tid < NN) {
        int n = tid;
        if (mask[b * NN + n] == 0) {
            #pragma unroll
            for (int k = 0; k < KK; k++) sSm[n * KK + k] = 1.0f / 16.0f;
        } else {
            float m = -3.4e38f;
            #pragma unroll
            for (int k = 0; k < KK; k++) m = fmaxf(m, sSc[k * 80 + n]);
            float e[KK]; float s = 0.f;
            #pragma unroll
            for (int k = 0; k < KK; k++) { e[k] = __expf(sSc[k * 80 + n] - m); s += e[k]; }
            float inv = 1.0f / s;
            #pragma unroll
            for (int k = 0; k < KK; k++) sSm[n * KK + k] = e[k] * inv;
        }
        #pragma unroll
        for (int k = 0; k < KK; k++)
            outS[(b * NN + n) * KK + k] = sSm[n * KK + k];
    }
    __syncthreads();
    if (tid < KK) {
        float s = 0.f;
        for (int n = 0; n < NN; n++) s += sSm[n * KK + tid];
        g_rowsum[b * KK + tid] = s;
    }
}

// ---------------- kU: U = S^T w, write split-U -> g_Abf -------------------
__global__ void kU(const float* __restrict__ w, const float* __restrict__ S) {
    int b = blockIdx.x, dh = blockIdx.y;
    int tid = threadIdx.x;
    int d0 = dh * 384 + tid * 4;
    __shared__ float sS[NN * KK];
    for (int idx = tid; idx < NN * KK; idx += 96)
        sS[idx] = S[b * NN * KK + idx];
    __syncthreads();

    float4 acc[KK];
    #pragma unroll
    for (int k = 0; k < KK; k++) { acc[k].x = 0.f; acc[k].y = 0.f; acc[k].z = 0.f; acc[k].w = 0.f; }
    const float* wp = w + (size_t)b * NN * DD + d0;
    #pragma unroll 2
    for (int n = 0; n < NN; n++) {
        float4 wv = *(const float4*)(wp + (size_t)n * DD);
        const float* srow = sS + n * KK;
        #pragma unroll
        for (int k = 0; k < KK; k++) {
            float s = srow[k];
            acc[k].x += s * wv.x; acc[k].y += s * wv.y;
            acc[k].z += s * wv.z; acc[k].w += s * wv.w;
        }
    }
    #pragma unroll
    for (int k = 0; k < KK; k++) {
        float4 v = acc[k];
        float hx = __bfloat162float(__float2bfloat16(v.x));
        float hy = __bfloat162float(__float2bfloat16(v.y));
        float hz = __bfloat162float(__float2bfloat16(v.z));
        float hw = __bfloat162float(__float2bfloat16(v.w));
        uint2 hp, lp;
        hp.x = packbf2(v.x, v.y); hp.y = packbf2(v.z, v.w);
        lp.x = packbf2(v.x - hx, v.y - hy); lp.y = packbf2(v.z - hz, v.w - hw);
        __nv_bfloat16* ur = (__nv_bfloat16*)g_Abf + (size_t)(b * KK + k) * KSPLIT;
        *(uint2*)(ur + d0) = hp;
        *(uint2*)(ur + 768 + d0) = hp;
        *(uint2*)(ur + 1536 + d0) = lp;
    }
}

// ---------------- kTGemm: mma.sync bf16-split GEMM ------------------------
// block 128x128, 8 warps as 4m x 2n (warp tile 32x64), 3-stage cp.async
// asel: 0 = g_Abf (split U), 1 = g_Abf2 (split V)
// wsel: 0=WbfV, 1=WbfG0, 2=WbfG1, 3=WbfE1 (ignored for mode 3)
// mode: 0 -> C=g_H; 1 -> C=g_V + split-V; 2 -> C=g_M (+bias);
//       3 -> merged: by<8 H=V@We1, by>=8 M=V@Wg0 (+bias)
__global__ __launch_bounds__(256, 2) void kTGemm(
    int asel, int wsel, int mode, const float* __restrict__ bias,
    const float* __restrict__ nq, const float* __restrict__ gatep)
{
    __shared__ __align__(1024) __nv_bfloat16 sA[3][128 * 32];
    __shared__ __align__(1024) __nv_bfloat16 sB[3][128 * 32];

    const __nv_bfloat16* Ag = (const __nv_bfloat16*)(asel ? g_Abf2 : g_Abf);
    const int m0 = blockIdx.x * 128;
    int n0 = blockIdx.y * 128;
    const __nv_bfloat16* Bg;
    float* C; int Ncols; int emode = mode;
    if (mode == 3) {
        if (blockIdx.y < 8) {
            Bg = (const __nv_bfloat16*)g_WbfE1; C = g_H; Ncols = 2 * HID; emode = 0;
        } else {
            n0 = (blockIdx.y - 8) * 128;
            Bg = (const __nv_bfloat16*)g_WbfG0; C = g_M; Ncols = DN; emode = 2;
        }
    } else {
        const uint4* B4 = (wsel == 0) ? g_WbfV : (wsel == 1) ? g_WbfG0
                        : (wsel == 2) ? g_WbfG1 : g_WbfE1;
        Bg = (const __nv_bfloat16*)B4;
        if (mode == 0)      { C = g_H; Ncols = 2 * HID; }
        else if (mode == 1) { C = g_V; Ncols = DN; }
        else                { C = g_M; Ncols = DN; }
    }

    const int tid = threadIdx.x;
    const int lane = tid & 31, warp = tid >> 5;
    const int wm = warp >> 1, wn = warp & 1;   // 4m x 2n warps, warp tile 32x64

    const uint32_t sAu = smem_u32(sA), sBu = smem_u32(sB);

    // cp.async slots: 2 each for A and B (128 rows x 4 quads each)
    uint32_t soff[2];
    const __nv_bfloat16* gA[2];
    const __nv_bfloat16* gB[2];
    #pragma unroll
    for (int i = 0; i < 2; i++) {
        int v = tid * 2 + i, row = v >> 2, q = v & 3;
        soff[i] = row * 64 + ((q ^ ((row >> 1) & 3)) << 4);
        gA[i] = Ag + (size_t)(m0 + row) * KSPLIT + q * 8;
        gB[i] = Bg + (size_t)(n0 + row) * KSPLIT + q * 8;
    }

    // ldmatrix offsets
    const int r16 = lane & 15, hh = lane >> 4;
    uint32_t aoff[2][2], boff[2][4];
    #pragma unroll
    for (int s = 0; s < 2; s++) {
        int quad = 2 * s + hh;
        #pragma unroll
        for (int mt = 0; mt < 2; mt++) {
            int row = wm * 32 + mt * 16 + r16;
            aoff[s][mt] = row * 64 + ((quad ^ ((row >> 1) & 3)) << 4);
        }
        #pragma unroll
        for (int nb = 0; nb < 4; nb++) {
            int row = wn * 64 + nb * 16 + r16;
            boff[s][nb] = row * 64 + ((quad ^ ((row >> 1) & 3)) << 4);
        }
    }

    float acc[2][8][4];
    #pragma unroll
    for (int a = 0; a < 2; a++)
        #pragma unroll
        for (int b = 0; b < 8; b++)
            #pragma unroll
            for (int r = 0; r < 4; r++) acc[a][b][r] = 0.f;

    #pragma unroll
    for (int st = 0; st < 2; st++) {
        uint32_t da = sAu + st * 8192, db = sBu + st * 8192;
        #pragma unroll
        for (int i = 0; i < 2; i++) {
            asm volatile("cp.async.ca.shared.global [%0], [%1], 16;"
                         :: "r"(da + soff[i]), "l"(gA[i] + st * 32));
            asm volatile("cp.async.ca.shared.global [%0], [%1], 16;"
                         :: "r"(db + soff[i]), "l"(gB[i] + st * 32));
        }
        asm volatile("cp.async.commit_group;");
    }

    for (int c = 0; c < KCH; c++) {
        const int buf = c % 3;
        if (c + 1 < KCH) asm volatile("cp.async.wait_group 1;");
        else             asm volatile("cp.async.wait_group 0;");
        __syncthreads();
        if (c + 2 < KCH) {
            const int wb = (c + 2) % 3;
            const uint32_t da = sAu + wb * 8192, db = sBu + wb * 8192;
            #pragma unroll
            for (int i = 0; i < 2; i++) {
                asm volatile("cp.async.ca.shared.global [%0], [%1], 16;"
                             :: "r"(da + soff[i]), "l"(gA[i] + (c + 2) * 32));
                asm volatile("cp.async.ca.shared.global [%0], [%1], 16;"
                             :: "r"(db + soff[i]), "l"(gB[i] + (c + 2) * 32));
            }
            asm volatile("cp.async.commit_group;");
        }

        const uint32_t baseA = sAu + buf * 8192;
        const uint32_t baseB = sBu + buf * 8192;
        #pragma unroll
        for (int s = 0; s < 2; s++) {
            uint32_t afr[2][4];
            #pragma unroll
            for (int mt = 0; mt < 2; mt++) {
                asm volatile("ldmatrix.sync.aligned.m8n8.x4.shared.b16 "
                             "{%0,%1,%2,%3}, [%4];"
                             : "=r"(afr[mt][0]), "=r"(afr[mt][1]),
                               "=r"(afr[mt][2]), "=r"(afr[mt][3])
                             : "r"(baseA + aoff[s][mt]));
            }
            uint32_t bfr[8][2];
            #pragma unroll
            for (int nb = 0; nb < 4; nb++) {
                uint32_t r0, r1, r2, r3;
                asm volatile("ldmatrix.sync.aligned.m8n8.x4.shared.b16 "
                             "{%0,%1,%2,%3}, [%4];"
                             : "=r"(r0), "=r"(r1), "=r"(r2), "=r"(r3)
                             : "r"(baseB + boff[s][nb]));
                bfr[nb * 2][0] = r0;     bfr[nb * 2][1] = r2;
                bfr[nb * 2 + 1][0] = r1; bfr[nb * 2 + 1][1] = r3;
            }
            #pragma unroll
            for (int mt = 0; mt < 2; mt++)
                #pragma unroll
                for (int nt = 0; nt < 8; nt++) {
                    asm volatile(
                        "mma.sync.aligned.m16n8k16.row.col.f32.bf16.bf16.f32 "
                        "{%0,%1,%2,%3}, {%4,%5,%6,%7}, {%8,%9}, {%0,%1,%2,%3};"
                        : "+f"(acc[mt][nt][0]), "+f"(acc[mt][nt][1]),
                          "+f"(acc[mt][nt][2]), "+f"(acc[mt][nt][3])
                        : "r"(afr[mt][0]), "r"(afr[mt][1]),
                          "r"(afr[mt][2]), "r"(afr[mt][3]),
                          "r"(bfr[nt][0]), "r"(bfr[nt][1]));
                }
        }
    }

    float gate = 0.f, omg = 1.f;
    if (emode == 1) {
        gate = 1.0f / (1.0f + expf(-gatep[0]));
        omg = 1.0f - gate;
    }
    #pragma unroll
    for (int mt = 0; mt < 2; mt++) {
        #pragma unroll
        for (int half = 0; half < 2; half++) {
            int row = m0 + wm * 32 + mt * 16 + (lane >> 2) + 8 * half;
            float rsv = 0.f; const float* nqr = nullptr;
            __nv_bfloat16* arow2 = nullptr;
            if (emode == 1) {
                rsv = g_rowsum[row];
                nqr = nq + (size_t)(row & 15) * DN;
                arow2 = (__nv_bfloat16*)g_Abf2 + (size_t)row * KSPLIT;
            }
            float* crow = C + (size_t)row * Ncols;
            #pragma unroll
            for (int nt = 0; nt < 8; nt++) {
                int col = n0 + wn * 64 + nt * 8 + (lane & 3) * 2;
                float v0 = acc[mt][nt][half * 2 + 0];
                float v1 = acc[mt][nt][half * 2 + 1];
                if (emode == 1) {
                    v0 += rsv * __ldg(&bias[col]);
                    v1 += rsv * __ldg(&bias[col + 1]);
                    v0 = omg * v0 + gate * __ldg(&nqr[col]);
                    v1 = omg * v1 + gate * __ldg(&nqr[col + 1]);
                    float h0 = __bfloat162float(__float2bfloat16(v0));
                    float h1 = __bfloat162float(__float2bfloat16(v1));
                    unsigned hp = packbf2(v0, v1);
                    unsigned lp = packbf2(v0 - h0, v1 - h1);
                    *(unsigned*)(arow2 + col) = hp;
                    *(unsigned*)(arow2 + 768 + col) = hp;
                    *(unsigned*)(arow2 + 1536 + col) = lp;
                } else if (emode == 2) {
                    v0 += __ldg(&bias[col]);
                    v1 += __ldg(&bias[col + 1]);
                }
                float2 o; o.x = v0; o.y = v1;
                *(float2*)(crow + col) = o;
            }
        }
    }
}

// ---------------- kEdge ----------------------------------------------
__global__ void kEdge(const float* __restrict__ be1, const float* __restrict__ We2,
                      const float* __restrict__ be2, float* __restrict__ outE,
                      int post) {
    int b = blockIdx.x;
    int tid = threadIdx.x;
    int i = tid >> 4, j = tid & 15;
    __shared__ float sHi[KK * 257];
    __shared__ float sHj[KK * 257];
    __shared__ float sW2[256];
    __shared__ float sE[KK * 17];

    float acc = 0.f;
    for (int h0 = 0; h0 < HID; h0 += 256) {
        for (int idx = tid; idx < KK * 256; idx += 256) {
            int r = idx >> 8, c = idx & 255;
            sHi[r * 257 + c] = g_H[(size_t)(b * KK + r) * (2 * HID) + h0 + c] + be1[h0 + c];
            sHj[r * 257 + c] = g_H[(size_t)(b * KK + r) * (2 * HID) + HID + h0 + c];
        }
        sW2[tid] = We2[h0 + tid];
        __syncthreads();
        const float* hi = sHi + i * 257;
        const float* hj = sHj + j * 257;
        float a0 = 0.f, a1 = 0.f, a2 = 0.f, a3 = 0.f;
        #pragma unroll 4
        for (int c = 0; c < 256; c += 4) {
            a0 += fmaxf(hi[c]     + hj[c],     0.f) * sW2[c];
            a1 += fmaxf(hi[c + 1] + hj[c + 1], 0.f) * sW2[c + 1];
            a2 += fmaxf(hi[c + 2] + hj[c + 2], 0.f) * sW2[c + 2];
            a3 += fmaxf(hi[c + 3] + hj[c + 3], 0.f) * sW2[c + 3];
        }
        acc += (a0 + a1) + (a2 + a3);
        __syncthreads();
    }
    float E = acc + be2[0];
    if (post) {
        outE[b * 256 + tid] = E;
    } else {
        sE[i * 17 + j] = E;
        __syncthreads();
        float m = -3.4e38f;
        #pragma unroll
        for (int jj = 0; jj < KK; jj++) m = fmaxf(m, sE[i * 17 + jj]);
        float s = 0.f;
        #pragma unroll
        for (int jj = 0; jj < KK; jj++) s += __expf(sE[i * 17 + jj] - m);
        g_A[b * 256 + tid] = __expf(E - m) / s;
    }
}

// ---------------- kMsg: V += relu(A @ M), write split-V (+optional outV) --
__global__ void kMsg(float* __restrict__ outV) {
    int b = blockIdx.x;
    int tid = threadIdx.x;
    __shared__ float sAm[KK * 17];
    sAm[(tid >> 4) * 17 + (tid & 15)] = g_A[b * 256 + tid];
    __syncthreads();
    float acc[KK][3];
    #pragma unroll
    for (int i = 0; i < KK; i++) { acc[i][0] = 0.f; acc[i][1] = 0.f; acc[i][2] = 0.f; }
    for (int j = 0; j < KK; j++) {
        const float* mr = g_M + (size_t)(b * KK + j) * DN + tid;
        float m0 = mr[0], m1 = mr[256], m2 = mr[512];
        #pragma unroll
        for (int i = 0; i < KK; i++) {
            float a = sAm[i * 17 + j];
            acc[i][0] += a * m0; acc[i][1] += a * m1; acc[i][2] += a * m2;
        }
    }
    #pragma unroll
    for (int i = 0; i < KK; i++) {
        int row = b * KK + i;
        float* vr = g_V + (size_t)row * DN;
        __nv_bfloat16* ar = (__nv_bfloat16*)g_Abf2 + (size_t)row * KSPLIT;
        float* ovr = outV ? (outV + (size_t)row * DN) : nullptr;
        #pragma unroll
        for (int c3 = 0; c3 < 3; c3++) {
            int d = tid + c3 * 256;
            float nv = vr[d] + fmaxf(acc[i][c3], 0.f);
            vr[d] = nv;
            __nv_bfloat16 h = __float2bfloat16(nv);
            __nv_bfloat16 l = __float2bfloat16(nv - __bfloat162float(h));
            ar[d] = h; ar[768 + d] = h; ar[1536 + d] = l;
            if (ovr) ovr[d] = nv;
        }
    }
}

// ---------------- host ----------------------------------------------------
extern "C" void kernel_launch(void* const* d_in, const int* in_sizes, int n_in,
                              void* d_out, int out_size) {
    const float* w    = (const float*)d_in[0];
    const int*   mask = (const int*)  d_in[1];
    const float* nq   = (const float*)d_in[2];
    const float* Wq   = (const float*)d_in[3];
    const float* bq   = (const float*)d_in[4];
    const float* Wk   = (const float*)d_in[5];
    const float* bk   = (const float*)d_in[6];
    const float* Wv   = (const float*)d_in[7];
    const float* bv   = (const float*)d_in[8];
    const float* We1  = (const float*)d_in[9];
    const float* be1  = (const float*)d_in[10];
    const float* We2  = (const float*)d_in[11];
    const float* be2  = (const float*)d_in[12];
    const float* fg   = (const float*)d_in[13];
    const float* Wg   = (const float*)d_in[14];
    const float* bg   = (const float*)d_in[15];

    float* outS = (float*)d_out;
    float* outV = outS + (size_t)BB * NN * KK;
    float* outE = outV + (size_t)BB * KK * DN;

    kSplitAllW<<<1248, 256>>>(Wv, Wg, We1);
    kQ<<<dim3(3, 8), 256>>>(nq, Wq);
    kP<<<96, 256>>>(Wk, bk, bq);
    kScore<<<BB, 256>>>(w, mask, outS);
    kU<<<dim3(BB, 2), 96>>>(w, outS);                          // split-U -> g_Abf

    kTGemm<<<dim3(32, 6), 256>>>(0, 0, 1, bv, nq, fg);         // V = U@Wv; split-V -> Abf2
    kTGemm<<<dim3(32, 14), 256>>>(1, 0, 3, bg, nullptr, nullptr);   // H = V@We1 AND M = V@Wg0+bg0
    kEdge<<<BB, 256>>>(be1, We2, be2, nullptr, 0);             // A = softmax(E)
    kMsg<<<BB, 256>>>(nullptr);                                // V += relu(A@M); Abf2
    kTGemm<<<dim3(32, 6), 256>>>(1, 2, 2, bg + DN, nullptr, nullptr); // M = V@Wg1+bg1
    kMsg<<<BB, 256>>>(outV);                                   // final V; Abf2; outV
    kTGemm<<<dim3(32, 8), 256>>>(1, 3, 0, nullptr, nullptr, nullptr); // H on final V
    kEdge<<<BB, 256>>>(be1, We2, be2, outE, 1);                // E -> out
}

// round 9
// speedup vs baseline: 1.9689x; 1.0704x over previous
#include <cuda_runtime.h>
#include <cuda_bf16.h>
#include <math.h>
#include <stdint.h>

// Problem dims
#define BB 256
#define NN 77
#define DD 768
#define KK 16
#define DN 768
#define HID 512
#define MTOT (BB*KK)          // 4096
#define SCALE 0.10206207261596575f   // (768/8)^-0.5
#define KSPLIT 2304           // 3*768 (split-K concat)
#define KCH 72                // 2304/32 chunks

// ---------------- scratch (device globals; no allocation) ----------------
__device__ float g_Qp[8][KK*DN];
__device__ float g_Pt[DD*KK];
__device__ float g_c[KK];
__device__ float g_Sp[4][BB*KK*80];   // partial scores [slice][b][k][n-pitch80]
__device__ float g_V[MTOT*DN];
__device__ float g_rowsum[MTOT];
__device__ float g_H[MTOT*2*HID];
__device__ float g_M[MTOT*DN];
__device__ float g_A[BB*KK*KK];
// split-bf16 operand buffers (uint4 for 16B alignment)
__device__ uint4 g_Abf [(size_t)MTOT*KSPLIT/8];   // split-U
__device__ uint4 g_Abf2[(size_t)MTOT*KSPLIT/8];   // split-V
__device__ uint4 g_WbfV [768*KSPLIT/8];
__device__ uint4 g_WbfG0[768*KSPLIT/8];
__device__ uint4 g_WbfG1[768*KSPLIT/8];
__device__ uint4 g_WbfE1[1024*KSPLIT/8];

__device__ __forceinline__ uint32_t smem_u32(const void* p) {
    uint32_t a;
    asm("{ .reg .u64 t; cvta.to.shared.u64 t, %1; cvt.u32.u64 %0, t; }"
        : "=r"(a) : "l"(p));
    return a;
}

__device__ __forceinline__ unsigned packbf2(float a, float b) {
    unsigned short lo = __bfloat16_as_ushort(__float2bfloat16(a));
    unsigned short hi = __bfloat16_as_ushort(__float2bfloat16(b));
    return ((unsigned)hi << 16) | lo;
}

// ---------------- kQ: partial Q = nq @ Wq (Wq read once) ------------------
__global__ void kQ(const float* __restrict__ nq, const float* __restrict__ Wq) {
    int d = blockIdx.x * 256 + threadIdx.x;
    int sl = blockIdx.y;
    int e0 = sl * 96;
    __shared__ float snq[KK][96];
    for (int idx = threadIdx.x; idx < KK * 96; idx += 256)
        snq[idx / 96][idx % 96] = nq[(idx / 96) * DN + e0 + idx % 96];
    __syncthreads();
    float acc[KK];
    #pragma unroll
    for (int k = 0; k < KK; k++) acc[k] = 0.f;
    const float* wp = Wq + (size_t)e0 * DN + d;
    #pragma unroll 4
    for (int e = 0; e < 96; e++) {
        float wv = wp[(size_t)e * DN];
        #pragma unroll
        for (int k = 0; k < KK; k++) acc[k] += snq[k][e] * wv;
    }
    #pragma unroll
    for (int k = 0; k < KK; k++) g_Qp[sl][k * DN + d] = acc[k];
}

// ---------------- kP: P^T[j][k] = Wk[j,:].Q[k,:] (warp per j) -------------
__global__ void kP(const float* __restrict__ Wk, const float* __restrict__ bk,
                   const float* __restrict__ bq) {
    __shared__ float sQ[KK][DN];   // 48 KB
    int tid = threadIdx.x;
    int lane = tid & 31, warp = tid >> 5;
    for (int idx = tid; idx < KK * DN; idx += 256) {
        float s = bq[idx % DN];
        #pragma unroll
        for (int sl = 0; sl < 8; sl++) s += g_Qp[sl][idx];
        sQ[idx / DN][idx % DN] = s;
    }
    __syncthreads();

    int j = blockIdx.x * 8 + warp;
    const float4* wr = (const float4*)(Wk + (size_t)j * DN);
    float acc[KK];
    #pragma unroll
    for (int k = 0; k < KK; k++) acc[k] = 0.f;
    #pragma unroll
    for (int it = 0; it < 6; it++) {
        int e = it * 128 + lane * 4;
        float4 wv = wr[it * 32 + lane];
        #pragma unroll
        for (int k = 0; k < KK; k++) {
            float4 qv = *(const float4*)&sQ[k][e];
            acc[k] += wv.x * qv.x + wv.y * qv.y + wv.z * qv.z + wv.w * qv.w;
        }
    }
    float out = 0.f;
    #pragma unroll
    for (int k = 0; k < KK; k++) {
        float v = acc[k];
        v += __shfl_xor_sync(0xFFFFFFFFu, v, 16);
        v += __shfl_xor_sync(0xFFFFFFFFu, v, 8);
        v += __shfl_xor_sync(0xFFFFFFFFu, v, 4);
        v += __shfl_xor_sync(0xFFFFFFFFu, v, 2);
        v += __shfl_xor_sync(0xFFFFFFFFu, v, 1);
        if (lane == k) out = v;
    }
    if (lane < KK) g_Pt[j * KK + lane] = out;

    if (blockIdx.x >= 94) {
        int k = (blockIdx.x - 94) * 8 + warp;
        float cc = 0.f;
        #pragma unroll
        for (int it = 0; it < 6; it++) {
            int e = it * 128 + lane * 4;
            float4 bv = *(const float4*)(bk + e);
            float4 qv = *(const float4*)&sQ[k][e];
            cc += bv.x * qv.x + bv.y * qv.y + bv.z * qv.z + bv.w * qv.w;
        }
        cc += __shfl_xor_sync(0xFFFFFFFFu, cc, 16);
        cc += __shfl_xor_sync(0xFFFFFFFFu, cc, 8);
        cc += __shfl_xor_sync(0xFFFFFFFFu, cc, 4);
        cc += __shfl_xor_sync(0xFFFFFFFFu, cc, 2);
        cc += __shfl_xor_sync(0xFFFFFFFFu, cc, 1);
        if (lane == 0) g_c[k] = cc;
    }
}

// ---------------- kSplitAllW: all 4 weight splits, one launch ------------
__global__ void kSplitAllW(const float* __restrict__ Wv,
                           const float* __restrict__ Wg,
                           const float* __restrict__ We1) {
    int sid = blockIdx.x * 256 + threadIdx.x;   // 0..319487
    float a[8];
    __nv_bfloat16* out;
    int e0;
    if (sid < 221184) {
        int job = sid / 73728, s = sid % 73728;
        int n = s % 768, seg = s / 768;
        e0 = seg * 8;
        const float* Wp = (job == 0) ? Wv : (job == 1) ? Wg : (Wg + 768 * 768);
        uint4* o4 = (job == 0) ? g_WbfV : (job == 1) ? g_WbfG0 : g_WbfG1;
        out = (__nv_bfloat16*)o4 + (size_t)n * KSPLIT;
        #pragma unroll
        for (int i = 0; i < 8; i++) a[i] = Wp[(size_t)(e0 + i) * 768 + n];
    } else {
        int s = sid - 221184;
        int n = s % 1024, seg = s / 1024;
        e0 = seg * 8;
        out = (__nv_bfloat16*)g_WbfE1 + (size_t)n * KSPLIT;
        size_t base = (n < HID) ? (size_t)n : ((size_t)768 * HID + (n - HID));
        #pragma unroll
        for (int i = 0; i < 8; i++) a[i] = We1[base + (size_t)(e0 + i) * HID];
    }
    unsigned h[4], l[4];
    #pragma unroll
    for (int i = 0; i < 4; i++) {
        float x = a[2 * i], y = a[2 * i + 1];
        float xh = __bfloat162float(__float2bfloat16(x));
        float yh = __bfloat162float(__float2bfloat16(y));
        h[i] = packbf2(x, y);
        l[i] = packbf2(x - xh, y - yh);
    }
    *(uint4*)(out + e0)        = *(uint4*)h;
    *(uint4*)(out + 768 + e0)  = *(uint4*)l;
    *(uint4*)(out + 1536 + e0) = *(uint4*)h;
}

// ---------------- kScoreP: partial scores over d-slice of 192 -------------
// grid (BB, 4), 256 threads; writes raw partial dots to g_Sp[slice]
__global__ void kScoreP(const float* __restrict__ w) {
    int b = blockIdx.x, dh = blockIdx.y;
    int tid = threadIdx.x;
    int ty = tid >> 4, tx = tid & 15;   // ty = k
    __shared__ float sW[80 * 68];       // [n][dd] pitch 68
    __shared__ float sP[64 * KK];

    float acc[5] = {0.f, 0.f, 0.f, 0.f, 0.f};
    #pragma unroll
    for (int it = 0; it < 3; it++) {
        int d0 = dh * 192 + it * 64;
        // vectorized stage: 80 rows x 16 float4
        for (int idx = tid; idx < 80 * 16; idx += 256) {
            int n = idx >> 4, dq = idx & 15;
            float4 v = (n < NN) ? *(const float4*)(w + (size_t)(b * NN + n) * DD + d0 + dq * 4)
                                : make_float4(0.f, 0.f, 0.f, 0.f);
            *(float4*)&sW[n * 68 + dq * 4] = v;
        }
        for (int idx = tid; idx < 64 * KK; idx += 256)
            sP[idx] = g_Pt[(size_t)d0 * KK + idx];
        __syncthreads();
        #pragma unroll 2
        for (int dd = 0; dd < 64; dd += 4) {
            float p0 = sP[(dd + 0) * KK + ty];
            float p1 = sP[(dd + 1) * KK + ty];
            float p2 = sP[(dd + 2) * KK + ty];
            float p3 = sP[(dd + 3) * KK + ty];
            #pragma unroll
            for (int i = 0; i < 5; i++) {
                float4 wv = *(const float4*)&sW[(tx + 16 * i) * 68 + dd];
                acc[i] += p0 * wv.x + p1 * wv.y + p2 * wv.z + p3 * wv.w;
            }
        }
        __syncthreads();
    }
    float* sp = g_Sp[dh] + (size_t)b * (KK * 80) + ty * 80 + tx;
    #pragma unroll
    for (int i = 0; i < 5; i++) sp[16 * i] = acc[i];
}

// ---------------- kSoftmax: combine partials -> softmax -> outS + rowsum --
__global__ void kSoftmax(const int* __restrict__ mask, float* __restrict__ outS) {
    int b = blockIdx.x;
    int tid = threadIdx.x;   // 128
    __shared__ float sSc[KK * 80];
    __shared__ float sSm[NN * KK];
    for (int idx = tid; idx < KK * 80; idx += 128) {
        float s = g_Sp[0][(size_t)b * (KK * 80) + idx] + g_Sp[1][(size_t)b * (KK * 80) + idx]
                + g_Sp[2][(size_t)b * (KK * 80) + idx] + g_Sp[3][(size_t)b * (KK * 80) + idx];
        sSc[idx] = (s + g_c[idx / 80]) * SCALE;
    }
    __syncthreads();
    if (tid < NN) {
        int n = tid;
        if (mask[b * NN + n] == 0) {
            #pragma unroll
            for (int k = 0; k < KK; k++) sSm[n * KK + k] = 1.0f / 16.0f;
        } else {
            float m = -3.4e38f;
            #pragma unroll
            for (int k = 0; k < KK; k++) m = fmaxf(m, sSc[k * 80 + n]);
            float e[KK]; float s = 0.f;
            #pragma unroll
            for (int k = 0; k < KK; k++) { e[k] = __expf(sSc[k * 80 + n] - m); s += e[k]; }
            float inv = 1.0f / s;
            #pragma unroll
            for (int k = 0; k < KK; k++) sSm[n * KK + k] = e[k] * inv;
        }
        #pragma unroll
        for (int k = 0; k < KK; k++)
            outS[(b * NN + n) * KK + k] = sSm[n * KK + k];
    }
    __syncthreads();
    if (tid < KK) {
        float s = 0.f;
        for (int n = 0; n < NN; n++) s += sSm[n * KK + tid];
        g_rowsum[b * KK + tid] = s;
    }
}

// ---------------- kU: U = S^T w, write split-U -> g_Abf -------------------
// grid (BB, 4), 96 threads; thread owns 2 adjacent d (float2)
__global__ void kU(const float* __restrict__ w, const float* __restrict__ S) {
    int b = blockIdx.x, dh = blockIdx.y;
    int tid = threadIdx.x;
    int d0 = dh * 192 + tid * 2;
    __shared__ float sS[NN * KK];
    for (int idx = tid; idx < NN * KK; idx += 96)
        sS[idx] = S[b * NN * KK + idx];
    __syncthreads();

    float2 acc[KK];
    #pragma unroll
    for (int k = 0; k < KK; k++) { acc[k].x = 0.f; acc[k].y = 0.f; }
    const float* wp = w + (size_t)b * NN * DD + d0;
    #pragma unroll 4
    for (int n = 0; n < NN; n++) {
        float2 wv = *(const float2*)(wp + (size_t)n * DD);
        const float* srow = sS + n * KK;
        #pragma unroll
        for (int k = 0; k < KK; k++) {
            float s = srow[k];
            acc[k].x += s * wv.x; acc[k].y += s * wv.y;
        }
    }
    #pragma unroll
    for (int k = 0; k < KK; k++) {
        float2 v = acc[k];
        float hx = __bfloat162float(__float2bfloat16(v.x));
        float hy = __bfloat162float(__float2bfloat16(v.y));
        unsigned hp = packbf2(v.x, v.y);
        unsigned lp = packbf2(v.x - hx, v.y - hy);
        __nv_bfloat16* ur = (__nv_bfloat16*)g_Abf + (size_t)(b * KK + k) * KSPLIT;
        *(unsigned*)(ur + d0) = hp;
        *(unsigned*)(ur + 768 + d0) = hp;
        *(unsigned*)(ur + 1536 + d0) = lp;
    }
}

// ---------------- kTGemm: mma.sync bf16-split GEMM ------------------------
// block 128x128, 8 warps as 4m x 2n (warp tile 32x64), 3-stage cp.async
__global__ __launch_bounds__(256, 2) void kTGemm(
    int asel, int wsel, int mode, const float* __restrict__ bias,
    const float* __restrict__ nq, const float* __restrict__ gatep)
{
    __shared__ __align__(1024) __nv_bfloat16 sA[3][128 * 32];
    __shared__ __align__(1024) __nv_bfloat16 sB[3][128 * 32];

    const __nv_bfloat16* Ag = (const __nv_bfloat16*)(asel ? g_Abf2 : g_Abf);
    const int m0 = blockIdx.x * 128;
    int n0 = blockIdx.y * 128;
    const __nv_bfloat16* Bg;
    float* C; int Ncols; int emode = mode;
    if (mode == 3) {
        if (blockIdx.y < 8) {
            Bg = (const __nv_bfloat16*)g_WbfE1; C = g_H; Ncols = 2 * HID; emode = 0;
        } else {
            n0 = (blockIdx.y - 8) * 128;
            Bg = (const __nv_bfloat16*)g_WbfG0; C = g_M; Ncols = DN; emode = 2;
        }
    } else {
        const uint4* B4 = (wsel == 0) ? g_WbfV : (wsel == 1) ? g_WbfG0
                        : (wsel == 2) ? g_WbfG1 : g_WbfE1;
        Bg = (const __nv_bfloat16*)B4;
        if (mode == 0)      { C = g_H; Ncols = 2 * HID; }
        else if (mode == 1) { C = g_V; Ncols = DN; }
        else                { C = g_M; Ncols = DN; }
    }

    const int tid = threadIdx.x;
    const int lane = tid & 31, warp = tid >> 5;
    const int wm = warp >> 1, wn = warp & 1;   // 4m x 2n warps, warp tile 32x64

    const uint32_t sAu = smem_u32(sA), sBu = smem_u32(sB);

    uint32_t soff[2];
    const __nv_bfloat16* gA[2];
    const __nv_bfloat16* gB[2];
    #pragma unroll
    for (int i = 0; i < 2; i++) {
        int v = tid * 2 + i, row = v >> 2, q = v & 3;
        soff[i] = row * 64 + ((q ^ ((row >> 1) & 3)) << 4);
        gA[i] = Ag + (size_t)(m0 + row) * KSPLIT + q * 8;
        gB[i] = Bg + (size_t)(n0 + row) * KSPLIT + q * 8;
    }

    const int r16 = lane & 15, hh = lane >> 4;
    uint32_t aoff[2][2], boff[2][4];
    #pragma unroll
    for (int s = 0; s < 2; s++) {
        int quad = 2 * s + hh;
        #pragma unroll
        for (int mt = 0; mt < 2; mt++) {
            int row = wm * 32 + mt * 16 + r16;
            aoff[s][mt] = row * 64 + ((quad ^ ((row >> 1) & 3)) << 4);
        }
        #pragma unroll
        for (int nb = 0; nb < 4; nb++) {
            int row = wn * 64 + nb * 16 + r16;
            boff[s][nb] = row * 64 + ((quad ^ ((row >> 1) & 3)) << 4);
        }
    }

    float acc[2][8][4];
    #pragma unroll
    for (int a = 0; a < 2; a++)
        #pragma unroll
        for (int b = 0; b < 8; b++)
            #pragma unroll
            for (int r = 0; r < 4; r++) acc[a][b][r] = 0.f;

    #pragma unroll
    for (int st = 0; st < 2; st++) {
        uint32_t da = sAu + st * 8192, db = sBu + st * 8192;
        #pragma unroll
        for (int i = 0; i < 2; i++) {
            asm volatile("cp.async.ca.shared.global [%0], [%1], 16;"
                         :: "r"(da + soff[i]), "l"(gA[i] + st * 32));
            asm volatile("cp.async.ca.shared.global [%0], [%1], 16;"
                         :: "r"(db + soff[i]), "l"(gB[i] + st * 32));
        }
        asm volatile("cp.async.commit_group;");
    }

    for (int c = 0; c < KCH; c++) {
        const int buf = c % 3;
        if (c + 1 < KCH) asm volatile("cp.async.wait_group 1;");
        else             asm volatile("cp.async.wait_group 0;");
        __syncthreads();
        if (c + 2 < KCH) {
            const int wb = (c + 2) % 3;
            const uint32_t da = sAu + wb * 8192, db = sBu + wb * 8192;
            #pragma unroll
            for (int i = 0; i < 2; i++) {
                asm volatile("cp.async.ca.shared.global [%0], [%1], 16;"
                             :: "r"(da + soff[i]), "l"(gA[i] + (c + 2) * 32));
                asm volatile("cp.async.ca.shared.global [%0], [%1], 16;"
                             :: "r"(db + soff[i]), "l"(gB[i] + (c + 2) * 32));
            }
            asm volatile("cp.async.commit_group;");
        }

        const uint32_t baseA = sAu + buf * 8192;
        const uint32_t baseB = sBu + buf * 8192;
        #pragma unroll
        for (int s = 0; s < 2; s++) {
            uint32_t afr[2][4];
            #pragma unroll
            for (int mt = 0; mt < 2; mt++) {
                asm volatile("ldmatrix.sync.aligned.m8n8.x4.shared.b16 "
                             "{%0,%1,%2,%3}, [%4];"
                             : "=r"(afr[mt][0]), "=r"(afr[mt][1]),
                               "=r"(afr[mt][2]), "=r"(afr[mt][3])
                             : "r"(baseA + aoff[s][mt]));
            }
            uint32_t bfr[8][2];
            #pragma unroll
            for (int nb = 0; nb < 4; nb++) {
                uint32_t r0, r1, r2, r3;
                asm volatile("ldmatrix.sync.aligned.m8n8.x4.shared.b16 "
                             "{%0,%1,%2,%3}, [%4];"
                             : "=r"(r0), "=r"(r1), "=r"(r2), "=r"(r3)
                             : "r"(baseB + boff[s][nb]));
                bfr[nb * 2][0] = r0;     bfr[nb * 2][1] = r2;
                bfr[nb * 2 + 1][0] = r1; bfr[nb * 2 + 1][1] = r3;
            }
            #pragma unroll
            for (int mt = 0; mt < 2; mt++)
                #pragma unroll
                for (int nt = 0; nt < 8; nt++) {
                    asm volatile(
                        "mma.sync.aligned.m16n8k16.row.col.f32.bf16.bf16.f32 "
                        "{%0,%1,%2,%3}, {%4,%5,%6,%7}, {%8,%9}, {%0,%1,%2,%3};"
                        : "+f"(acc[mt][nt][0]), "+f"(acc[mt][nt][1]),
                          "+f"(acc[mt][nt][2]), "+f"(acc[mt][nt][3])
                        : "r"(afr[mt][0]), "r"(afr[mt][1]),
                          "r"(afr[mt][2]), "r"(afr[mt][3]),
                          "r"(bfr[nt][0]), "r"(bfr[nt][1]));
                }
        }
    }

    float gate = 0.f, omg = 1.f;
    if (emode == 1) {
        gate = 1.0f / (1.0f + expf(-gatep[0]));
        omg = 1.0f - gate;
    }
    #pragma unroll
    for (int mt = 0; mt < 2; mt++) {
        #pragma unroll
        for (int half = 0; half < 2; half++) {
            int row = m0 + wm * 32 + mt * 16 + (lane >> 2) + 8 * half;
            float rsv = 0.f; const float* nqr = nullptr;
            __nv_bfloat16* arow2 = nullptr;
            if (emode == 1) {
                rsv = g_rowsum[row];
                nqr = nq + (size_t)(row & 15) * DN;
                arow2 = (__nv_bfloat16*)g_Abf2 + (size_t)row * KSPLIT;
            }
            float* crow = C + (size_t)row * Ncols;
            #pragma unroll
            for (int nt = 0; nt < 8; nt++) {
                int col = n0 + wn * 64 + nt * 8 + (lane & 3) * 2;
                float v0 = acc[mt][nt][half * 2 + 0];
                float v1 = acc[mt][nt][half * 2 + 1];
                if (emode == 1) {
                    v0 += rsv * __ldg(&bias[col]);
                    v1 += rsv * __ldg(&bias[col + 1]);
                    v0 = omg * v0 + gate * __ldg(&nqr[col]);
                    v1 = omg * v1 + gate * __ldg(&nqr[col + 1]);
                    float h0 = __bfloat162float(__float2bfloat16(v0));
                    float h1 = __bfloat162float(__float2bfloat16(v1));
                    unsigned hp = packbf2(v0, v1);
                    unsigned lp = packbf2(v0 - h0, v1 - h1);
                    *(unsigned*)(arow2 + col) = hp;
                    *(unsigned*)(arow2 + 768 + col) = hp;
                    *(unsigned*)(arow2 + 1536 + col) = lp;
                } else if (emode == 2) {
                    v0 += __ldg(&bias[col]);
                    v1 += __ldg(&bias[col + 1]);
                }
                float2 o; o.x = v0; o.y = v1;
                *(float2*)(crow + col) = o;
            }
        }
    }
}

// ---------------- kEdge ----------------------------------------------
__global__ void kEdge(const float* __restrict__ be1, const float* __restrict__ We2,
                      const float* __restrict__ be2, float* __restrict__ outE,
                      int post) {
    int b = blockIdx.x;
    int tid = threadIdx.x;
    int i = tid >> 4, j = tid & 15;
    __shared__ float sHi[KK * 257];
    __shared__ float sHj[KK * 257];
    __shared__ float sW2[256];
    __shared__ float sE[KK * 17];

    float acc = 0.f;
    for (int h0 = 0; h0 < HID; h0 += 256) {
        for (int idx = tid; idx < KK * 256; idx += 256) {
            int r = idx >> 8, c = idx & 255;
            sHi[r * 257 + c] = g_H[(size_t)(b * KK + r) * (2 * HID) + h0 + c] + be1[h0 + c];
            sHj[r * 257 + c] = g_H[(size_t)(b * KK + r) * (2 * HID) + HID + h0 + c];
        }
        sW2[tid] = We2[h0 + tid];
        __syncthreads();
        const float* hi = sHi + i * 257;
        const float* hj = sHj + j * 257;
        float a0 = 0.f, a1 = 0.f, a2 = 0.f, a3 = 0.f;
        #pragma unroll 4
        for (int c = 0; c < 256; c += 4) {
            a0 += fmaxf(hi[c]     + hj[c],     0.f) * sW2[c];
            a1 += fmaxf(hi[c + 1] + hj[c + 1], 0.f) * sW2[c + 1];
            a2 += fmaxf(hi[c + 2] + hj[c + 2], 0.f) * sW2[c + 2];
            a3 += fmaxf(hi[c + 3] + hj[c + 3], 0.f) * sW2[c + 3];
        }
        acc += (a0 + a1) + (a2 + a3);
        __syncthreads();
    }
    float E = acc + be2[0];
    if (post) {
        outE[b * 256 + tid] = E;
    } else {
        sE[i * 17 + j] = E;
        __syncthreads();
        float m = -3.4e38f;
        #pragma unroll
        for (int jj = 0; jj < KK; jj++) m = fmaxf(m, sE[i * 17 + jj]);
        float s = 0.f;
        #pragma unroll
        for (int jj = 0; jj < KK; jj++) s += __expf(sE[i * 17 + jj] - m);
        g_A[b * 256 + tid] = __expf(E - m) / s;
    }
}

// ---------------- kMsg: V += relu(A @ M), write split-V (+optional outV) --
__global__ void kMsg(float* __restrict__ outV) {
    int b = blockIdx.x;
    int tid = threadIdx.x;
    __shared__ float sAm[KK * 17];
    sAm[(tid >> 4) * 17 + (tid & 15)] = g_A[b * 256 + tid];
    __syncthreads();
    float acc[KK][3];
    #pragma unroll
    for (int i = 0; i < KK; i++) { acc[i][0] = 0.f; acc[i][1] = 0.f; acc[i][2] = 0.f; }
    for (int j = 0; j < KK; j++) {
        const float* mr = g_M + (size_t)(b * KK + j) * DN + tid;
        float m0 = mr[0], m1 = mr[256], m2 = mr[512];
        #pragma unroll
        for (int i = 0; i < KK; i++) {
            float a = sAm[i * 17 + j];
            acc[i][0] += a * m0; acc[i][1] += a * m1; acc[i][2] += a * m2;
        }
    }
    #pragma unroll
    for (int i = 0; i < KK; i++) {
        int row = b * KK + i;
        float* vr = g_V + (size_t)row * DN;
        __nv_bfloat16* ar = (__nv_bfloat16*)g_Abf2 + (size_t)row * KSPLIT;
        float* ovr = outV ? (outV + (size_t)row * DN) : nullptr;
        #pragma unroll
        for (int c3 = 0; c3 < 3; c3++) {
            int d = tid + c3 * 256;
            float nv = vr[d] + fmaxf(acc[i][c3], 0.f);
            vr[d] = nv;
            __nv_bfloat16 h = __float2bfloat16(nv);
            __nv_bfloat16 l = __float2bfloat16(nv - __bfloat162float(h));
            ar[d] = h; ar[768 + d] = h; ar[1536 + d] = l;
            if (ovr) ovr[d] = nv;
        }
    }
}

// ---------------- host ----------------------------------------------------
extern "C" void kernel_launch(void* const* d_in, const int* in_sizes, int n_in,
                              void* d_out, int out_size) {
    const float* w    = (const float*)d_in[0];
    const int*   mask = (const int*)  d_in[1];
    const float* nq   = (const float*)d_in[2];
    const float* Wq   = (const float*)d_in[3];
    const float* bq   = (const float*)d_in[4];
    const float* Wk   = (const float*)d_in[5];
    const float* bk   = (const float*)d_in[6];
    const float* Wv   = (const float*)d_in[7];
    const float* bv   = (const float*)d_in[8];
    const float* We1  = (const float*)d_in[9];
    const float* be1  = (const float*)d_in[10];
    const float* We2  = (const float*)d_in[11];
    const float* be2  = (const float*)d_in[12];
    const float* fg   = (const float*)d_in[13];
    const float* Wg   = (const float*)d_in[14];
    const float* bg   = (const float*)d_in[15];

    float* outS = (float*)d_out;
    float* outV = outS + (size_t)BB * NN * KK;
    float* outE = outV + (size_t)BB * KK * DN;

    kSplitAllW<<<1248, 256>>>(Wv, Wg, We1);
    kQ<<<dim3(3, 8), 256>>>(nq, Wq);
    kP<<<96, 256>>>(Wk, bk, bq);
    kScoreP<<<dim3(BB, 4), 256>>>(w);
    kSoftmax<<<BB, 128>>>(mask, outS);
    kU<<<dim3(BB, 4), 96>>>(w, outS);                          // split-U -> g_Abf

    kTGemm<<<dim3(32, 6), 256>>>(0, 0, 1, bv, nq, fg);         // V = U@Wv; split-V -> Abf2
    kTGemm<<<dim3(32, 14), 256>>>(1, 0, 3, bg, nullptr, nullptr);   // H = V@We1 AND M = V@Wg0+bg0
    kEdge<<<BB, 256>>>(be1, We2, be2, nullptr, 0);             // A = softmax(E)
    kMsg<<<BB, 256>>>(nullptr);                                // V += relu(A@M); Abf2
    kTGemm<<<dim3(32, 6), 256>>>(1, 2, 2, bg + DN, nullptr, nullptr); // M = V@Wg1+bg1
    kMsg<<<BB, 256>>>(outV);                                   // final V; Abf2; outV
    kTGemm<<<dim3(32, 8), 256>>>(1, 3, 0, nullptr, nullptr, nullptr); // H on final V
    kEdge<<<BB, 256>>>(be1, We2, be2, outE, 1);                // E -> out
}

// round 10
// speedup vs baseline: 1.9919x; 1.0117x over previous
#include <cuda_runtime.h>
#include <cuda_bf16.h>
#include <math.h>
#include <stdint.h>

// Problem dims
#define BB 256
#define NN 77
#define DD 768
#define KK 16
#define DN 768
#define HID 512
#define MTOT (BB*KK)          // 4096
#define SCALE 0.10206207261596575f   // (768/8)^-0.5
#define KSPLIT 2304           // 3*768 (split-K concat)
#define KCH 72                // 2304/32 chunks

// ---------------- scratch (device globals; no allocation) ----------------
__device__ float g_Qp[8][KK*DN];
__device__ float g_Pt[DD*KK];
__device__ float g_c[KK];
__device__ float g_Sp[8][BB*KK*80];   // partial scores [slice][b][k][n-pitch80]
__device__ float g_Ep[2][BB*256];     // partial edge logits
__device__ float g_V[MTOT*DN];
__device__ float g_rowsum[MTOT];
__device__ float g_H[MTOT*2*HID];
__device__ float g_M[MTOT*DN];
__device__ float g_A[BB*KK*KK];
// split-bf16 operand buffers (uint4 for 16B alignment)
__device__ uint4 g_Abf [(size_t)MTOT*KSPLIT/8];   // split-U
__device__ uint4 g_Abf2[(size_t)MTOT*KSPLIT/8];   // split-V
__device__ uint4 g_WbfV [768*KSPLIT/8];
__device__ uint4 g_WbfG0[768*KSPLIT/8];
__device__ uint4 g_WbfG1[768*KSPLIT/8];
__device__ uint4 g_WbfE1[1024*KSPLIT/8];

__device__ __forceinline__ uint32_t smem_u32(const void* p) {
    uint32_t a;
    asm("{ .reg .u64 t; cvta.to.shared.u64 t, %1; cvt.u32.u64 %0, t; }"
        : "=r"(a) : "l"(p));
    return a;
}

__device__ __forceinline__ unsigned packbf2(float a, float b) {
    unsigned short lo = __bfloat16_as_ushort(__float2bfloat16(a));
    unsigned short hi = __bfloat16_as_ushort(__float2bfloat16(b));
    return ((unsigned)hi << 16) | lo;
}

// ---------------- kQ: partial Q = nq @ Wq (Wq read once) ------------------
__global__ void kQ(const float* __restrict__ nq, const float* __restrict__ Wq) {
    int d = blockIdx.x * 256 + threadIdx.x;
    int sl = blockIdx.y;
    int e0 = sl * 96;
    __shared__ float snq[KK][96];
    for (int idx = threadIdx.x; idx < KK * 96; idx += 256)
        snq[idx / 96][idx % 96] = nq[(idx / 96) * DN + e0 + idx % 96];
    __syncthreads();
    float acc[KK];
    #pragma unroll
    for (int k = 0; k < KK; k++) acc[k] = 0.f;
    const float* wp = Wq + (size_t)e0 * DN + d;
    #pragma unroll 4
    for (int e = 0; e < 96; e++) {
        float wv = wp[(size_t)e * DN];
        #pragma unroll
        for (int k = 0; k < KK; k++) acc[k] += snq[k][e] * wv;
    }
    #pragma unroll
    for (int k = 0; k < KK; k++) g_Qp[sl][k * DN + d] = acc[k];
}

// ---------------- kP: P^T[j][k] = Wk[j,:].Q[k,:] (warp per j) -------------
__global__ void kP(const float* __restrict__ Wk, const float* __restrict__ bk,
                   const float* __restrict__ bq) {
    __shared__ float sQ[KK][DN];   // 48 KB
    int tid = threadIdx.x;
    int lane = tid & 31, warp = tid >> 5;
    for (int idx = tid; idx < KK * DN; idx += 256) {
        float s = bq[idx % DN];
        #pragma unroll
        for (int sl = 0; sl < 8; sl++) s += g_Qp[sl][idx];
        sQ[idx / DN][idx % DN] = s;
    }
    __syncthreads();

    int j = blockIdx.x * 8 + warp;
    const float4* wr = (const float4*)(Wk + (size_t)j * DN);
    float acc[KK];
    #pragma unroll
    for (int k = 0; k < KK; k++) acc[k] = 0.f;
    #pragma unroll
    for (int it = 0; it < 6; it++) {
        int e = it * 128 + lane * 4;
        float4 wv = wr[it * 32 + lane];
        #pragma unroll
        for (int k = 0; k < KK; k++) {
            float4 qv = *(const float4*)&sQ[k][e];
            acc[k] += wv.x * qv.x + wv.y * qv.y + wv.z * qv.z + wv.w * qv.w;
        }
    }
    float out = 0.f;
    #pragma unroll
    for (int k = 0; k < KK; k++) {
        float v = acc[k];
        v += __shfl_xor_sync(0xFFFFFFFFu, v, 16);
        v += __shfl_xor_sync(0xFFFFFFFFu, v, 8);
        v += __shfl_xor_sync(0xFFFFFFFFu, v, 4);
        v += __shfl_xor_sync(0xFFFFFFFFu, v, 2);
        v += __shfl_xor_sync(0xFFFFFFFFu, v, 1);
        if (lane == k) out = v;
    }
    if (lane < KK) g_Pt[j * KK + lane] = out;

    if (blockIdx.x >= 94) {
        int k = (blockIdx.x - 94) * 8 + warp;
        float cc = 0.f;
        #pragma unroll
        for (int it = 0; it < 6; it++) {
            int e = it * 128 + lane * 4;
            float4 bv = *(const float4*)(bk + e);
            float4 qv = *(const float4*)&sQ[k][e];
            cc += bv.x * qv.x + bv.y * qv.y + bv.z * qv.z + bv.w * qv.w;
        }
        cc += __shfl_xor_sync(0xFFFFFFFFu, cc, 16);
        cc += __shfl_xor_sync(0xFFFFFFFFu, cc, 8);
        cc += __shfl_xor_sync(0xFFFFFFFFu, cc, 4);
        cc += __shfl_xor_sync(0xFFFFFFFFu, cc, 2);
        cc += __shfl_xor_sync(0xFFFFFFFFu, cc, 1);
        if (lane == 0) g_c[k] = cc;
    }
}

// ---------------- kSplitAllW: all 4 weight splits, one launch ------------
__global__ void kSplitAllW(const float* __restrict__ Wv,
                           const float* __restrict__ Wg,
                           const float* __restrict__ We1) {
    int sid = blockIdx.x * 256 + threadIdx.x;   // 0..319487
    float a[8];
    __nv_bfloat16* out;
    int e0;
    if (sid < 221184) {
        int job = sid / 73728, s = sid % 73728;
        int n = s % 768, seg = s / 768;
        e0 = seg * 8;
        const float* Wp = (job == 0) ? Wv : (job == 1) ? Wg : (Wg + 768 * 768);
        uint4* o4 = (job == 0) ? g_WbfV : (job == 1) ? g_WbfG0 : g_WbfG1;
        out = (__nv_bfloat16*)o4 + (size_t)n * KSPLIT;
        #pragma unroll
        for (int i = 0; i < 8; i++) a[i] = Wp[(size_t)(e0 + i) * 768 + n];
    } else {
        int s = sid - 221184;
        int n = s % 1024, seg = s / 1024;
        e0 = seg * 8;
        out = (__nv_bfloat16*)g_WbfE1 + (size_t)n * KSPLIT;
        size_t base = (n < HID) ? (size_t)n : ((size_t)768 * HID + (n - HID));
        #pragma unroll
        for (int i = 0; i < 8; i++) a[i] = We1[base + (size_t)(e0 + i) * HID];
    }
    unsigned h[4], l[4];
    #pragma unroll
    for (int i = 0; i < 4; i++) {
        float x = a[2 * i], y = a[2 * i + 1];
        float xh = __bfloat162float(__float2bfloat16(x));
        float yh = __bfloat162float(__float2bfloat16(y));
        h[i] = packbf2(x, y);
        l[i] = packbf2(x - xh, y - yh);
    }
    *(uint4*)(out + e0)        = *(uint4*)h;
    *(uint4*)(out + 768 + e0)  = *(uint4*)l;
    *(uint4*)(out + 1536 + e0) = *(uint4*)h;
}

// ---------------- kScoreP: partial scores, 2k x 5n register tile ----------
// grid (BB, 4), 256 threads = rep(2) x ky(8) x tx(16); rep splits dd range.
// writes slice = dh*2+rep of g_Sp[8]
__global__ void kScoreP(const float* __restrict__ w) {
    int b = blockIdx.x, dh = blockIdx.y;
    int tid = threadIdx.x;
    int rep = tid >> 7, ky = (tid >> 4) & 7, tx = tid & 15;
    __shared__ float sW[80 * 68];       // [n][dd] pitch 68
    __shared__ float sP[64 * KK];       // [dd][k], k contiguous

    float acc[2][5];
    #pragma unroll
    for (int kk = 0; kk < 2; kk++)
        #pragma unroll
        for (int i = 0; i < 5; i++) acc[kk][i] = 0.f;

    #pragma unroll
    for (int it = 0; it < 3; it++) {
        int d0 = dh * 192 + it * 64;
        for (int idx = tid; idx < 80 * 16; idx += 256) {
            int n = idx >> 4, dq = idx & 15;
            float4 v = (n < NN) ? *(const float4*)(w + (size_t)(b * NN + n) * DD + d0 + dq * 4)
                                : make_float4(0.f, 0.f, 0.f, 0.f);
            *(float4*)&sW[n * 68 + dq * 4] = v;
        }
        for (int idx = tid; idx < 64 * KK; idx += 256)
            sP[idx] = g_Pt[(size_t)d0 * KK + idx];
        __syncthreads();
        int ddbase = rep * 32;
        #pragma unroll 2
        for (int dd = ddbase; dd < ddbase + 32; dd += 4) {
            float2 pp0 = *(const float2*)&sP[(dd + 0) * KK + 2 * ky];
            float2 pp1 = *(const float2*)&sP[(dd + 1) * KK + 2 * ky];
            float2 pp2 = *(const float2*)&sP[(dd + 2) * KK + 2 * ky];
            float2 pp3 = *(const float2*)&sP[(dd + 3) * KK + 2 * ky];
            #pragma unroll
            for (int i = 0; i < 5; i++) {
                float4 wv = *(const float4*)&sW[(tx + 16 * i) * 68 + dd];
                acc[0][i] += pp0.x * wv.x + pp1.x * wv.y + pp2.x * wv.z + pp3.x * wv.w;
                acc[1][i] += pp0.y * wv.x + pp1.y * wv.y + pp2.y * wv.z + pp3.y * wv.w;
            }
        }
        __syncthreads();
    }
    int slice = dh * 2 + rep;
    #pragma unroll
    for (int kk = 0; kk < 2; kk++) {
        float* sp = g_Sp[slice] + (size_t)b * (KK * 80) + (2 * ky + kk) * 80 + tx;
        #pragma unroll
        for (int i = 0; i < 5; i++) sp[16 * i] = acc[kk][i];
    }
}

// ---------------- kSoftmax: combine 8 partials -> softmax -> outS + rowsum
__global__ void kSoftmax(const int* __restrict__ mask, float* __restrict__ outS) {
    int b = blockIdx.x;
    int tid = threadIdx.x;   // 128
    __shared__ float sSc[KK * 80];
    __shared__ float sSm[NN * KK];
    for (int idx = tid; idx < KK * 80; idx += 128) {
        float s = 0.f;
        #pragma unroll
        for (int sl = 0; sl < 8; sl++) s += g_Sp[sl][(size_t)b * (KK * 80) + idx];
        sSc[idx] = (s + g_c[idx / 80]) * SCALE;
    }
    __syncthreads();
    if (tid < NN) {
        int n = tid;
        if (mask[b * NN + n] == 0) {
            #pragma unroll
            for (int k = 0; k < KK; k++) sSm[n * KK + k] = 1.0f / 16.0f;
        } else {
            float m = -3.4e38f;
            #pragma unroll
            for (int k = 0; k < KK; k++) m = fmaxf(m, sSc[k * 80 + n]);
            float e[KK]; float s = 0.f;
            #pragma unroll
            for (int k = 0; k < KK; k++) { e[k] = __expf(sSc[k * 80 + n] - m); s += e[k]; }
            float inv = 1.0f / s;
            #pragma unroll
            for (int k = 0; k < KK; k++) sSm[n * KK + k] = e[k] * inv;
        }
        #pragma unroll
        for (int k = 0; k < KK; k++)
            outS[(b * NN + n) * KK + k] = sSm[n * KK + k];
    }
    __syncthreads();
    if (tid < KK) {
        float s = 0.f;
        for (int n = 0; n < NN; n++) s += sSm[n * KK + tid];
        g_rowsum[b * KK + tid] = s;
    }
}

// ---------------- kU: U = S^T w, write split-U -> g_Abf -------------------
// grid (BB, 4), 96 threads; thread owns 2 adjacent d (float2)
__global__ void kU(const float* __restrict__ w, const float* __restrict__ S) {
    int b = blockIdx.x, dh = blockIdx.y;
    int tid = threadIdx.x;
    int d0 = dh * 192 + tid * 2;
    __shared__ float sS[NN * KK];
    for (int idx = tid; idx < NN * KK; idx += 96)
        sS[idx] = S[b * NN * KK + idx];
    __syncthreads();

    float2 acc[KK];
    #pragma unroll
    for (int k = 0; k < KK; k++) { acc[k].x = 0.f; acc[k].y = 0.f; }
    const float* wp = w + (size_t)b * NN * DD + d0;
    #pragma unroll 4
    for (int n = 0; n < NN; n++) {
        float2 wv = *(const float2*)(wp + (size_t)n * DD);
        const float* srow = sS + n * KK;
        #pragma unroll
        for (int k = 0; k < KK; k++) {
            float s = srow[k];
            acc[k].x += s * wv.x; acc[k].y += s * wv.y;
        }
    }
    #pragma unroll
    for (int k = 0; k < KK; k++) {
        float2 v = acc[k];
        float hx = __bfloat162float(__float2bfloat16(v.x));
        float hy = __bfloat162float(__float2bfloat16(v.y));
        unsigned hp = packbf2(v.x, v.y);
        unsigned lp = packbf2(v.x - hx, v.y - hy);
        __nv_bfloat16* ur = (__nv_bfloat16*)g_Abf + (size_t)(b * KK + k) * KSPLIT;
        *(unsigned*)(ur + d0) = hp;
        *(unsigned*)(ur + 768 + d0) = hp;
        *(unsigned*)(ur + 1536 + d0) = lp;
    }
}

// ---------------- kTGemm: mma.sync bf16-split GEMM ------------------------
// block 128x128, 8 warps as 4m x 2n (warp tile 32x64), 3-stage cp.async
__global__ __launch_bounds__(256, 2) void kTGemm(
    int asel, int wsel, int mode, const float* __restrict__ bias,
    const float* __restrict__ nq, const float* __restrict__ gatep)
{
    __shared__ __align__(1024) __nv_bfloat16 sA[3][128 * 32];
    __shared__ __align__(1024) __nv_bfloat16 sB[3][128 * 32];

    const __nv_bfloat16* Ag = (const __nv_bfloat16*)(asel ? g_Abf2 : g_Abf);
    const int m0 = blockIdx.x * 128;
    int n0 = blockIdx.y * 128;
    const __nv_bfloat16* Bg;
    float* C; int Ncols; int emode = mode;
    if (mode == 3) {
        if (blockIdx.y < 8) {
            Bg = (const __nv_bfloat16*)g_WbfE1; C = g_H; Ncols = 2 * HID; emode = 0;
        } else {
            n0 = (blockIdx.y - 8) * 128;
            Bg = (const __nv_bfloat16*)g_WbfG0; C = g_M; Ncols = DN; emode = 2;
        }
    } else {
        const uint4* B4 = (wsel == 0) ? g_WbfV : (wsel == 1) ? g_WbfG0
                        : (wsel == 2) ? g_WbfG1 : g_WbfE1;
        Bg = (const __nv_bfloat16*)B4;
        if (mode == 0)      { C = g_H; Ncols = 2 * HID; }
        else if (mode == 1) { C = g_V; Ncols = DN; }
        else                { C = g_M; Ncols = DN; }
    }

    const int tid = threadIdx.x;
    const int lane = tid & 31, warp = tid >> 5;
    const int wm = warp >> 1, wn = warp & 1;   // 4m x 2n warps, warp tile 32x64

    const uint32_t sAu = smem_u32(sA), sBu = smem_u32(sB);

    uint32_t soff[2];
    const __nv_bfloat16* gA[2];
    const __nv_bfloat16* gB[2];
    #pragma unroll
    for (int i = 0; i < 2; i++) {
        int v = tid * 2 + i, row = v >> 2, q = v & 3;
        soff[i] = row * 64 + ((q ^ ((row >> 1) & 3)) << 4);
        gA[i] = Ag + (size_t)(m0 + row) * KSPLIT + q * 8;
        gB[i] = Bg + (size_t)(n0 + row) * KSPLIT + q * 8;
    }

    const int r16 = lane & 15, hh = lane >> 4;
    uint32_t aoff[2][2], boff[2][4];
    #pragma unroll
    for (int s = 0; s < 2; s++) {
        int quad = 2 * s + hh;
        #pragma unroll
        for (int mt = 0; mt < 2; mt++) {
            int row = wm * 32 + mt * 16 + r16;
            aoff[s][mt] = row * 64 + ((quad ^ ((row >> 1) & 3)) << 4);
        }
        #pragma unroll
        for (int nb = 0; nb < 4; nb++) {
            int row = wn * 64 + nb * 16 + r16;
            boff[s][nb] = row * 64 + ((quad ^ ((row >> 1) & 3)) << 4);
        }
    }

    float acc[2][8][4];
    #pragma unroll
    for (int a = 0; a < 2; a++)
        #pragma unroll
        for (int b = 0; b < 8; b++)
            #pragma unroll
            for (int r = 0; r < 4; r++) acc[a][b][r] = 0.f;

    #pragma unroll
    for (int st = 0; st < 2; st++) {
        uint32_t da = sAu + st * 8192, db = sBu + st * 8192;
        #pragma unroll
        for (int i = 0; i < 2; i++) {
            asm volatile("cp.async.ca.shared.global [%0], [%1], 16;"
                         :: "r"(da + soff[i]), "l"(gA[i] + st * 32));
            asm volatile("cp.async.ca.shared.global [%0], [%1], 16;"
                         :: "r"(db + soff[i]), "l"(gB[i] + st * 32));
        }
        asm volatile("cp.async.commit_group;");
    }

    for (int c = 0; c < KCH; c++) {
        const int buf = c % 3;
        if (c + 1 < KCH) asm volatile("cp.async.wait_group 1;");
        else             asm volatile("cp.async.wait_group 0;");
        __syncthreads();
        if (c + 2 < KCH) {
            const int wb = (c + 2) % 3;
            const uint32_t da = sAu + wb * 8192, db = sBu + wb * 8192;
            #pragma unroll
            for (int i = 0; i < 2; i++) {
                asm volatile("cp.async.ca.shared.global [%0], [%1], 16;"
                             :: "r"(da + soff[i]), "l"(gA[i] + (c + 2) * 32));
                asm volatile("cp.async.ca.shared.global [%0], [%1], 16;"
                             :: "r"(db + soff[i]), "l"(gB[i] + (c + 2) * 32));
            }
            asm volatile("cp.async.commit_group;");
        }

        const uint32_t baseA = sAu + buf * 8192;
        const uint32_t baseB = sBu + buf * 8192;
        #pragma unroll
        for (int s = 0; s < 2; s++) {
            uint32_t afr[2][4];
            #pragma unroll
            for (int mt = 0; mt < 2; mt++) {
                asm volatile("ldmatrix.sync.aligned.m8n8.x4.shared.b16 "
                             "{%0,%1,%2,%3}, [%4];"
                             : "=r"(afr[mt][0]), "=r"(afr[mt][1]),
                               "=r"(afr[mt][2]), "=r"(afr[mt][3])
                             : "r"(baseA + aoff[s][mt]));
            }
            uint32_t bfr[8][2];
            #pragma unroll
            for (int nb = 0; nb < 4; nb++) {
                uint32_t r0, r1, r2, r3;
                asm volatile("ldmatrix.sync.aligned.m8n8.x4.shared.b16 "
                             "{%0,%1,%2,%3}, [%4];"
                             : "=r"(r0), "=r"(r1), "=r"(r2), "=r"(r3)
                             : "r"(baseB + boff[s][nb]));
                bfr[nb * 2][0] = r0;     bfr[nb * 2][1] = r2;
                bfr[nb * 2 + 1][0] = r1; bfr[nb * 2 + 1][1] = r3;
            }
            #pragma unroll
            for (int mt = 0; mt < 2; mt++)
                #pragma unroll
                for (int nt = 0; nt < 8; nt++) {
                    asm volatile(
                        "mma.sync.aligned.m16n8k16.row.col.f32.bf16.bf16.f32 "
                        "{%0,%1,%2,%3}, {%4,%5,%6,%7}, {%8,%9}, {%0,%1,%2,%3};"
                        : "+f"(acc[mt][nt][0]), "+f"(acc[mt][nt][1]),
                          "+f"(acc[mt][nt][2]), "+f"(acc[mt][nt][3])
                        : "r"(afr[mt][0]), "r"(afr[mt][1]),
                          "r"(afr[mt][2]), "r"(afr[mt][3]),
                          "r"(bfr[nt][0]), "r"(bfr[nt][1]));
                }
        }
    }

    float gate = 0.f, omg = 1.f;
    if (emode == 1) {
        gate = 1.0f / (1.0f + expf(-gatep[0]));
        omg = 1.0f - gate;
    }
    #pragma unroll
    for (int mt = 0; mt < 2; mt++) {
        #pragma unroll
        for (int half = 0; half < 2; half++) {
            int row = m0 + wm * 32 + mt * 16 + (lane >> 2) + 8 * half;
            float rsv = 0.f; const float* nqr = nullptr;
            __nv_bfloat16* arow2 = nullptr;
            if (emode == 1) {
                rsv = g_rowsum[row];
                nqr = nq + (size_t)(row & 15) * DN;
                arow2 = (__nv_bfloat16*)g_Abf2 + (size_t)row * KSPLIT;
            }
            float* crow = C + (size_t)row * Ncols;
            #pragma unroll
            for (int nt = 0; nt < 8; nt++) {
                int col = n0 + wn * 64 + nt * 8 + (lane & 3) * 2;
                float v0 = acc[mt][nt][half * 2 + 0];
                float v1 = acc[mt][nt][half * 2 + 1];
                if (emode == 1) {
                    v0 += rsv * __ldg(&bias[col]);
                    v1 += rsv * __ldg(&bias[col + 1]);
                    v0 = omg * v0 + gate * __ldg(&nqr[col]);
                    v1 = omg * v1 + gate * __ldg(&nqr[col + 1]);
                    float h0 = __bfloat162float(__float2bfloat16(v0));
                    float h1 = __bfloat162float(__float2bfloat16(v1));
                    unsigned hp = packbf2(v0, v1);
                    unsigned lp = packbf2(v0 - h0, v1 - h1);
                    *(unsigned*)(arow2 + col) = hp;
                    *(unsigned*)(arow2 + 768 + col) = hp;
                    *(unsigned*)(arow2 + 1536 + col) = lp;
                } else if (emode == 2) {
                    v0 += __ldg(&bias[col]);
                    v1 += __ldg(&bias[col + 1]);
                }
                float2 o; o.x = v0; o.y = v1;
                *(float2*)(crow + col) = o;
            }
        }
    }
}

// ---------------- kEdgeP: partial edge logits over one 256-h chunk --------
// grid (BB, 2): by = h-chunk
__global__ void kEdgeP(const float* __restrict__ be1, const float* __restrict__ We2) {
    int b = blockIdx.x;
    int h0 = blockIdx.y * 256;
    int tid = threadIdx.x;
    int i = tid >> 4, j = tid & 15;
    __shared__ float sHi[KK * 257];
    __shared__ float sHj[KK * 257];
    __shared__ float sW2[256];

    for (int idx = tid; idx < KK * 256; idx += 256) {
        int r = idx >> 8, c = idx & 255;
        sHi[r * 257 + c] = g_H[(size_t)(b * KK + r) * (2 * HID) + h0 + c] + be1[h0 + c];
        sHj[r * 257 + c] = g_H[(size_t)(b * KK + r) * (2 * HID) + HID + h0 + c];
    }
    sW2[tid] = We2[h0 + tid];
    __syncthreads();
    const float* hi = sHi + i * 257;
    const float* hj = sHj + j * 257;
    float a0 = 0.f, a1 = 0.f, a2 = 0.f, a3 = 0.f;
    #pragma unroll 4
    for (int c = 0; c < 256; c += 4) {
        a0 += fmaxf(hi[c]     + hj[c],     0.f) * sW2[c];
        a1 += fmaxf(hi[c + 1] + hj[c + 1], 0.f) * sW2[c + 1];
        a2 += fmaxf(hi[c + 2] + hj[c + 2], 0.f) * sW2[c + 2];
        a3 += fmaxf(hi[c + 3] + hj[c + 3], 0.f) * sW2[c + 3];
    }
    g_Ep[blockIdx.y][b * 256 + tid] = (a0 + a1) + (a2 + a3);
}

// ---------------- kEdgeR: combine partials -> softmax(A) or outE ----------
__global__ void kEdgeR(const float* __restrict__ be2, float* __restrict__ outE,
                       int post) {
    int b = blockIdx.x;
    int tid = threadIdx.x;
    int i = tid >> 4;
    __shared__ float sE[KK * 17];
    float E = g_Ep[0][b * 256 + tid] + g_Ep[1][b * 256 + tid] + be2[0];
    if (post) {
        outE[b * 256 + tid] = E;
    } else {
        sE[i * 17 + (tid & 15)] = E;
        __syncthreads();
        float m = -3.4e38f;
        #pragma unroll
        for (int jj = 0; jj < KK; jj++) m = fmaxf(m, sE[i * 17 + jj]);
        float s = 0.f;
        #pragma unroll
        for (int jj = 0; jj < KK; jj++) s += __expf(sE[i * 17 + jj] - m);
        g_A[b * 256 + tid] = __expf(E - m) / s;
    }
}

// ---------------- kMsg: V += relu(A @ M), write split-V (+optional outV) --
__global__ void kMsg(float* __restrict__ outV) {
    int b = blockIdx.x;
    int tid = threadIdx.x;
    __shared__ float sAm[KK * 17];
    sAm[(tid >> 4) * 17 + (tid & 15)] = g_A[b * 256 + tid];
    __syncthreads();
    float acc[KK][3];
    #pragma unroll
    for (int i = 0; i < KK; i++) { acc[i][0] = 0.f; acc[i][1] = 0.f; acc[i][2] = 0.f; }
    for (int j = 0; j < KK; j++) {
        const float* mr = g_M + (size_t)(b * KK + j) * DN + tid;
        float m0 = mr[0], m1 = mr[256], m2 = mr[512];
        #pragma unroll
        for (int i = 0; i < KK; i++) {
            float a = sAm[i * 17 + j];
            acc[i][0] += a * m0; acc[i][1] += a * m1; acc[i][2] += a * m2;
        }
    }
    #pragma unroll
    for (int i = 0; i < KK; i++) {
        int row = b * KK + i;
        float* vr = g_V + (size_t)row * DN;
        __nv_bfloat16* ar = (__nv_bfloat16*)g_Abf2 + (size_t)row * KSPLIT;
        float* ovr = outV ? (outV + (size_t)row * DN) : nullptr;
        #pragma unroll
        for (int c3 = 0; c3 < 3; c3++) {
            int d = tid + c3 * 256;
            float nv = vr[d] + fmaxf(acc[i][c3], 0.f);
            vr[d] = nv;
            __nv_bfloat16 h = __float2bfloat16(nv);
            __nv_bfloat16 l = __float2bfloat16(nv - __bfloat162float(h));
            ar[d] = h; ar[768 + d] = h; ar[1536 + d] = l;
            if (ovr) ovr[d] = nv;
        }
    }
}

// ---------------- host ----------------------------------------------------
extern "C" void kernel_launch(void* const* d_in, const int* in_sizes, int n_in,
                              void* d_out, int out_size) {
    const float* w    = (const float*)d_in[0];
    const int*   mask = (const int*)  d_in[1];
    const float* nq   = (const float*)d_in[2];
    const float* Wq   = (const float*)d_in[3];
    const float* bq   = (const float*)d_in[4];
    const float* Wk   = (const float*)d_in[5];
    const float* bk   = (const float*)d_in[6];
    const float* Wv   = (const float*)d_in[7];
    const float* bv   = (const float*)d_in[8];
    const float* We1  = (const float*)d_in[9];
    const float* be1  = (const float*)d_in[10];
    const float* We2  = (const float*)d_in[11];
    const float* be2  = (const float*)d_in[12];
    const float* fg   = (const float*)d_in[13];
    const float* Wg   = (const float*)d_in[14];
    const float* bg   = (const float*)d_in[15];

    float* outS = (float*)d_out;
    float* outV = outS + (size_t)BB * NN * KK;
    float* outE = outV + (size_t)BB * KK * DN;

    kSplitAllW<<<1248, 256>>>(Wv, Wg, We1);
    kQ<<<dim3(3, 8), 256>>>(nq, Wq);
    kP<<<96, 256>>>(Wk, bk, bq);
    kScoreP<<<dim3(BB, 4), 256>>>(w);
    kSoftmax<<<BB, 128>>>(mask, outS);
    kU<<<dim3(BB, 4), 96>>>(w, outS);                          // split-U -> g_Abf

    kTGemm<<<dim3(32, 6), 256>>>(0, 0, 1, bv, nq, fg);         // V = U@Wv; split-V -> Abf2
    kTGemm<<<dim3(32, 14), 256>>>(1, 0, 3, bg, nullptr, nullptr);   // H = V@We1 AND M = V@Wg0+bg0
    kEdgeP<<<dim3(BB, 2), 256>>>(be1, We2);                    // partial E
    kEdgeR<<<BB, 256>>>(be2, nullptr, 0);                      // A = softmax(E)
    kMsg<<<BB, 256>>>(nullptr);                                // V += relu(A@M); Abf2
    kTGemm<<<dim3(32, 6), 256>>>(1, 2, 2, bg + DN, nullptr, nullptr); // M = V@Wg1+bg1
    kMsg<<<BB, 256>>>(outV);                                   // final V; Abf2; outV
    kTGemm<<<dim3(32, 8), 256>>>(1, 3, 0, nullptr, nullptr, nullptr); // H on final V
    kEdgeP<<<dim3(BB, 2), 256>>>(be1, We2);                    // partial E (final V)
    kEdgeR<<<BB, 256>>>(be2, outE, 1);                         // E -> out
}

// round 11
// speedup vs baseline: 3.5554x; 1.7849x over previous
#include <cuda_runtime.h>
#include <cuda_bf16.h>
#include <cuda_fp16.h>
#include <math.h>
#include <stdint.h>

// Problem dims
#define BB 256
#define NN 77
#define DD 768
#define KK 16
#define DN 768
#define HID 512
#define MTOT (BB*KK)          // 4096
#define SCALE 0.10206207261596575f   // (768/8)^-0.5
#define KH 768                // GEMM K (fp16 single-term)
#define KCH 24                // 768/32 chunks

// ---------------- scratch (device globals; no allocation) ----------------
__device__ float g_Qp[8][KK*DN];
__device__ float g_Pt[DD*KK];
__device__ float g_c[KK];
__device__ float g_Sp[8][BB*KK*80];   // partial scores [slice][b][k][n-pitch80]
__device__ float g_Ep[2][BB*256];     // partial edge logits
__device__ float g_V[MTOT*DN];
__device__ float g_rowsum[MTOT];
__device__ float g_H[MTOT*2*HID];
__device__ float g_M[MTOT*DN];
__device__ float g_A[BB*KK*KK];
// fp16 operand buffers (uint4 for 16B alignment)
__device__ uint4 g_Abf [(size_t)MTOT*KH/8];   // fp16 U
__device__ uint4 g_Abf2[(size_t)MTOT*KH/8];   // fp16 V
__device__ uint4 g_WbfV [768*KH/8];
__device__ uint4 g_WbfG0[768*KH/8];
__device__ uint4 g_WbfG1[768*KH/8];
__device__ uint4 g_WbfE1[1024*KH/8];

__device__ __forceinline__ uint32_t smem_u32(const void* p) {
    uint32_t a;
    asm("{ .reg .u64 t; cvta.to.shared.u64 t, %1; cvt.u32.u64 %0, t; }"
        : "=r"(a) : "l"(p));
    return a;
}

__device__ __forceinline__ unsigned packh2(float a, float b) {
    __half2 h = __floats2half2_rn(a, b);
    return *(unsigned*)&h;
}

// ---------------- kQ: partial Q = nq @ Wq (Wq read once) ------------------
__global__ void kQ(const float* __restrict__ nq, const float* __restrict__ Wq) {
    int d = blockIdx.x * 256 + threadIdx.x;
    int sl = blockIdx.y;
    int e0 = sl * 96;
    __shared__ float snq[KK][96];
    for (int idx = threadIdx.x; idx < KK * 96; idx += 256)
        snq[idx / 96][idx % 96] = nq[(idx / 96) * DN + e0 + idx % 96];
    __syncthreads();
    float acc[KK];
    #pragma unroll
    for (int k = 0; k < KK; k++) acc[k] = 0.f;
    const float* wp = Wq + (size_t)e0 * DN + d;
    #pragma unroll 4
    for (int e = 0; e < 96; e++) {
        float wv = wp[(size_t)e * DN];
        #pragma unroll
        for (int k = 0; k < KK; k++) acc[k] += snq[k][e] * wv;
    }
    #pragma unroll
    for (int k = 0; k < KK; k++) g_Qp[sl][k * DN + d] = acc[k];
}

// ---------------- kP: P^T[j][k] = Wk[j,:].Q[k,:] (warp per j) -------------
__global__ void kP(const float* __restrict__ Wk, const float* __restrict__ bk,
                   const float* __restrict__ bq) {
    __shared__ float sQ[KK][DN];   // 48 KB
    int tid = threadIdx.x;
    int lane = tid & 31, warp = tid >> 5;
    for (int idx = tid; idx < KK * DN; idx += 256) {
        float s = bq[idx % DN];
        #pragma unroll
        for (int sl = 0; sl < 8; sl++) s += g_Qp[sl][idx];
        sQ[idx / DN][idx % DN] = s;
    }
    __syncthreads();

    int j = blockIdx.x * 8 + warp;
    const float4* wr = (const float4*)(Wk + (size_t)j * DN);
    float acc[KK];
    #pragma unroll
    for (int k = 0; k < KK; k++) acc[k] = 0.f;
    #pragma unroll
    for (int it = 0; it < 6; it++) {
        int e = it * 128 + lane * 4;
        float4 wv = wr[it * 32 + lane];
        #pragma unroll
        for (int k = 0; k < KK; k++) {
            float4 qv = *(const float4*)&sQ[k][e];
            acc[k] += wv.x * qv.x + wv.y * qv.y + wv.z * qv.z + wv.w * qv.w;
        }
    }
    float out = 0.f;
    #pragma unroll
    for (int k = 0; k < KK; k++) {
        float v = acc[k];
        v += __shfl_xor_sync(0xFFFFFFFFu, v, 16);
        v += __shfl_xor_sync(0xFFFFFFFFu, v, 8);
        v += __shfl_xor_sync(0xFFFFFFFFu, v, 4);
        v += __shfl_xor_sync(0xFFFFFFFFu, v, 2);
        v += __shfl_xor_sync(0xFFFFFFFFu, v, 1);
        if (lane == k) out = v;
    }
    if (lane < KK) g_Pt[j * KK + lane] = out;

    if (blockIdx.x >= 94) {
        int k = (blockIdx.x - 94) * 8 + warp;
        float cc = 0.f;
        #pragma unroll
        for (int it = 0; it < 6; it++) {
            int e = it * 128 + lane * 4;
            float4 bv = *(const float4*)(bk + e);
            float4 qv = *(const float4*)&sQ[k][e];
            cc += bv.x * qv.x + bv.y * qv.y + bv.z * qv.z + bv.w * qv.w;
        }
        cc += __shfl_xor_sync(0xFFFFFFFFu, cc, 16);
        cc += __shfl_xor_sync(0xFFFFFFFFu, cc, 8);
        cc += __shfl_xor_sync(0xFFFFFFFFu, cc, 4);
        cc += __shfl_xor_sync(0xFFFFFFFFu, cc, 2);
        cc += __shfl_xor_sync(0xFFFFFFFFu, cc, 1);
        if (lane == 0) g_c[k] = cc;
    }
}

// ---------------- kSplitAllW: all 4 weight conversions, one launch -------
__global__ void kSplitAllW(const float* __restrict__ Wv,
                           const float* __restrict__ Wg,
                           const float* __restrict__ We1) {
    int sid = blockIdx.x * 256 + threadIdx.x;   // 0..319487
    float a[8];
    __half* out;
    int e0;
    if (sid < 221184) {
        int job = sid / 73728, s = sid % 73728;
        int n = s % 768, seg = s / 768;
        e0 = seg * 8;
        const float* Wp = (job == 0) ? Wv : (job == 1) ? Wg : (Wg + 768 * 768);
        uint4* o4 = (job == 0) ? g_WbfV : (job == 1) ? g_WbfG0 : g_WbfG1;
        out = (__half*)o4 + (size_t)n * KH;
        #pragma unroll
        for (int i = 0; i < 8; i++) a[i] = Wp[(size_t)(e0 + i) * 768 + n];
    } else {
        int s = sid - 221184;
        int n = s % 1024, seg = s / 1024;
        e0 = seg * 8;
        out = (__half*)g_WbfE1 + (size_t)n * KH;
        size_t base = (n < HID) ? (size_t)n : ((size_t)768 * HID + (n - HID));
        #pragma unroll
        for (int i = 0; i < 8; i++) a[i] = We1[base + (size_t)(e0 + i) * HID];
    }
    unsigned h[4];
    #pragma unroll
    for (int i = 0; i < 4; i++) h[i] = packh2(a[2 * i], a[2 * i + 1]);
    *(uint4*)(out + e0) = *(uint4*)h;
}

// ---------------- kScoreP: partial scores, 2k x 5n register tile ----------
__global__ void kScoreP(const float* __restrict__ w) {
    int b = blockIdx.x, dh = blockIdx.y;
    int tid = threadIdx.x;
    int rep = tid >> 7, ky = (tid >> 4) & 7, tx = tid & 15;
    __shared__ float sW[80 * 68];       // [n][dd] pitch 68
    __shared__ float sP[64 * KK];       // [dd][k], k contiguous

    float acc[2][5];
    #pragma unroll
    for (int kk = 0; kk < 2; kk++)
        #pragma unroll
        for (int i = 0; i < 5; i++) acc[kk][i] = 0.f;

    #pragma unroll
    for (int it = 0; it < 3; it++) {
        int d0 = dh * 192 + it * 64;
        for (int idx = tid; idx < 80 * 16; idx += 256) {
            int n = idx >> 4, dq = idx & 15;
            float4 v = (n < NN) ? *(const float4*)(w + (size_t)(b * NN + n) * DD + d0 + dq * 4)
                                : make_float4(0.f, 0.f, 0.f, 0.f);
            *(float4*)&sW[n * 68 + dq * 4] = v;
        }
        for (int idx = tid; idx < 64 * KK; idx += 256)
            sP[idx] = g_Pt[(size_t)d0 * KK + idx];
        __syncthreads();
        int ddbase = rep * 32;
        #pragma unroll 2
        for (int dd = ddbase; dd < ddbase + 32; dd += 4) {
            float2 pp0 = *(const float2*)&sP[(dd + 0) * KK + 2 * ky];
            float2 pp1 = *(const float2*)&sP[(dd + 1) * KK + 2 * ky];
            float2 pp2 = *(const float2*)&sP[(dd + 2) * KK + 2 * ky];
            float2 pp3 = *(const float2*)&sP[(dd + 3) * KK + 2 * ky];
            #pragma unroll
            for (int i = 0; i < 5; i++) {
                float4 wv = *(const float4*)&sW[(tx + 16 * i) * 68 + dd];
                acc[0][i] += pp0.x * wv.x + pp1.x * wv.y + pp2.x * wv.z + pp3.x * wv.w;
                acc[1][i] += pp0.y * wv.x + pp1.y * wv.y + pp2.y * wv.z + pp3.y * wv.w;
            }
        }
        __syncthreads();
    }
    int slice = dh * 2 + rep;
    #pragma unroll
    for (int kk = 0; kk < 2; kk++) {
        float* sp = g_Sp[slice] + (size_t)b * (KK * 80) + (2 * ky + kk) * 80 + tx;
        #pragma unroll
        for (int i = 0; i < 5; i++) sp[16 * i] = acc[kk][i];
    }
}

// ---------------- kSoftmax: combine 8 partials -> softmax -> outS + rowsum
__global__ void kSoftmax(const int* __restrict__ mask, float* __restrict__ outS) {
    int b = blockIdx.x;
    int tid = threadIdx.x;   // 128
    __shared__ float sSc[KK * 80];
    __shared__ float sSm[NN * KK];
    for (int idx = tid; idx < KK * 80; idx += 128) {
        float s = 0.f;
        #pragma unroll
        for (int sl = 0; sl < 8; sl++) s += g_Sp[sl][(size_t)b * (KK * 80) + idx];
        sSc[idx] = (s + g_c[idx / 80]) * SCALE;
    }
    __syncthreads();
    if (tid < NN) {
        int n = tid;
        if (mask[b * NN + n] == 0) {
            #pragma unroll
            for (int k = 0; k < KK; k++) sSm[n * KK + k] = 1.0f / 16.0f;
        } else {
            float m = -3.4e38f;
            #pragma unroll
            for (int k = 0; k < KK; k++) m = fmaxf(m, sSc[k * 80 + n]);
            float e[KK]; float s = 0.f;
            #pragma unroll
            for (int k = 0; k < KK; k++) { e[k] = __expf(sSc[k * 80 + n] - m); s += e[k]; }
            float inv = 1.0f / s;
            #pragma unroll
            for (int k = 0; k < KK; k++) sSm[n * KK + k] = e[k] * inv;
        }
        #pragma unroll
        for (int k = 0; k < KK; k++)
            outS[(b * NN + n) * KK + k] = sSm[n * KK + k];
    }
    __syncthreads();
    if (tid < KK) {
        float s = 0.f;
        for (int n = 0; n < NN; n++) s += sSm[n * KK + tid];
        g_rowsum[b * KK + tid] = s;
    }
}

// ---------------- kU: U = S^T w, write fp16 U -> g_Abf --------------------
// grid (BB, 4), 96 threads; thread owns 2 adjacent d (float2)
__global__ void kU(const float* __restrict__ w, const float* __restrict__ S) {
    int b = blockIdx.x, dh = blockIdx.y;
    int tid = threadIdx.x;
    int d0 = dh * 192 + tid * 2;
    __shared__ float sS[NN * KK];
    for (int idx = tid; idx < NN * KK; idx += 96)
        sS[idx] = S[b * NN * KK + idx];
    __syncthreads();

    float2 acc[KK];
    #pragma unroll
    for (int k = 0; k < KK; k++) { acc[k].x = 0.f; acc[k].y = 0.f; }
    const float* wp = w + (size_t)b * NN * DD + d0;
    #pragma unroll 4
    for (int n = 0; n < NN; n++) {
        float2 wv = *(const float2*)(wp + (size_t)n * DD);
        const float* srow = sS + n * KK;
        #pragma unroll
        for (int k = 0; k < KK; k++) {
            float s = srow[k];
            acc[k].x += s * wv.x; acc[k].y += s * wv.y;
        }
    }
    #pragma unroll
    for (int k = 0; k < KK; k++) {
        __half* ur = (__half*)g_Abf + (size_t)(b * KK + k) * KH;
        *(unsigned*)(ur + d0) = packh2(acc[k].x, acc[k].y);
    }
}

// ---------------- kTGemm: mma.sync fp16 GEMM ------------------------------
// block 128x128, 8 warps as 4m x 2n (warp tile 32x64), 3-stage cp.async
// asel: 0 = g_Abf (U), 1 = g_Abf2 (V)
// wsel: 0=WbfV, 1=WbfG0, 2=WbfG1, 3=WbfE1 (ignored for mode 3)
// mode: 0 -> C=g_H; 1 -> C=g_V + fp16 V -> g_Abf2; 2 -> C=g_M (+bias);
//       3 -> merged: by<8 H=V@We1, by>=8 M=V@Wg0 (+bias)
__global__ __launch_bounds__(256, 2) void kTGemm(
    int asel, int wsel, int mode, const float* __restrict__ bias,
    const float* __restrict__ nq, const float* __restrict__ gatep)
{
    __shared__ __align__(1024) __half sA[3][128 * 32];
    __shared__ __align__(1024) __half sB[3][128 * 32];

    const __half* Ag = (const __half*)(asel ? g_Abf2 : g_Abf);
    const int m0 = blockIdx.x * 128;
    int n0 = blockIdx.y * 128;
    const __half* Bg;
    float* C; int Ncols; int emode = mode;
    if (mode == 3) {
        if (blockIdx.y < 8) {
            Bg = (const __half*)g_WbfE1; C = g_H; Ncols = 2 * HID; emode = 0;
        } else {
            n0 = (blockIdx.y - 8) * 128;
            Bg = (const __half*)g_WbfG0; C = g_M; Ncols = DN; emode = 2;
        }
    } else {
        const uint4* B4 = (wsel == 0) ? g_WbfV : (wsel == 1) ? g_WbfG0
                        : (wsel == 2) ? g_WbfG1 : g_WbfE1;
        Bg = (const __half*)B4;
        if (mode == 0)      { C = g_H; Ncols = 2 * HID; }
        else if (mode == 1) { C = g_V; Ncols = DN; }
        else                { C = g_M; Ncols = DN; }
    }

    const int tid = threadIdx.x;
    const int lane = tid & 31, warp = tid >> 5;
    const int wm = warp >> 1, wn = warp & 1;   // 4m x 2n warps, warp tile 32x64

    const uint32_t sAu = smem_u32(sA), sBu = smem_u32(sB);

    uint32_t soff[2];
    const __half* gA[2];
    const __half* gB[2];
    #pragma unroll
    for (int i = 0; i < 2; i++) {
        int v = tid * 2 + i, row = v >> 2, q = v & 3;
        soff[i] = row * 64 + ((q ^ ((row >> 1) & 3)) << 4);
        gA[i] = Ag + (size_t)(m0 + row) * KH + q * 8;
        gB[i] = Bg + (size_t)(n0 + row) * KH + q * 8;
    }

    const int r16 = lane & 15, hh = lane >> 4;
    uint32_t aoff[2][2], boff[2][4];
    #pragma unroll
    for (int s = 0; s < 2; s++) {
        int quad = 2 * s + hh;
        #pragma unroll
        for (int mt = 0; mt < 2; mt++) {
            int row = wm * 32 + mt * 16 + r16;
            aoff[s][mt] = row * 64 + ((quad ^ ((row >> 1) & 3)) << 4);
        }
        #pragma unroll
        for (int nb = 0; nb < 4; nb++) {
            int row = wn * 64 + nb * 16 + r16;
            boff[s][nb] = row * 64 + ((quad ^ ((row >> 1) & 3)) << 4);
        }
    }

    float acc[2][8][4];
    #pragma unroll
    for (int a = 0; a < 2; a++)
        #pragma unroll
        for (int b = 0; b < 8; b++)
            #pragma unroll
            for (int r = 0; r < 4; r++) acc[a][b][r] = 0.f;

    #pragma unroll
    for (int st = 0; st < 2; st++) {
        uint32_t da = sAu + st * 8192, db = sBu + st * 8192;
        #pragma unroll
        for (int i = 0; i < 2; i++) {
            asm volatile("cp.async.ca.shared.global [%0], [%1], 16;"
                         :: "r"(da + soff[i]), "l"(gA[i] + st * 32));
            asm volatile("cp.async.ca.shared.global [%0], [%1], 16;"
                         :: "r"(db + soff[i]), "l"(gB[i] + st * 32));
        }
        asm volatile("cp.async.commit_group;");
    }

    for (int c = 0; c < KCH; c++) {
        const int buf = c % 3;
        if (c + 1 < KCH) asm volatile("cp.async.wait_group 1;");
        else             asm volatile("cp.async.wait_group 0;");
        __syncthreads();
        if (c + 2 < KCH) {
            const int wb = (c + 2) % 3;
            const uint32_t da = sAu + wb * 8192, db = sBu + wb * 8192;
            #pragma unroll
            for (int i = 0; i < 2; i++) {
                asm volatile("cp.async.ca.shared.global [%0], [%1], 16;"
                             :: "r"(da + soff[i]), "l"(gA[i] + (c + 2) * 32));
                asm volatile("cp.async.ca.shared.global [%0], [%1], 16;"
                             :: "r"(db + soff[i]), "l"(gB[i] + (c + 2) * 32));
            }
            asm volatile("cp.async.commit_group;");
        }

        const uint32_t baseA = sAu + buf * 8192;
        const uint32_t baseB = sBu + buf * 8192;
        #pragma unroll
        for (int s = 0; s < 2; s++) {
            uint32_t afr[2][4];
            #pragma unroll
            for (int mt = 0; mt < 2; mt++) {
                asm volatile("ldmatrix.sync.aligned.m8n8.x4.shared.b16 "
                             "{%0,%1,%2,%3}, [%4];"
                             : "=r"(afr[mt][0]), "=r"(afr[mt][1]),
                               "=r"(afr[mt][2]), "=r"(afr[mt][3])
                             : "r"(baseA + aoff[s][mt]));
            }
            uint32_t bfr[8][2];
            #pragma unroll
            for (int nb = 0; nb < 4; nb++) {
                uint32_t r0, r1, r2, r3;
                asm volatile("ldmatrix.sync.aligned.m8n8.x4.shared.b16 "
                             "{%0,%1,%2,%3}, [%4];"
                             : "=r"(r0), "=r"(r1), "=r"(r2), "=r"(r3)
                             : "r"(baseB + boff[s][nb]));
                bfr[nb * 2][0] = r0;     bfr[nb * 2][1] = r2;
                bfr[nb * 2 + 1][0] = r1; bfr[nb * 2 + 1][1] = r3;
            }
            #pragma unroll
            for (int mt = 0; mt < 2; mt++)
                #pragma unroll
                for (int nt = 0; nt < 8; nt++) {
                    asm volatile(
                        "mma.sync.aligned.m16n8k16.row.col.f32.f16.f16.f32 "
                        "{%0,%1,%2,%3}, {%4,%5,%6,%7}, {%8,%9}, {%0,%1,%2,%3};"
                        : "+f"(acc[mt][nt][0]), "+f"(acc[mt][nt][1]),
                          "+f"(acc[mt][nt][2]), "+f"(acc[mt][nt][3])
                        : "r"(afr[mt][0]), "r"(afr[mt][1]),
                          "r"(afr[mt][2]), "r"(afr[mt][3]),
                          "r"(bfr[nt][0]), "r"(bfr[nt][1]));
                }
        }
    }

    float gate = 0.f, omg = 1.f;
    if (emode == 1) {
        gate = 1.0f / (1.0f + expf(-gatep[0]));
        omg = 1.0f - gate;
    }
    #pragma unroll
    for (int mt = 0; mt < 2; mt++) {
        #pragma unroll
        for (int half = 0; half < 2; half++) {
            int row = m0 + wm * 32 + mt * 16 + (lane >> 2) + 8 * half;
            float rsv = 0.f; const float* nqr = nullptr;
            __half* arow2 = nullptr;
            if (emode == 1) {
                rsv = g_rowsum[row];
                nqr = nq + (size_t)(row & 15) * DN;
                arow2 = (__half*)g_Abf2 + (size_t)row * KH;
            }
            float* crow = C + (size_t)row * Ncols;
            #pragma unroll
            for (int nt = 0; nt < 8; nt++) {
                int col = n0 + wn * 64 + nt * 8 + (lane & 3) * 2;
                float v0 = acc[mt][nt][half * 2 + 0];
                float v1 = acc[mt][nt][half * 2 + 1];
                if (emode == 1) {
                    v0 += rsv * __ldg(&bias[col]);
                    v1 += rsv * __ldg(&bias[col + 1]);
                    v0 = omg * v0 + gate * __ldg(&nqr[col]);
                    v1 = omg * v1 + gate * __ldg(&nqr[col + 1]);
                    *(unsigned*)(arow2 + col) = packh2(v0, v1);
                } else if (emode == 2) {
                    v0 += __ldg(&bias[col]);
                    v1 += __ldg(&bias[col + 1]);
                }
                float2 o; o.x = v0; o.y = v1;
                *(float2*)(crow + col) = o;
            }
        }
    }
}

// ---------------- kEdgeP: partial edge logits over one 256-h chunk --------
__global__ void kEdgeP(const float* __restrict__ be1, const float* __restrict__ We2) {
    int b = blockIdx.x;
    int h0 = blockIdx.y * 256;
    int tid = threadIdx.x;
    int i = tid >> 4, j = tid & 15;
    __shared__ float sHi[KK * 257];
    __shared__ float sHj[KK * 257];
    __shared__ float sW2[256];

    for (int idx = tid; idx < KK * 256; idx += 256) {
        int r = idx >> 8, c = idx & 255;
        sHi[r * 257 + c] = g_H[(size_t)(b * KK + r) * (2 * HID) + h0 + c] + be1[h0 + c];
        sHj[r * 257 + c] = g_H[(size_t)(b * KK + r) * (2 * HID) + HID + h0 + c];
    }
    sW2[tid] = We2[h0 + tid];
    __syncthreads();
    const float* hi = sHi + i * 257;
    const float* hj = sHj + j * 257;
    float a0 = 0.f, a1 = 0.f, a2 = 0.f, a3 = 0.f;
    #pragma unroll 4
    for (int c = 0; c < 256; c += 4) {
        a0 += fmaxf(hi[c]     + hj[c],     0.f) * sW2[c];
        a1 += fmaxf(hi[c + 1] + hj[c + 1], 0.f) * sW2[c + 1];
        a2 += fmaxf(hi[c + 2] + hj[c + 2], 0.f) * sW2[c + 2];
        a3 += fmaxf(hi[c + 3] + hj[c + 3], 0.f) * sW2[c + 3];
    }
    g_Ep[blockIdx.y][b * 256 + tid] = (a0 + a1) + (a2 + a3);
}

// ---------------- kEdgeR: combine partials -> softmax(A) or outE ----------
__global__ void kEdgeR(const float* __restrict__ be2, float* __restrict__ outE,
                       int post) {
    int b = blockIdx.x;
    int tid = threadIdx.x;
    int i = tid >> 4;
    __shared__ float sE[KK * 17];
    float E = g_Ep[0][b * 256 + tid] + g_Ep[1][b * 256 + tid] + be2[0];
    if (post) {
        outE[b * 256 + tid] = E;
    } else {
        sE[i * 17 + (tid & 15)] = E;
        __syncthreads();
        float m = -3.4e38f;
        #pragma unroll
        for (int jj = 0; jj < KK; jj++) m = fmaxf(m, sE[i * 17 + jj]);
        float s = 0.f;
        #pragma unroll
        for (int jj = 0; jj < KK; jj++) s += __expf(sE[i * 17 + jj] - m);
        g_A[b * 256 + tid] = __expf(E - m) / s;
    }
}

// ---------------- kMsg: V += relu(A @ M), write fp16 V (+optional outV) ---
__global__ void kMsg(float* __restrict__ outV) {
    int b = blockIdx.x;
    int tid = threadIdx.x;
    __shared__ float sAm[KK * 17];
    sAm[(tid >> 4) * 17 + (tid & 15)] = g_A[b * 256 + tid];
    __syncthreads();
    float acc[KK][3];
    #pragma unroll
    for (int i = 0; i < KK; i++) { acc[i][0] = 0.f; acc[i][1] = 0.f; acc[i][2] = 0.f; }
    for (int j = 0; j < KK; j++) {
        const float* mr = g_M + (size_t)(b * KK + j) * DN + tid;
        float m0 = mr[0], m1 = mr[256], m2 = mr[512];
        #pragma unroll
        for (int i = 0; i < KK; i++) {
            float a = sAm[i * 17 + j];
            acc[i][0] += a * m0; acc[i][1] += a * m1; acc[i][2] += a * m2;
        }
    }
    #pragma unroll
    for (int i = 0; i < KK; i++) {
        int row = b * KK + i;
        float* vr = g_V + (size_t)row * DN;
        __half* ar = (__half*)g_Abf2 + (size_t)row * KH;
        float* ovr = outV ? (outV + (size_t)row * DN) : nullptr;
        #pragma unroll
        for (int c3 = 0; c3 < 3; c3++) {
            int d = tid + c3 * 256;
            float nv = vr[d] + fmaxf(acc[i][c3], 0.f);
            vr[d] = nv;
            ar[d] = __float2half_rn(nv);
            if (ovr) ovr[d] = nv;
        }
    }
}

// ---------------- host ----------------------------------------------------
extern "C" void kernel_launch(void* const* d_in, const int* in_sizes, int n_in,
                              void* d_out, int out_size) {
    const float* w    = (const float*)d_in[0];
    const int*   mask = (const int*)  d_in[1];
    const float* nq   = (const float*)d_in[2];
    const float* Wq   = (const float*)d_in[3];
    const float* bq   = (const float*)d_in[4];
    const float* Wk   = (const float*)d_in[5];
    const float* bk   = (const float*)d_in[6];
    const float* Wv   = (const float*)d_in[7];
    const float* bv   = (const float*)d_in[8];
    const float* We1  = (const float*)d_in[9];
    const float* be1  = (const float*)d_in[10];
    const float* We2  = (const float*)d_in[11];
    const float* be2  = (const float*)d_in[12];
    const float* fg   = (const float*)d_in[13];
    const float* Wg   = (const float*)d_in[14];
    const float* bg   = (const float*)d_in[15];

    float* outS = (float*)d_out;
    float* outV = outS + (size_t)BB * NN * KK;
    float* outE = outV + (size_t)BB * KK * DN;

    kSplitAllW<<<1248, 256>>>(Wv, Wg, We1);
    kQ<<<dim3(3, 8), 256>>>(nq, Wq);
    kP<<<96, 256>>>(Wk, bk, bq);
    kScoreP<<<dim3(BB, 4), 256>>>(w);
    kSoftmax<<<BB, 128>>>(mask, outS);
    kU<<<dim3(BB, 4), 96>>>(w, outS);                          // fp16 U -> g_Abf

    kTGemm<<<dim3(32, 6), 256>>>(0, 0, 1, bv, nq, fg);         // V = U@Wv; fp16 V -> Abf2
    kTGemm<<<dim3(32, 14), 256>>>(1, 0, 3, bg, nullptr, nullptr);   // H = V@We1 AND M = V@Wg0+bg0
    kEdgeP<<<dim3(BB, 2), 256>>>(be1, We2);                    // partial E
    kEdgeR<<<BB, 256>>>(be2, nullptr, 0);                      // A = softmax(E)
    kMsg<<<BB, 256>>>(nullptr);                                // V += relu(A@M); Abf2
    kTGemm<<<dim3(32, 6), 256>>>(1, 2, 2, bg + DN, nullptr, nullptr); // M = V@Wg1+bg1
    kMsg<<<BB, 256>>>(outV);                                   // final V; Abf2; outV
    kTGemm<<<dim3(32, 8), 256>>>(1, 3, 0, nullptr, nullptr, nullptr); // H on final V
    kEdgeP<<<dim3(BB, 2), 256>>>(be1, We2);                    // partial E (final V)
    kEdgeR<<<BB, 256>>>(be2, outE, 1);                         // E -> out
}

// round 12
// speedup vs baseline: 3.7648x; 1.0589x over previous
#include <cuda_runtime.h>
#include <cuda_bf16.h>
#include <cuda_fp16.h>
#include <math.h>
#include <stdint.h>

// Problem dims
#define BB 256
#define NN 77
#define DD 768
#define KK 16
#define DN 768
#define HID 512
#define MTOT (BB*KK)          // 4096
#define SCALE 0.10206207261596575f   // (768/8)^-0.5
#define KH 768                // GEMM K (fp16 single-term)
#define KCH 24                // 768/32 chunks
#define MSC (BB*NN)           // 19712 score rows = 154*128

// ---------------- scratch (device globals; no allocation) ----------------
__device__ float g_Qp[8][KK*DN];
__device__ float g_c[KK];
__device__ float g_Sc[(size_t)MSC*KK];   // raw scores [m][k]
__device__ float g_Ep[2][BB*256];        // partial edge logits
__device__ float g_V[MTOT*DN];
__device__ float g_rowsum[MTOT];
__device__ float g_H[MTOT*2*HID];
__device__ float g_M[MTOT*DN];
__device__ float g_A[BB*KK*KK];
// fp16 operand buffers (uint4 for 16B alignment)
__device__ uint4 g_wh [(size_t)MSC*DD/8];     // fp16 copy of w
__device__ uint4 g_Pth[KK*DN/8];              // fp16 P, node-major [16][768]
__device__ uint4 g_Abf [(size_t)MTOT*KH/8];   // fp16 U
__device__ uint4 g_Abf2[(size_t)MTOT*KH/8];   // fp16 V
__device__ uint4 g_WbfV [768*KH/8];
__device__ uint4 g_WbfG0[768*KH/8];
__device__ uint4 g_WbfG1[768*KH/8];
__device__ uint4 g_WbfE1[1024*KH/8];

__device__ __forceinline__ uint32_t smem_u32(const void* p) {
    uint32_t a;
    asm("{ .reg .u64 t; cvta.to.shared.u64 t, %1; cvt.u32.u64 %0, t; }"
        : "=r"(a) : "l"(p));
    return a;
}

__device__ __forceinline__ unsigned packh2(float a, float b) {
    __half2 h = __floats2half2_rn(a, b);
    return *(unsigned*)&h;
}

// ---------------- kWh: w -> fp16 ------------------------------------------
__global__ void kWh(const float* __restrict__ w) {
    size_t idx = (size_t)blockIdx.x * 256 + threadIdx.x;   // 1,892,352 uint4s
    const float4* s = (const float4*)w + idx * 2;
    float4 a = s[0], b = s[1];
    uint4 o;
    o.x = packh2(a.x, a.y); o.y = packh2(a.z, a.w);
    o.z = packh2(b.x, b.y); o.w = packh2(b.z, b.w);
    g_wh[idx] = o;
}

// ---------------- kQ: partial Q = nq @ Wq (Wq read once) ------------------
__global__ void kQ(const float* __restrict__ nq, const float* __restrict__ Wq) {
    int d = blockIdx.x * 256 + threadIdx.x;
    int sl = blockIdx.y;
    int e0 = sl * 96;
    __shared__ float snq[KK][96];
    for (int idx = threadIdx.x; idx < KK * 96; idx += 256)
        snq[idx / 96][idx % 96] = nq[(idx / 96) * DN + e0 + idx % 96];
    __syncthreads();
    float acc[KK];
    #pragma unroll
    for (int k = 0; k < KK; k++) acc[k] = 0.f;
    const float* wp = Wq + (size_t)e0 * DN + d;
    #pragma unroll 4
    for (int e = 0; e < 96; e++) {
        float wv = wp[(size_t)e * DN];
        #pragma unroll
        for (int k = 0; k < KK; k++) acc[k] += snq[k][e] * wv;
    }
    #pragma unroll
    for (int k = 0; k < KK; k++) g_Qp[sl][k * DN + d] = acc[k];
}

// ---------------- kP: P[k][j] = Wk[j,:].Q[k,:]; fp16 node-major out -------
__global__ void kP(const float* __restrict__ Wk, const float* __restrict__ bk,
                   const float* __restrict__ bq) {
    __shared__ float sQ[KK][DN];   // 48 KB
    int tid = threadIdx.x;
    int lane = tid & 31, warp = tid >> 5;
    for (int idx = tid; idx < KK * DN; idx += 256) {
        float s = bq[idx % DN];
        #pragma unroll
        for (int sl = 0; sl < 8; sl++) s += g_Qp[sl][idx];
        sQ[idx / DN][idx % DN] = s;
    }
    __syncthreads();

    int j = blockIdx.x * 8 + warp;
    const float4* wr = (const float4*)(Wk + (size_t)j * DN);
    float acc[KK];
    #pragma unroll
    for (int k = 0; k < KK; k++) acc[k] = 0.f;
    #pragma unroll
    for (int it = 0; it < 6; it++) {
        int e = it * 128 + lane * 4;
        float4 wv = wr[it * 32 + lane];
        #pragma unroll
        for (int k = 0; k < KK; k++) {
            float4 qv = *(const float4*)&sQ[k][e];
            acc[k] += wv.x * qv.x + wv.y * qv.y + wv.z * qv.z + wv.w * qv.w;
        }
    }
    float out = 0.f;
    #pragma unroll
    for (int k = 0; k < KK; k++) {
        float v = acc[k];
        v += __shfl_xor_sync(0xFFFFFFFFu, v, 16);
        v += __shfl_xor_sync(0xFFFFFFFFu, v, 8);
        v += __shfl_xor_sync(0xFFFFFFFFu, v, 4);
        v += __shfl_xor_sync(0xFFFFFFFFu, v, 2);
        v += __shfl_xor_sync(0xFFFFFFFFu, v, 1);
        if (lane == k) out = v;
    }
    if (lane < KK)
        ((__half*)g_Pth)[lane * DN + j] = __float2half_rn(out);

    if (blockIdx.x >= 94) {
        int k = (blockIdx.x - 94) * 8 + warp;
        float cc = 0.f;
        #pragma unroll
        for (int it = 0; it < 6; it++) {
            int e = it * 128 + lane * 4;
            float4 bv = *(const float4*)(bk + e);
            float4 qv = *(const float4*)&sQ[k][e];
            cc += bv.x * qv.x + bv.y * qv.y + bv.z * qv.z + bv.w * qv.w;
        }
        cc += __shfl_xor_sync(0xFFFFFFFFu, cc, 16);
        cc += __shfl_xor_sync(0xFFFFFFFFu, cc, 8);
        cc += __shfl_xor_sync(0xFFFFFFFFu, cc, 4);
        cc += __shfl_xor_sync(0xFFFFFFFFu, cc, 2);
        cc += __shfl_xor_sync(0xFFFFFFFFu, cc, 1);
        if (lane == 0) g_c[k] = cc;
    }
}

// ---------------- kSplitAllW: all 4 weight conversions, one launch -------
__global__ void kSplitAllW(const float* __restrict__ Wv,
                           const float* __restrict__ Wg,
                           const float* __restrict__ We1) {
    int sid = blockIdx.x * 256 + threadIdx.x;   // 0..319487
    float a[8];
    __half* out;
    int e0;
    if (sid < 221184) {
        int job = sid / 73728, s = sid % 73728;
        int n = s % 768, seg = s / 768;
        e0 = seg * 8;
        const float* Wp = (job == 0) ? Wv : (job == 1) ? Wg : (Wg + 768 * 768);
        uint4* o4 = (job == 0) ? g_WbfV : (job == 1) ? g_WbfG0 : g_WbfG1;
        out = (__half*)o4 + (size_t)n * KH;
        #pragma unroll
        for (int i = 0; i < 8; i++) a[i] = Wp[(size_t)(e0 + i) * 768 + n];
    } else {
        int s = sid - 221184;
        int n = s % 1024, seg = s / 1024;
        e0 = seg * 8;
        out = (__half*)g_WbfE1 + (size_t)n * KH;
        size_t base = (n < HID) ? (size_t)n : ((size_t)768 * HID + (n - HID));
        #pragma unroll
        for (int i = 0; i < 8; i++) a[i] = We1[base + (size_t)(e0 + i) * HID];
    }
    unsigned h[4];
    #pragma unroll
    for (int i = 0; i < 4; i++) h[i] = packh2(a[2 * i], a[2 * i + 1]);
    *(uint4*)(out + e0) = *(uint4*)h;
}

// ---------------- kScoreG: scores = wh @ Pth^T, tensor cores --------------
// grid 154, block 256 (8 warps); tile 128 x 16, K=768
__global__ __launch_bounds__(256, 2) void kScoreG() {
    __shared__ __align__(1024) __half sB[16 * 768];     // 24 KB, resident
    __shared__ __align__(1024) __half sA[3][128 * 32];  // 24 KB, 3-stage

    const __half* Ag = (const __half*)g_wh;
    const int m0 = blockIdx.x * 128;
    const int tid = threadIdx.x;
    const int lane = tid & 31, warp = tid >> 5;
    const uint32_t sAu = smem_u32(sA), sBu = smem_u32(sB);

    // load full B (16 nodes x 768) with unit-XOR swizzle
    for (int idx = tid; idx < 16 * 96; idx += 256) {
        int r = idx / 96, u = idx % 96;
        uint4 v = g_Pth[r * 96 + u];
        *(uint4*)((char*)sB + r * 1536 + ((u ^ (r & 7)) << 4)) = v;
    }

    // A staging slots (2 x 16B per thread per chunk)
    uint32_t soff[2];
    const __half* gA[2];
    #pragma unroll
    for (int i = 0; i < 2; i++) {
        int v = tid * 2 + i, row = v >> 2, q = v & 3;
        soff[i] = row * 64 + ((q ^ ((row >> 1) & 3)) << 4);
        gA[i] = Ag + (size_t)(m0 + row) * KH + q * 8;
    }

    const int r16 = lane & 15, hh = lane >> 4;
    uint32_t aoff[2];
    #pragma unroll
    for (int s = 0; s < 2; s++) {
        int quad = 2 * s + hh;
        int row = warp * 16 + r16;
        aoff[s] = row * 64 + ((quad ^ ((row >> 1) & 3)) << 4);
    }

    float acc[2][4];
    #pragma unroll
    for (int b = 0; b < 2; b++)
        #pragma unroll
        for (int r = 0; r < 4; r++) acc[b][r] = 0.f;

    #pragma unroll
    for (int st = 0; st < 2; st++) {
        uint32_t da = sAu + st * 8192;
        #pragma unroll
        for (int i = 0; i < 2; i++)
            asm volatile("cp.async.ca.shared.global [%0], [%1], 16;"
                         :: "r"(da + soff[i]), "l"(gA[i] + st * 32));
        asm volatile("cp.async.commit_group;");
    }
    __syncthreads();   // B visible

    for (int c = 0; c < KCH; c++) {
        const int buf = c % 3;
        if (c + 1 < KCH) asm volatile("cp.async.wait_group 1;");
        else             asm volatile("cp.async.wait_group 0;");
        __syncthreads();
        if (c + 2 < KCH) {
            const uint32_t da = sAu + ((c + 2) % 3) * 8192;
            #pragma unroll
            for (int i = 0; i < 2; i++)
                asm volatile("cp.async.ca.shared.global [%0], [%1], 16;"
                             :: "r"(da + soff[i]), "l"(gA[i] + (c + 2) * 32));
            asm volatile("cp.async.commit_group;");
        }

        const uint32_t baseA = sAu + buf * 8192;
        #pragma unroll
        for (int s = 0; s < 2; s++) {
            uint32_t afr[4];
            asm volatile("ldmatrix.sync.aligned.m8n8.x4.shared.b16 "
                         "{%0,%1,%2,%3}, [%4];"
                         : "=r"(afr[0]), "=r"(afr[1]), "=r"(afr[2]), "=r"(afr[3])
                         : "r"(baseA + aoff[s]));
            int u = c * 4 + s * 2 + hh;
            uint32_t baddr = sBu + r16 * 1536 + (((u) ^ (r16 & 7)) << 4);
            uint32_t r0, r1, r2, r3;
            asm volatile("ldmatrix.sync.aligned.m8n8.x4.shared.b16 "
                         "{%0,%1,%2,%3}, [%4];"
                         : "=r"(r0), "=r"(r1), "=r"(r2), "=r"(r3) : "r"(baddr));
            uint32_t bfr[2][2];
            bfr[0][0] = r0; bfr[0][1] = r2;
            bfr[1][0] = r1; bfr[1][1] = r3;
            #pragma unroll
            for (int nt = 0; nt < 2; nt++) {
                asm volatile(
                    "mma.sync.aligned.m16n8k16.row.col.f32.f16.f16.f32 "
                    "{%0,%1,%2,%3}, {%4,%5,%6,%7}, {%8,%9}, {%0,%1,%2,%3};"
                    : "+f"(acc[nt][0]), "+f"(acc[nt][1]),
                      "+f"(acc[nt][2]), "+f"(acc[nt][3])
                    : "r"(afr[0]), "r"(afr[1]), "r"(afr[2]), "r"(afr[3]),
                      "r"(bfr[nt][0]), "r"(bfr[nt][1]));
            }
        }
    }

    #pragma unroll
    for (int half = 0; half < 2; half++) {
        int row = m0 + warp * 16 + (lane >> 2) + 8 * half;
        float* crow = g_Sc + (size_t)row * KK;
        #pragma unroll
        for (int nt = 0; nt < 2; nt++) {
            int col = nt * 8 + (lane & 3) * 2;
            crow[col]     = acc[nt][half * 2 + 0];
            crow[col + 1] = acc[nt][half * 2 + 1];
        }
    }
}

// ---------------- kSoftmax: g_Sc -> softmax -> outS + rowsum --------------
__global__ void kSoftmax(const int* __restrict__ mask, float* __restrict__ outS) {
    int b = blockIdx.x;
    int tid = threadIdx.x;   // 128
    __shared__ float sSm[NN * KK];
    __shared__ float sC[KK];
    if (tid < KK) sC[tid] = g_c[tid];
    __syncthreads();
    if (tid < NN) {
        int n = tid;
        float v[KK];
        const float4* src = (const float4*)(g_Sc + (size_t)(b * NN + n) * KK);
        #pragma unroll
        for (int q = 0; q < 4; q++) *(float4*)&v[q * 4] = src[q];
        if (mask[b * NN + n] == 0) {
            #pragma unroll
            for (int k = 0; k < KK; k++) sSm[n * KK + k] = 1.0f / 16.0f;
        } else {
            float sc[KK]; float m = -3.4e38f;
            #pragma unroll
            for (int k = 0; k < KK; k++) { sc[k] = (v[k] + sC[k]) * SCALE; m = fmaxf(m, sc[k]); }
            float e[KK]; float s = 0.f;
            #pragma unroll
            for (int k = 0; k < KK; k++) { e[k] = __expf(sc[k] - m); s += e[k]; }
            float inv = 1.0f / s;
            #pragma unroll
            for (int k = 0; k < KK; k++) sSm[n * KK + k] = e[k] * inv;
        }
        float4* dst = (float4*)(outS + (size_t)(b * NN + n) * KK);
        #pragma unroll
        for (int q = 0; q < 4; q++) dst[q] = *(float4*)&sSm[n * KK + q * 4];
    }
    __syncthreads();
    if (tid < KK) {
        float s = 0.f;
        for (int n = 0; n < NN; n++) s += sSm[n * KK + tid];
        g_rowsum[b * KK + tid] = s;
    }
}

// ---------------- kU: U = S^T w (fp16 w), write fp16 U -> g_Abf -----------
__global__ void kU(const float* __restrict__ S) {
    int b = blockIdx.x, dh = blockIdx.y;
    int tid = threadIdx.x;
    int d0 = dh * 192 + tid * 2;
    __shared__ float sS[NN * KK];
    for (int idx = tid; idx < NN * KK; idx += 96)
        sS[idx] = S[b * NN * KK + idx];
    __syncthreads();

    float2 acc[KK];
    #pragma unroll
    for (int k = 0; k < KK; k++) { acc[k].x = 0.f; acc[k].y = 0.f; }
    const __half* wp = (const __half*)g_wh + (size_t)b * NN * DD + d0;
    #pragma unroll 4
    for (int n = 0; n < NN; n++) {
        __half2 hv = *(const __half2*)(wp + (size_t)n * DD);
        float2 wv = __half22float2(hv);
        const float* srow = sS + n * KK;
        #pragma unroll
        for (int k = 0; k < KK; k++) {
            float s = srow[k];
            acc[k].x += s * wv.x; acc[k].y += s * wv.y;
        }
    }
    #pragma unroll
    for (int k = 0; k < KK; k++) {
        __half* ur = (__half*)g_Abf + (size_t)(b * KK + k) * KH;
        *(unsigned*)(ur + d0) = packh2(acc[k].x, acc[k].y);
    }
}

// ---------------- kTGemm: mma.sync fp16 GEMM ------------------------------
// block 128x128, 8 warps as 4m x 2n (warp tile 32x64), 3-stage cp.async
__global__ __launch_bounds__(256, 2) void kTGemm(
    int asel, int wsel, int mode, const float* __restrict__ bias,
    const float* __restrict__ nq, const float* __restrict__ gatep)
{
    __shared__ __align__(1024) __half sA[3][128 * 32];
    __shared__ __align__(1024) __half sB[3][128 * 32];

    const __half* Ag = (const __half*)(asel ? g_Abf2 : g_Abf);
    const int m0 = blockIdx.x * 128;
    int n0 = blockIdx.y * 128;
    const __half* Bg;
    float* C; int Ncols; int emode = mode;
    if (mode == 3) {
        if (blockIdx.y < 8) {
            Bg = (const __half*)g_WbfE1; C = g_H; Ncols = 2 * HID; emode = 0;
        } else {
            n0 = (blockIdx.y - 8) * 128;
            Bg = (const __half*)g_WbfG0; C = g_M; Ncols = DN; emode = 2;
        }
    } else {
        const uint4* B4 = (wsel == 0) ? g_WbfV : (wsel == 1) ? g_WbfG0
                        : (wsel == 2) ? g_WbfG1 : g_WbfE1;
        Bg = (const __half*)B4;
        if (mode == 0)      { C = g_H; Ncols = 2 * HID; }
        else if (mode == 1) { C = g_V; Ncols = DN; }
        else                { C = g_M; Ncols = DN; }
    }

    const int tid = threadIdx.x;
    const int lane = tid & 31, warp = tid >> 5;
    const int wm = warp >> 1, wn = warp & 1;

    const uint32_t sAu = smem_u32(sA), sBu = smem_u32(sB);

    uint32_t soff[2];
    const __half* gA[2];
    const __half* gB[2];
    #pragma unroll
    for (int i = 0; i < 2; i++) {
        int v = tid * 2 + i, row = v >> 2, q = v & 3;
        soff[i] = row * 64 + ((q ^ ((row >> 1) & 3)) << 4);
        gA[i] = Ag + (size_t)(m0 + row) * KH + q * 8;
        gB[i] = Bg + (size_t)(n0 + row) * KH + q * 8;
    }

    const int r16 = lane & 15, hh = lane >> 4;
    uint32_t aoff[2][2], boff[2][4];
    #pragma unroll
    for (int s = 0; s < 2; s++) {
        int quad = 2 * s + hh;
        #pragma unroll
        for (int mt = 0; mt < 2; mt++) {
            int row = wm * 32 + mt * 16 + r16;
            aoff[s][mt] = row * 64 + ((quad ^ ((row >> 1) & 3)) << 4);
        }
        #pragma unroll
        for (int nb = 0; nb < 4; nb++) {
            int row = wn * 64 + nb * 16 + r16;
            boff[s][nb] = row * 64 + ((quad ^ ((row >> 1) & 3)) << 4);
        }
    }

    float acc[2][8][4];
    #pragma unroll
    for (int a = 0; a < 2; a++)
        #pragma unroll
        for (int b = 0; b < 8; b++)
            #pragma unroll
            for (int r = 0; r < 4; r++) acc[a][b][r] = 0.f;

    #pragma unroll
    for (int st = 0; st < 2; st++) {
        uint32_t da = sAu + st * 8192, db = sBu + st * 8192;
        #pragma unroll
        for (int i = 0; i < 2; i++) {
            asm volatile("cp.async.ca.shared.global [%0], [%1], 16;"
                         :: "r"(da + soff[i]), "l"(gA[i] + st * 32));
            asm volatile("cp.async.ca.shared.global [%0], [%1], 16;"
                         :: "r"(db + soff[i]), "l"(gB[i] + st * 32));
        }
        asm volatile("cp.async.commit_group;");
    }

    for (int c = 0; c < KCH; c++) {
        const int buf = c % 3;
        if (c + 1 < KCH) asm volatile("cp.async.wait_group 1;");
        else             asm volatile("cp.async.wait_group 0;");
        __syncthreads();
        if (c + 2 < KCH) {
            const int wb = (c + 2) % 3;
            const uint32_t da = sAu + wb * 8192, db = sBu + wb * 8192;
            #pragma unroll
            for (int i = 0; i < 2; i++) {
                asm volatile("cp.async.ca.shared.global [%0], [%1], 16;"
                             :: "r"(da + soff[i]), "l"(gA[i] + (c + 2) * 32));
                asm volatile("cp.async.ca.shared.global [%0], [%1], 16;"
                             :: "r"(db + soff[i]), "l"(gB[i] + (c + 2) * 32));
            }
            asm volatile("cp.async.commit_group;");
        }

        const uint32_t baseA = sAu + buf * 8192;
        const uint32_t baseB = sBu + buf * 8192;
        #pragma unroll
        for (int s = 0; s < 2; s++) {
            uint32_t afr[2][4];
            #pragma unroll
            for (int mt = 0; mt < 2; mt++) {
                asm volatile("ldmatrix.sync.aligned.m8n8.x4.shared.b16 "
                             "{%0,%1,%2,%3}, [%4];"
                             : "=r"(afr[mt][0]), "=r"(afr[mt][1]),
                               "=r"(afr[mt][2]), "=r"(afr[mt][3])
                             : "r"(baseA + aoff[s][mt]));
            }
            uint32_t bfr[8][2];
            #pragma unroll
            for (int nb = 0; nb < 4; nb++) {
                uint32_t r0, r1, r2, r3;
                asm volatile("ldmatrix.sync.aligned.m8n8.x4.shared.b16 "
                             "{%0,%1,%2,%3}, [%4];"
                             : "=r"(r0), "=r"(r1), "=r"(r2), "=r"(r3)
                             : "r"(baseB + boff[s][nb]));
                bfr[nb * 2][0] = r0;     bfr[nb * 2][1] = r2;
                bfr[nb * 2 + 1][0] = r1; bfr[nb * 2 + 1][1] = r3;
            }
            #pragma unroll
            for (int mt = 0; mt < 2; mt++)
                #pragma unroll
                for (int nt = 0; nt < 8; nt++) {
                    asm volatile(
                        "mma.sync.aligned.m16n8k16.row.col.f32.f16.f16.f32 "
                        "{%0,%1,%2,%3}, {%4,%5,%6,%7}, {%8,%9}, {%0,%1,%2,%3};"
                        : "+f"(acc[mt][nt][0]), "+f"(acc[mt][nt][1]),
                          "+f"(acc[mt][nt][2]), "+f"(acc[mt][nt][3])
                        : "r"(afr[mt][0]), "r"(afr[mt][1]),
                          "r"(afr[mt][2]), "r"(afr[mt][3]),
                          "r"(bfr[nt][0]), "r"(bfr[nt][1]));
                }
        }
    }

    float gate = 0.f, omg = 1.f;
    if (emode == 1) {
        gate = 1.0f / (1.0f + expf(-gatep[0]));
        omg = 1.0f - gate;
    }
    #pragma unroll
    for (int mt = 0; mt < 2; mt++) {
        #pragma unroll
        for (int half = 0; half < 2; half++) {
            int row = m0 + wm * 32 + mt * 16 + (lane >> 2) + 8 * half;
            float rsv = 0.f; const float* nqr = nullptr;
            __half* arow2 = nullptr;
            if (emode == 1) {
                rsv = g_rowsum[row];
                nqr = nq + (size_t)(row & 15) * DN;
                arow2 = (__half*)g_Abf2 + (size_t)row * KH;
            }
            float* crow = C + (size_t)row * Ncols;
            #pragma unroll
            for (int nt = 0; nt < 8; nt++) {
                int col = n0 + wn * 64 + nt * 8 + (lane & 3) * 2;
                float v0 = acc[mt][nt][half * 2 + 0];
                float v1 = acc[mt][nt][half * 2 + 1];
                if (emode == 1) {
                    v0 += rsv * __ldg(&bias[col]);
                    v1 += rsv * __ldg(&bias[col + 1]);
                    v0 = omg * v0 + gate * __ldg(&nqr[col]);
                    v1 = omg * v1 + gate * __ldg(&nqr[col + 1]);
                    *(unsigned*)(arow2 + col) = packh2(v0, v1);
                } else if (emode == 2) {
                    v0 += __ldg(&bias[col]);
                    v1 += __ldg(&bias[col + 1]);
                }
                float2 o; o.x = v0; o.y = v1;
                *(float2*)(crow + col) = o;
            }
        }
    }
}

// ---------------- kEdgeP: partial edge logits, float4 inner ---------------
__global__ void kEdgeP(const float* __restrict__ be1, const float* __restrict__ We2) {
    int b = blockIdx.x;
    int h0 = blockIdx.y * 256;
    int tid = threadIdx.x;
    int i = tid >> 4, j = tid & 15;
    __shared__ __align__(16) float sHi[KK * 260];
    __shared__ __align__(16) float sHj[KK * 260];
    __shared__ __align__(16) float sW2[256];

    for (int idx = tid; idx < KK * 256; idx += 256) {
        int r = idx >> 8, c = idx & 255;
        sHi[r * 260 + c] = g_H[(size_t)(b * KK + r) * (2 * HID) + h0 + c] + be1[h0 + c];
        sHj[r * 260 + c] = g_H[(size_t)(b * KK + r) * (2 * HID) + HID + h0 + c];
    }
    sW2[tid] = We2[h0 + tid];
    __syncthreads();
    const float* hi = sHi + i * 260;
    const float* hj = sHj + j * 260;
    float a0 = 0.f, a1 = 0.f, a2 = 0.f, a3 = 0.f;
    #pragma unroll 4
    for (int c = 0; c < 256; c += 4) {
        float4 h4 = *(const float4*)&hi[c];
        float4 g4 = *(const float4*)&hj[c];
        float4 w4 = *(const float4*)&sW2[c];
        a0 += fmaxf(h4.x + g4.x, 0.f) * w4.x;
        a1 += fmaxf(h4.y + g4.y, 0.f) * w4.y;
        a2 += fmaxf(h4.z + g4.z, 0.f) * w4.z;
        a3 += fmaxf(h4.w + g4.w, 0.f) * w4.w;
    }
    g_Ep[blockIdx.y][b * 256 + tid] = (a0 + a1) + (a2 + a3);
}

// ---------------- kEdgeR: combine partials -> softmax(A) or outE ----------
__global__ void kEdgeR(const float* __restrict__ be2, float* __restrict__ outE,
                       int post) {
    int b = blockIdx.x;
    int tid = threadIdx.x;
    int i = tid >> 4;
    __shared__ float sE[KK * 17];
    float E = g_Ep[0][b * 256 + tid] + g_Ep[1][b * 256 + tid] + be2[0];
    if (post) {
        outE[b * 256 + tid] = E;
    } else {
        sE[i * 17 + (tid & 15)] = E;
        __syncthreads();
        float m = -3.4e38f;
        #pragma unroll
        for (int jj = 0; jj < KK; jj++) m = fmaxf(m, sE[i * 17 + jj]);
        float s = 0.f;
        #pragma unroll
        for (int jj = 0; jj < KK; jj++) s += __expf(sE[i * 17 + jj] - m);
        g_A[b * 256 + tid] = __expf(E - m) / s;
    }
}

// ---------------- kMsg: V += relu(A @ M), write fp16 V (+optional outV) ---
__global__ void kMsg(float* __restrict__ outV) {
    int b = blockIdx.x;
    int tid = threadIdx.x;
    __shared__ float sAm[KK * 17];
    sAm[(tid >> 4) * 17 + (tid & 15)] = g_A[b * 256 + tid];
    __syncthreads();
    float acc[KK][3];
    #pragma unroll
    for (int i = 0; i < KK; i++) { acc[i][0] = 0.f; acc[i][1] = 0.f; acc[i][2] = 0.f; }
    for (int j = 0; j < KK; j++) {
        const float* mr = g_M + (size_t)(b * KK + j) * DN + tid;
        float m0 = mr[0], m1 = mr[256], m2 = mr[512];
        #pragma unroll
        for (int i = 0; i < KK; i++) {
            float a = sAm[i * 17 + j];
            acc[i][0] += a * m0; acc[i][1] += a * m1; acc[i][2] += a * m2;
        }
    }
    #pragma unroll
    for (int i = 0; i < KK; i++) {
        int row = b * KK + i;
        float* vr = g_V + (size_t)row * DN;
        __half* ar = (__half*)g_Abf2 + (size_t)row * KH;
        float* ovr = outV ? (outV + (size_t)row * DN) : nullptr;
        #pragma unroll
        for (int c3 = 0; c3 < 3; c3++) {
            int d = tid + c3 * 256;
            float nv = vr[d] + fmaxf(acc[i][c3], 0.f);
            vr[d] = nv;
            ar[d] = __float2half_rn(nv);
            if (ovr) ovr[d] = nv;
        }
    }
}

// ---------------- host ----------------------------------------------------
extern "C" void kernel_launch(void* const* d_in, const int* in_sizes, int n_in,
                              void* d_out, int out_size) {
    const float* w    = (const float*)d_in[0];
    const int*   mask = (const int*)  d_in[1];
    const float* nq   = (const float*)d_in[2];
    const float* Wq   = (const float*)d_in[3];
    const float* bq   = (const float*)d_in[4];
    const float* Wk   = (const float*)d_in[5];
    const float* bk   = (const float*)d_in[6];
    const float* Wv   = (const float*)d_in[7];
    const float* bv   = (const float*)d_in[8];
    const float* We1  = (const float*)d_in[9];
    const float* be1  = (const float*)d_in[10];
    const float* We2  = (const float*)d_in[11];
    const float* be2  = (const float*)d_in[12];
    const float* fg   = (const float*)d_in[13];
    const float* Wg   = (const float*)d_in[14];
    const float* bg   = (const float*)d_in[15];

    float* outS = (float*)d_out;
    float* outV = outS + (size_t)BB * NN * KK;
    float* outE = outV + (size_t)BB * KK * DN;

    kWh<<<7392, 256>>>(w);                                     // w -> fp16
    kSplitAllW<<<1248, 256>>>(Wv, Wg, We1);
    kQ<<<dim3(3, 8), 256>>>(nq, Wq);
    kP<<<96, 256>>>(Wk, bk, bq);                               // Pth fp16 + c
    kScoreG<<<154, 256>>>();                                   // scores via HMMA
    kSoftmax<<<BB, 128>>>(mask, outS);
    kU<<<dim3(BB, 4), 96>>>(outS);                             // fp16 U -> g_Abf

    kTGemm<<<dim3(32, 6), 256>>>(0, 0, 1, bv, nq, fg);         // V = U@Wv; fp16 V -> Abf2
    kTGemm<<<dim3(32, 14), 256>>>(1, 0, 3, bg, nullptr, nullptr);   // H = V@We1 AND M = V@Wg0+bg0
    kEdgeP<<<dim3(BB, 2), 256>>>(be1, We2);                    // partial E
    kEdgeR<<<BB, 256>>>(be2, nullptr, 0);                      // A = softmax(E)
    kMsg<<<BB, 256>>>(nullptr);                                // V += relu(A@M); Abf2
    kTGemm<<<dim3(32, 6), 256>>>(1, 2, 2, bg + DN, nullptr, nullptr); // M = V@Wg1+bg1
    kMsg<<<BB, 256>>>(outV);                                   // final V; Abf2; outV
    kTGemm<<<dim3(32, 8), 256>>>(1, 3, 0, nullptr, nullptr, nullptr); // H on final V
    kEdgeP<<<dim3(BB, 2), 256>>>(be1, We2);                    // partial E (final V)
    kEdgeR<<<BB, 256>>>(be2, outE, 1);                         // E -> out
}

// round 13
// speedup vs baseline: 4.0970x; 1.0882x over previous
#include <cuda_runtime.h>
#include <cuda_bf16.h>
#include <cuda_fp16.h>
#include <math.h>
#include <stdint.h>

// Problem dims
#define BB 256
#define NN 77
#define DD 768
#define KK 16
#define DN 768
#define HID 512
#define MTOT (BB*KK)          // 4096
#define SCALE 0.10206207261596575f   // (768/8)^-0.5
#define KH 768                // GEMM K (fp16 single-term)
#define KCH 24                // 768/32 chunks
#define MSC (BB*NN)           // 19712 score rows = 154*128

// ---------------- scratch (device globals; no allocation) ----------------
__device__ float g_Qp[16][KK*DN];
__device__ float g_Q[KK*DN];
__device__ float g_Pt[DD*KK];
__device__ float g_c[KK];
__device__ float g_Sc[(size_t)MSC*KK];   // raw scores [m][k]
__device__ float g_Ep[2][BB*256];        // partial edge logits
__device__ float g_V[MTOT*DN];
__device__ float g_rowsum[MTOT];
__device__ float g_H[MTOT*2*HID];
__device__ float g_M[MTOT*DN];
__device__ float g_A[BB*KK*KK];
// fp16 operand buffers (uint4 for 16B alignment)
__device__ uint4 g_wh [(size_t)MSC*DD/8];     // fp16 copy of w
__device__ uint4 g_Pth[KK*DN/8];              // fp16 P, node-major [16][768]
__device__ uint4 g_Abf [(size_t)MTOT*KH/8];   // fp16 U
__device__ uint4 g_Abf2[(size_t)MTOT*KH/8];   // fp16 V
__device__ uint4 g_WbfV [768*KH/8];
__device__ uint4 g_WbfG0[768*KH/8];
__device__ uint4 g_WbfG1[768*KH/8];
__device__ uint4 g_WbfE1[1024*KH/8];

__device__ __forceinline__ uint32_t smem_u32(const void* p) {
    uint32_t a;
    asm("{ .reg .u64 t; cvta.to.shared.u64 t, %1; cvt.u32.u64 %0, t; }"
        : "=r"(a) : "l"(p));
    return a;
}

__device__ __forceinline__ unsigned packh2(float a, float b) {
    __half2 h = __floats2half2_rn(a, b);
    return *(unsigned*)&h;
}

// ---------------- kWh: w -> fp16 ------------------------------------------
__global__ void kWh(const float* __restrict__ w) {
    size_t idx = (size_t)blockIdx.x * 256 + threadIdx.x;   // 1,892,352 uint4s
    const float4* s = (const float4*)w + idx * 2;
    float4 a = s[0], b = s[1];
    uint4 o;
    o.x = packh2(a.x, a.y); o.y = packh2(a.z, a.w);
    o.z = packh2(b.x, b.y); o.w = packh2(b.z, b.w);
    g_wh[idx] = o;
}

// ---------------- kQ: partial Q = nq @ Wq over 48-wide e-slice ------------
__global__ void kQ(const float* __restrict__ nq, const float* __restrict__ Wq) {
    int d = blockIdx.x * 256 + threadIdx.x;
    int sl = blockIdx.y;      // 0..15
    int e0 = sl * 48;
    __shared__ float snq[KK][48];
    for (int idx = threadIdx.x; idx < KK * 48; idx += 256)
        snq[idx / 48][idx % 48] = nq[(idx / 48) * DN + e0 + idx % 48];
    __syncthreads();
    float acc[KK];
    #pragma unroll
    for (int k = 0; k < KK; k++) acc[k] = 0.f;
    const float* wp = Wq + (size_t)e0 * DN + d;
    #pragma unroll 4
    for (int e = 0; e < 48; e++) {
        float wv = wp[(size_t)e * DN];
        #pragma unroll
        for (int k = 0; k < KK; k++) acc[k] += snq[k][e] * wv;
    }
    #pragma unroll
    for (int k = 0; k < KK; k++) g_Qp[sl][k * DN + d] = acc[k];
}

// ---------------- kQr: sum 16 partials + bq -> g_Q ------------------------
__global__ void kQr(const float* __restrict__ bq) {
    int i = blockIdx.x * 256 + threadIdx.x;   // 12288
    float s = bq[i % DN];
    #pragma unroll
    for (int sl = 0; sl < 16; sl++) s += g_Qp[sl][i];
    g_Q[i] = s;
}

// ---------------- kP: P^T[j][k] = Wk[j,:].Q[k,:] (warp per j) -------------
__global__ void kP(const float* __restrict__ Wk, const float* __restrict__ bk) {
    __shared__ float sQ[KK][DN];   // 48 KB
    int tid = threadIdx.x;
    int lane = tid & 31, warp = tid >> 5;
    for (int idx = tid; idx < KK * DN; idx += 256)
        sQ[idx / DN][idx % DN] = g_Q[idx];
    __syncthreads();

    int j = blockIdx.x * 8 + warp;
    const float4* wr = (const float4*)(Wk + (size_t)j * DN);
    float acc[KK];
    #pragma unroll
    for (int k = 0; k < KK; k++) acc[k] = 0.f;
    #pragma unroll
    for (int it = 0; it < 6; it++) {
        int e = it * 128 + lane * 4;
        float4 wv = wr[it * 32 + lane];
        #pragma unroll
        for (int k = 0; k < KK; k++) {
            float4 qv = *(const float4*)&sQ[k][e];
            acc[k] += wv.x * qv.x + wv.y * qv.y + wv.z * qv.z + wv.w * qv.w;
        }
    }
    float out = 0.f;
    #pragma unroll
    for (int k = 0; k < KK; k++) {
        float v = acc[k];
        v += __shfl_xor_sync(0xFFFFFFFFu, v, 16);
        v += __shfl_xor_sync(0xFFFFFFFFu, v, 8);
        v += __shfl_xor_sync(0xFFFFFFFFu, v, 4);
        v += __shfl_xor_sync(0xFFFFFFFFu, v, 2);
        v += __shfl_xor_sync(0xFFFFFFFFu, v, 1);
        if (lane == k) out = v;
    }
    if (lane < KK) g_Pt[j * KK + lane] = out;

    if (blockIdx.x >= 94) {
        int k = (blockIdx.x - 94) * 8 + warp;
        float cc = 0.f;
        #pragma unroll
        for (int it = 0; it < 6; it++) {
            int e = it * 128 + lane * 4;
            float4 bv = *(const float4*)(bk + e);
            float4 qv = *(const float4*)&sQ[k][e];
            cc += bv.x * qv.x + bv.y * qv.y + bv.z * qv.z + bv.w * qv.w;
        }
        cc += __shfl_xor_sync(0xFFFFFFFFu, cc, 16);
        cc += __shfl_xor_sync(0xFFFFFFFFu, cc, 8);
        cc += __shfl_xor_sync(0xFFFFFFFFu, cc, 4);
        cc += __shfl_xor_sync(0xFFFFFFFFu, cc, 2);
        cc += __shfl_xor_sync(0xFFFFFFFFu, cc, 1);
        if (lane == 0) g_c[k] = cc;
    }
}

// ---------------- kPh: g_Pt [j][k] -> g_Pth fp16 node-major [k][j] --------
__global__ void kPh() {
    int idx = blockIdx.x * 256 + threadIdx.x;   // 12288
    int k = idx / DN, j = idx % DN;
    ((__half*)g_Pth)[idx] = __float2half_rn(g_Pt[j * KK + k]);
}

// ---------------- kSplitAllW: all 4 weight conversions, one launch -------
__global__ void kSplitAllW(const float* __restrict__ Wv,
                           const float* __restrict__ Wg,
                           const float* __restrict__ We1) {
    int sid = blockIdx.x * 256 + threadIdx.x;   // 0..319487
    float a[8];
    __half* out;
    int e0;
    if (sid < 221184) {
        int job = sid / 73728, s = sid % 73728;
        int n = s % 768, seg = s / 768;
        e0 = seg * 8;
        const float* Wp = (job == 0) ? Wv : (job == 1) ? Wg : (Wg + 768 * 768);
        uint4* o4 = (job == 0) ? g_WbfV : (job == 1) ? g_WbfG0 : g_WbfG1;
        out = (__half*)o4 + (size_t)n * KH;
        #pragma unroll
        for (int i = 0; i < 8; i++) a[i] = Wp[(size_t)(e0 + i) * 768 + n];
    } else {
        int s = sid - 221184;
        int n = s % 1024, seg = s / 1024;
        e0 = seg * 8;
        out = (__half*)g_WbfE1 + (size_t)n * KH;
        size_t base = (n < HID) ? (size_t)n : ((size_t)768 * HID + (n - HID));
        #pragma unroll
        for (int i = 0; i < 8; i++) a[i] = We1[base + (size_t)(e0 + i) * HID];
    }
    unsigned h[4];
    #pragma unroll
    for (int i = 0; i < 4; i++) h[i] = packh2(a[2 * i], a[2 * i + 1]);
    *(uint4*)(out + e0) = *(uint4*)h;
}

// ---------------- kScoreG: scores = wh @ Pth^T, tensor cores --------------
// grid 154, block 256 (8 warps); tile 128 x 16, K=768
__global__ __launch_bounds__(256, 2) void kScoreG() {
    __shared__ __align__(1024) __half sB[16 * 768];     // 24 KB, resident
    __shared__ __align__(1024) __half sA[3][128 * 32];  // 24 KB, 3-stage

    const __half* Ag = (const __half*)g_wh;
    const int m0 = blockIdx.x * 128;
    const int tid = threadIdx.x;
    const int lane = tid & 31, warp = tid >> 5;
    const uint32_t sAu = smem_u32(sA), sBu = smem_u32(sB);

    for (int idx = tid; idx < 16 * 96; idx += 256) {
        int r = idx / 96, u = idx % 96;
        uint4 v = g_Pth[r * 96 + u];
        *(uint4*)((char*)sB + r * 1536 + ((u ^ (r & 7)) << 4)) = v;
    }

    uint32_t soff[2];
    const __half* gA[2];
    #pragma unroll
    for (int i = 0; i < 2; i++) {
        int v = tid * 2 + i, row = v >> 2, q = v & 3;
        soff[i] = row * 64 + ((q ^ ((row >> 1) & 3)) << 4);
        gA[i] = Ag + (size_t)(m0 + row) * KH + q * 8;
    }

    const int r16 = lane & 15, hh = lane >> 4;
    uint32_t aoff[2];
    #pragma unroll
    for (int s = 0; s < 2; s++) {
        int quad = 2 * s + hh;
        int row = warp * 16 + r16;
        aoff[s] = row * 64 + ((quad ^ ((row >> 1) & 3)) << 4);
    }

    float acc[2][4];
    #pragma unroll
    for (int b = 0; b < 2; b++)
        #pragma unroll
        for (int r = 0; r < 4; r++) acc[b][r] = 0.f;

    #pragma unroll
    for (int st = 0; st < 2; st++) {
        uint32_t da = sAu + st * 8192;
        #pragma unroll
        for (int i = 0; i < 2; i++)
            asm volatile("cp.async.ca.shared.global [%0], [%1], 16;"
                         :: "r"(da + soff[i]), "l"(gA[i] + st * 32));
        asm volatile("cp.async.commit_group;");
    }
    __syncthreads();

    for (int c = 0; c < KCH; c++) {
        const int buf = c % 3;
        if (c + 1 < KCH) asm volatile("cp.async.wait_group 1;");
        else             asm volatile("cp.async.wait_group 0;");
        __syncthreads();
        if (c + 2 < KCH) {
            const uint32_t da = sAu + ((c + 2) % 3) * 8192;
            #pragma unroll
            for (int i = 0; i < 2; i++)
                asm volatile("cp.async.ca.shared.global [%0], [%1], 16;"
                             :: "r"(da + soff[i]), "l"(gA[i] + (c + 2) * 32));
            asm volatile("cp.async.commit_group;");
        }

        const uint32_t baseA = sAu + buf * 8192;
        #pragma unroll
        for (int s = 0; s < 2; s++) {
            uint32_t afr[4];
            asm volatile("ldmatrix.sync.aligned.m8n8.x4.shared.b16 "
                         "{%0,%1,%2,%3}, [%4];"
                         : "=r"(afr[0]), "=r"(afr[1]), "=r"(afr[2]), "=r"(afr[3])
                         : "r"(baseA + aoff[s]));
            int u = c * 4 + s * 2 + hh;
            uint32_t baddr = sBu + r16 * 1536 + (((u) ^ (r16 & 7)) << 4);
            uint32_t r0, r1, r2, r3;
            asm volatile("ldmatrix.sync.aligned.m8n8.x4.shared.b16 "
                         "{%0,%1,%2,%3}, [%4];"
                         : "=r"(r0), "=r"(r1), "=r"(r2), "=r"(r3) : "r"(baddr));
            uint32_t bfr[2][2];
            bfr[0][0] = r0; bfr[0][1] = r2;
            bfr[1][0] = r1; bfr[1][1] = r3;
            #pragma unroll
            for (int nt = 0; nt < 2; nt++) {
                asm volatile(
                    "mma.sync.aligned.m16n8k16.row.col.f32.f16.f16.f32 "
                    "{%0,%1,%2,%3}, {%4,%5,%6,%7}, {%8,%9}, {%0,%1,%2,%3};"
                    : "+f"(acc[nt][0]), "+f"(acc[nt][1]),
                      "+f"(acc[nt][2]), "+f"(acc[nt][3])
                    : "r"(afr[0]), "r"(afr[1]), "r"(afr[2]), "r"(afr[3]),
                      "r"(bfr[nt][0]), "r"(bfr[nt][1]));
            }
        }
    }

    #pragma unroll
    for (int half = 0; half < 2; half++) {
        int row = m0 + warp * 16 + (lane >> 2) + 8 * half;
        float* crow = g_Sc + (size_t)row * KK;
        #pragma unroll
        for (int nt = 0; nt < 2; nt++) {
            int col = nt * 8 + (lane & 3) * 2;
            crow[col]     = acc[nt][half * 2 + 0];
            crow[col + 1] = acc[nt][half * 2 + 1];
        }
    }
}

// ---------------- kSoftmax: g_Sc -> softmax -> outS + rowsum --------------
__global__ void kSoftmax(const int* __restrict__ mask, float* __restrict__ outS) {
    int b = blockIdx.x;
    int tid = threadIdx.x;   // 128
    __shared__ float sSm[NN * KK];
    __shared__ float sC[KK];
    if (tid < KK) sC[tid] = g_c[tid];
    __syncthreads();
    if (tid < NN) {
        int n = tid;
        float v[KK];
        const float4* src = (const float4*)(g_Sc + (size_t)(b * NN + n) * KK);
        #pragma unroll
        for (int q = 0; q < 4; q++) *(float4*)&v[q * 4] = src[q];
        if (mask[b * NN + n] == 0) {
            #pragma unroll
            for (int k = 0; k < KK; k++) sSm[n * KK + k] = 1.0f / 16.0f;
        } else {
            float sc[KK]; float m = -3.4e38f;
            #pragma unroll
            for (int k = 0; k < KK; k++) { sc[k] = (v[k] + sC[k]) * SCALE; m = fmaxf(m, sc[k]); }
            float e[KK]; float s = 0.f;
            #pragma unroll
            for (int k = 0; k < KK; k++) { e[k] = __expf(sc[k] - m); s += e[k]; }
            float inv = 1.0f / s;
            #pragma unroll
            for (int k = 0; k < KK; k++) sSm[n * KK + k] = e[k] * inv;
        }
        float4* dst = (float4*)(outS + (size_t)(b * NN + n) * KK);
        #pragma unroll
        for (int q = 0; q < 4; q++) dst[q] = *(float4*)&sSm[n * KK + q * 4];
    }
    __syncthreads();
    if (tid < KK) {
        float s = 0.f;
        for (int n = 0; n < NN; n++) s += sSm[n * KK + tid];
        g_rowsum[b * KK + tid] = s;
    }
}

// ---------------- kU: U = S^T w (fp16 w), write fp16 U -> g_Abf -----------
__global__ void kU(const float* __restrict__ S) {
    int b = blockIdx.x, dh = blockIdx.y;
    int tid = threadIdx.x;
    int d0 = dh * 192 + tid * 2;
    __shared__ float sS[NN * KK];
    for (int idx = tid; idx < NN * KK; idx += 96)
        sS[idx] = S[b * NN * KK + idx];
    __syncthreads();

    float2 acc[KK];
    #pragma unroll
    for (int k = 0; k < KK; k++) { acc[k].x = 0.f; acc[k].y = 0.f; }
    const __half* wp = (const __half*)g_wh + (size_t)b * NN * DD + d0;
    #pragma unroll 4
    for (int n = 0; n < NN; n++) {
        __half2 hv = *(const __half2*)(wp + (size_t)n * DD);
        float2 wv = __half22float2(hv);
        const float* srow = sS + n * KK;
        #pragma unroll
        for (int k = 0; k < KK; k++) {
            float s = srow[k];
            acc[k].x += s * wv.x; acc[k].y += s * wv.y;
        }
    }
    #pragma unroll
    for (int k = 0; k < KK; k++) {
        __half* ur = (__half*)g_Abf + (size_t)(b * KK + k) * KH;
        *(unsigned*)(ur + d0) = packh2(acc[k].x, acc[k].y);
    }
}

// ---------------- kTGemm: mma.sync fp16 GEMM ------------------------------
__global__ __launch_bounds__(256, 2) void kTGemm(
    int asel, int wsel, int mode, const float* __restrict__ bias,
    const float* __restrict__ nq, const float* __restrict__ gatep)
{
    __shared__ __align__(1024) __half sA[3][128 * 32];
    __shared__ __align__(1024) __half sB[3][128 * 32];

    const __half* Ag = (const __half*)(asel ? g_Abf2 : g_Abf);
    const int m0 = blockIdx.x * 128;
    int n0 = blockIdx.y * 128;
    const __half* Bg;
    float* C; int Ncols; int emode = mode;
    if (mode == 3) {
        if (blockIdx.y < 8) {
            Bg = (const __half*)g_WbfE1; C = g_H; Ncols = 2 * HID; emode = 0;
        } else {
            n0 = (blockIdx.y - 8) * 128;
            Bg = (const __half*)g_WbfG0; C = g_M; Ncols = DN; emode = 2;
        }
    } else {
        const uint4* B4 = (wsel == 0) ? g_WbfV : (wsel == 1) ? g_WbfG0
                        : (wsel == 2) ? g_WbfG1 : g_WbfE1;
        Bg = (const __half*)B4;
        if (mode == 0)      { C = g_H; Ncols = 2 * HID; }
        else if (mode == 1) { C = g_V; Ncols = DN; }
        else                { C = g_M; Ncols = DN; }
    }

    const int tid = threadIdx.x;
    const int lane = tid & 31, warp = tid >> 5;
    const int wm = warp >> 1, wn = warp & 1;

    const uint32_t sAu = smem_u32(sA), sBu = smem_u32(sB);

    uint32_t soff[2];
    const __half* gA[2];
    const __half* gB[2];
    #pragma unroll
    for (int i = 0; i < 2; i++) {
        int v = tid * 2 + i, row = v >> 2, q = v & 3;
        soff[i] = row * 64 + ((q ^ ((row >> 1) & 3)) << 4);
        gA[i] = Ag + (size_t)(m0 + row) * KH + q * 8;
        gB[i] = Bg + (size_t)(n0 + row) * KH + q * 8;
    }

    const int r16 = lane & 15, hh = lane >> 4;
    uint32_t aoff[2][2], boff[2][4];
    #pragma unroll
    for (int s = 0; s < 2; s++) {
        int quad = 2 * s + hh;
        #pragma unroll
        for (int mt = 0; mt < 2; mt++) {
            int row = wm * 32 + mt * 16 + r16;
            aoff[s][mt] = row * 64 + ((quad ^ ((row >> 1) & 3)) << 4);
        }
        #pragma unroll
        for (int nb = 0; nb < 4; nb++) {
            int row = wn * 64 + nb * 16 + r16;
            boff[s][nb] = row * 64 + ((quad ^ ((row >> 1) & 3)) << 4);
        }
    }

    float acc[2][8][4];
    #pragma unroll
    for (int a = 0; a < 2; a++)
        #pragma unroll
        for (int b = 0; b < 8; b++)
            #pragma unroll
            for (int r = 0; r < 4; r++) acc[a][b][r] = 0.f;

    #pragma unroll
    for (int st = 0; st < 2; st++) {
        uint32_t da = sAu + st * 8192, db = sBu + st * 8192;
        #pragma unroll
        for (int i = 0; i < 2; i++) {
            asm volatile("cp.async.ca.shared.global [%0], [%1], 16;"
                         :: "r"(da + soff[i]), "l"(gA[i] + st * 32));
            asm volatile("cp.async.ca.shared.global [%0], [%1], 16;"
                         :: "r"(db + soff[i]), "l"(gB[i] + st * 32));
        }
        asm volatile("cp.async.commit_group;");
    }

    for (int c = 0; c < KCH; c++) {
        const int buf = c % 3;
        if (c + 1 < KCH) asm volatile("cp.async.wait_group 1;");
        else             asm volatile("cp.async.wait_group 0;");
        __syncthreads();
        if (c + 2 < KCH) {
            const int wb = (c + 2) % 3;
            const uint32_t da = sAu + wb * 8192, db = sBu + wb * 8192;
            #pragma unroll
            for (int i = 0; i < 2; i++) {
                asm volatile("cp.async.ca.shared.global [%0], [%1], 16;"
                             :: "r"(da + soff[i]), "l"(gA[i] + (c + 2) * 32));
                asm volatile("cp.async.ca.shared.global [%0], [%1], 16;"
                             :: "r"(db + soff[i]), "l"(gB[i] + (c + 2) * 32));
            }
            asm volatile("cp.async.commit_group;");
        }

        const uint32_t baseA = sAu + buf * 8192;
        const uint32_t baseB = sBu + buf * 8192;
        #pragma unroll
        for (int s = 0; s < 2; s++) {
            uint32_t afr[2][4];
            #pragma unroll
            for (int mt = 0; mt < 2; mt++) {
                asm volatile("ldmatrix.sync.aligned.m8n8.x4.shared.b16 "
                             "{%0,%1,%2,%3}, [%4];"
                             : "=r"(afr[mt][0]), "=r"(afr[mt][1]),
                               "=r"(afr[mt][2]), "=r"(afr[mt][3])
                             : "r"(baseA + aoff[s][mt]));
            }
            uint32_t bfr[8][2];
            #pragma unroll
            for (int nb = 0; nb < 4; nb++) {
                uint32_t r0, r1, r2, r3;
                asm volatile("ldmatrix.sync.aligned.m8n8.x4.shared.b16 "
                             "{%0,%1,%2,%3}, [%4];"
                             : "=r"(r0), "=r"(r1), "=r"(r2), "=r"(r3)
                             : "r"(baseB + boff[s][nb]));
                bfr[nb * 2][0] = r0;     bfr[nb * 2][1] = r2;
                bfr[nb * 2 + 1][0] = r1; bfr[nb * 2 + 1][1] = r3;
            }
            #pragma unroll
            for (int mt = 0; mt < 2; mt++)
                #pragma unroll
                for (int nt = 0; nt < 8; nt++) {
                    asm volatile(
                        "mma.sync.aligned.m16n8k16.row.col.f32.f16.f16.f32 "
                        "{%0,%1,%2,%3}, {%4,%5,%6,%7}, {%8,%9}, {%0,%1,%2,%3};"
                        : "+f"(acc[mt][nt][0]), "+f"(acc[mt][nt][1]),
                          "+f"(acc[mt][nt][2]), "+f"(acc[mt][nt][3])
                        : "r"(afr[mt][0]), "r"(afr[mt][1]),
                          "r"(afr[mt][2]), "r"(afr[mt][3]),
                          "r"(bfr[nt][0]), "r"(bfr[nt][1]));
                }
        }
    }

    float gate = 0.f, omg = 1.f;
    if (emode == 1) {
        gate = 1.0f / (1.0f + expf(-gatep[0]));
        omg = 1.0f - gate;
    }
    #pragma unroll
    for (int mt = 0; mt < 2; mt++) {
        #pragma unroll
        for (int half = 0; half < 2; half++) {
            int row = m0 + wm * 32 + mt * 16 + (lane >> 2) + 8 * half;
            float rsv = 0.f; const float* nqr = nullptr;
            __half* arow2 = nullptr;
            if (emode == 1) {
                rsv = g_rowsum[row];
                nqr = nq + (size_t)(row & 15) * DN;
                arow2 = (__half*)g_Abf2 + (size_t)row * KH;
            }
            float* crow = C + (size_t)row * Ncols;
            #pragma unroll
            for (int nt = 0; nt < 8; nt++) {
                int col = n0 + wn * 64 + nt * 8 + (lane & 3) * 2;
                float v0 = acc[mt][nt][half * 2 + 0];
                float v1 = acc[mt][nt][half * 2 + 1];
                if (emode == 1) {
                    v0 += rsv * __ldg(&bias[col]);
                    v1 += rsv * __ldg(&bias[col + 1]);
                    v0 = omg * v0 + gate * __ldg(&nqr[col]);
                    v1 = omg * v1 + gate * __ldg(&nqr[col + 1]);
                    *(unsigned*)(arow2 + col) = packh2(v0, v1);
                } else if (emode == 2) {
                    v0 += __ldg(&bias[col]);
                    v1 += __ldg(&bias[col + 1]);
                }
                float2 o; o.x = v0; o.y = v1;
                *(float2*)(crow + col) = o;
            }
        }
    }
}

// ---------------- kEdgeP: partial edge logits, float4 inner ---------------
__global__ void kEdgeP(const float* __restrict__ be1, const float* __restrict__ We2) {
    int b = blockIdx.x;
    int h0 = blockIdx.y * 256;
    int tid = threadIdx.x;
    int i = tid >> 4, j = tid & 15;
    __shared__ __align__(16) float sHi[KK * 260];
    __shared__ __align__(16) float sHj[KK * 260];
    __shared__ __align__(16) float sW2[256];

    for (int idx = tid; idx < KK * 256; idx += 256) {
        int r = idx >> 8, c = idx & 255;
        sHi[r * 260 + c] = g_H[(size_t)(b * KK + r) * (2 * HID) + h0 + c] + be1[h0 + c];
        sHj[r * 260 + c] = g_H[(size_t)(b * KK + r) * (2 * HID) + HID + h0 + c];
    }
    sW2[tid] = We2[h0 + tid];
    __syncthreads();
    const float* hi = sHi + i * 260;
    const float* hj = sHj + j * 260;
    float a0 = 0.f, a1 = 0.f, a2 = 0.f, a3 = 0.f;
    #pragma unroll 4
    for (int c = 0; c < 256; c += 4) {
        float4 h4 = *(const float4*)&hi[c];
        float4 g4 = *(const float4*)&hj[c];
        float4 w4 = *(const float4*)&sW2[c];
        a0 += fmaxf(h4.x + g4.x, 0.f) * w4.x;
        a1 += fmaxf(h4.y + g4.y, 0.f) * w4.y;
        a2 += fmaxf(h4.z + g4.z, 0.f) * w4.z;
        a3 += fmaxf(h4.w + g4.w, 0.f) * w4.w;
    }
    g_Ep[blockIdx.y][b * 256 + tid] = (a0 + a1) + (a2 + a3);
}

// ---------------- kEdgeR: combine partials -> softmax(A) or outE ----------
__global__ void kEdgeR(const float* __restrict__ be2, float* __restrict__ outE,
                       int post) {
    int b = blockIdx.x;
    int tid = threadIdx.x;
    int i = tid >> 4;
    __shared__ float sE[KK * 17];
    float E = g_Ep[0][b * 256 + tid] + g_Ep[1][b * 256 + tid] + be2[0];
    if (post) {
        outE[b * 256 + tid] = E;
    } else {
        sE[i * 17 + (tid & 15)] = E;
        __syncthreads();
        float m = -3.4e38f;
        #pragma unroll
        for (int jj = 0; jj < KK; jj++) m = fmaxf(m, sE[i * 17 + jj]);
        float s = 0.f;
        #pragma unroll
        for (int jj = 0; jj < KK; jj++) s += __expf(sE[i * 17 + jj] - m);
        g_A[b * 256 + tid] = __expf(E - m) / s;
    }
}

// ---------------- kMsg: V += relu(A @ M), d-split grid (BB,3) -------------
__global__ void kMsg(float* __restrict__ outV) {
    int b = blockIdx.x, dh = blockIdx.y;
    int tid = threadIdx.x;
    int d = dh * 256 + tid;
    __shared__ float sAm[KK * 17];
    sAm[(tid >> 4) * 17 + (tid & 15)] = g_A[b * 256 + tid];
    __syncthreads();
    float m[KK];
    #pragma unroll
    for (int j = 0; j < KK; j++)
        m[j] = g_M[(size_t)(b * KK + j) * DN + d];
    #pragma unroll
    for (int i = 0; i < KK; i++) {
        const float* arow = sAm + i * 17;
        float acc = 0.f;
        #pragma unroll
        for (int j = 0; j < KK; j++) acc += arow[j] * m[j];
        int row = b * KK + i;
        float nv = g_V[(size_t)row * DN + d] + fmaxf(acc, 0.f);
        g_V[(size_t)row * DN + d] = nv;
        ((__half*)g_Abf2)[(size_t)row * KH + d] = __float2half_rn(nv);
        if (outV) outV[(size_t)row * DN + d] = nv;
    }
}

// ---------------- host ----------------------------------------------------
extern "C" void kernel_launch(void* const* d_in, const int* in_sizes, int n_in,
                              void* d_out, int out_size) {
    const float* w    = (const float*)d_in[0];
    const int*   mask = (const int*)  d_in[1];
    const float* nq   = (const float*)d_in[2];
    const float* Wq   = (const float*)d_in[3];
    const float* bq   = (const float*)d_in[4];
    const float* Wk   = (const float*)d_in[5];
    const float* bk   = (const float*)d_in[6];
    const float* Wv   = (const float*)d_in[7];
    const float* bv   = (const float*)d_in[8];
    const float* We1  = (const float*)d_in[9];
    const float* be1  = (const float*)d_in[10];
    const float* We2  = (const float*)d_in[11];
    const float* be2  = (const float*)d_in[12];
    const float* fg   = (const float*)d_in[13];
    const float* Wg   = (const float*)d_in[14];
    const float* bg   = (const float*)d_in[15];

    float* outS = (float*)d_out;
    float* outV = outS + (size_t)BB * NN * KK;
    float* outE = outV + (size_t)BB * KK * DN;

    kWh<<<7392, 256>>>(w);                                     // w -> fp16
    kSplitAllW<<<1248, 256>>>(Wv, Wg, We1);
    kQ<<<dim3(3, 16), 256>>>(nq, Wq);
    kQr<<<48, 256>>>(bq);
    kP<<<96, 256>>>(Wk, bk);                                   // g_Pt fp32 + c
    kPh<<<48, 256>>>();                                        // -> g_Pth fp16
    kScoreG<<<154, 256>>>();                                   // scores via HMMA
    kSoftmax<<<BB, 128>>>(mask, outS);
    kU<<<dim3(BB, 4), 96>>>(outS);                             // fp16 U -> g_Abf

    kTGemm<<<dim3(32, 6), 256>>>(0, 0, 1, bv, nq, fg);         // V = U@Wv; fp16 V -> Abf2
    kTGemm<<<dim3(32, 14), 256>>>(1, 0, 3, bg, nullptr, nullptr);   // H = V@We1 AND M = V@Wg0+bg0
    kEdgeP<<<dim3(BB, 2), 256>>>(be1, We2);                    // partial E
    kEdgeR<<<BB, 256>>>(be2, nullptr, 0);                      // A = softmax(E)
    kMsg<<<dim3(BB, 3), 256>>>(nullptr);                       // V += relu(A@M); Abf2
    kTGemm<<<dim3(32, 6), 256>>>(1, 2, 2, bg + DN, nullptr, nullptr); // M = V@Wg1+bg1
    kMsg<<<dim3(BB, 3), 256>>>(outV);                          // final V; Abf2; outV
    kTGemm<<<dim3(32, 8), 256>>>(1, 3, 0, nullptr, nullptr, nullptr); // H on final V
    kEdgeP<<<dim3(BB, 2), 256>>>(be1, We2);                    // partial E (final V)
    kEdgeR<<<BB, 256>>>(be2, outE, 1);                         // E -> out
}

// round 14
// speedup vs baseline: 4.1946x; 1.0238x over previous
#include <cuda_runtime.h>
#include <cuda_bf16.h>
#include <cuda_fp16.h>
#include <math.h>
#include <stdint.h>

// Problem dims
#define BB 256
#define NN 77
#define DD 768
#define KK 16
#define DN 768
#define HID 512
#define MTOT (BB*KK)          // 4096
#define SCALE 0.10206207261596575f   // (768/8)^-0.5
#define KH 768                // GEMM K (fp16)
#define KCH 24                // 768/32 chunks
#define MSC (BB*NN)           // 19712 score rows = 154*128

// ---------------- scratch (device globals; no allocation) ----------------
__device__ float g_Qp[16][KK*DN];
__device__ float g_Q[KK*DN];
__device__ float g_c[KK];
__device__ float g_Sc[(size_t)MSC*KK];   // raw scores [m][k]
__device__ float g_Ep[2][BB*256];        // partial edge logits
__device__ float g_V[MTOT*DN];
__device__ float g_rowsum[MTOT];
__device__ float g_H[MTOT*2*HID];
__device__ float g_M[MTOT*DN];
// fp16 operand buffers (uint4 for 16B alignment)
__device__ uint4 g_wh [(size_t)MSC*DD/8];     // fp16 copy of w
__device__ uint4 g_Pth[KK*DN/8];              // fp16 P, node-major [16][768]
__device__ uint4 g_Abf [(size_t)MTOT*KH/8];   // fp16 U
__device__ uint4 g_Abf2[(size_t)MTOT*KH/8];   // fp16 V
__device__ uint4 g_WbfV [768*KH/8];
__device__ uint4 g_WbfG0[768*KH/8];
__device__ uint4 g_WbfG1[768*KH/8];
__device__ uint4 g_WbfE1[1024*KH/8];

__device__ __forceinline__ uint32_t smem_u32(const void* p) {
    uint32_t a;
    asm("{ .reg .u64 t; cvta.to.shared.u64 t, %1; cvt.u32.u64 %0, t; }"
        : "=r"(a) : "l"(p));
    return a;
}

__device__ __forceinline__ unsigned packh2(float a, float b) {
    __half2 h = __floats2half2_rn(a, b);
    return *(unsigned*)&h;
}

// ---------------- kPrep: fused w->fp16, weight conversions, kQ partials ---
// blocks [0,7392): kWh ; [7392,8640): kSplitAllW ; [8640,8688): kQ
#define PREP_WH 7392
#define PREP_SPLIT 1248
#define PREP_KQ 48
__global__ void kPrep(const float* __restrict__ w,
                      const float* __restrict__ Wv,
                      const float* __restrict__ Wg,
                      const float* __restrict__ We1,
                      const float* __restrict__ nq,
                      const float* __restrict__ Wq) {
    int bid = blockIdx.x;
    int tid = threadIdx.x;
    if (bid < PREP_WH) {
        size_t idx = (size_t)bid * 256 + tid;
        const float4* s = (const float4*)w + idx * 2;
        float4 a = s[0], b = s[1];
        uint4 o;
        o.x = packh2(a.x, a.y); o.y = packh2(a.z, a.w);
        o.z = packh2(b.x, b.y); o.w = packh2(b.z, b.w);
        g_wh[idx] = o;
    } else if (bid < PREP_WH + PREP_SPLIT) {
        int sid = (bid - PREP_WH) * 256 + tid;
        float a[8];
        __half* out;
        int e0;
        if (sid < 221184) {
            int job = sid / 73728, s = sid % 73728;
            int n = s % 768, seg = s / 768;
            e0 = seg * 8;
            const float* Wp = (job == 0) ? Wv : (job == 1) ? Wg : (Wg + 768 * 768);
            uint4* o4 = (job == 0) ? g_WbfV : (job == 1) ? g_WbfG0 : g_WbfG1;
            out = (__half*)o4 + (size_t)n * KH;
            #pragma unroll
            for (int i = 0; i < 8; i++) a[i] = Wp[(size_t)(e0 + i) * 768 + n];
        } else {
            int s = sid - 221184;
            int n = s % 1024, seg = s / 1024;
            e0 = seg * 8;
            out = (__half*)g_WbfE1 + (size_t)n * KH;
            size_t base = (n < HID) ? (size_t)n : ((size_t)768 * HID + (n - HID));
            #pragma unroll
            for (int i = 0; i < 8; i++) a[i] = We1[base + (size_t)(e0 + i) * HID];
        }
        unsigned h[4];
        #pragma unroll
        for (int i = 0; i < 4; i++) h[i] = packh2(a[2 * i], a[2 * i + 1]);
        *(uint4*)(out + e0) = *(uint4*)h;
    } else {
        int q = bid - (PREP_WH + PREP_SPLIT);
        int dblk = q % 3, sl = q / 3;
        int d = dblk * 256 + tid;
        int e0 = sl * 48;
        __shared__ float snq[KK][48];
        for (int idx = tid; idx < KK * 48; idx += 256)
            snq[idx / 48][idx % 48] = nq[(idx / 48) * DN + e0 + idx % 48];
        __syncthreads();
        float acc[KK];
        #pragma unroll
        for (int k = 0; k < KK; k++) acc[k] = 0.f;
        const float* wp = Wq + (size_t)e0 * DN + d;
        #pragma unroll 4
        for (int e = 0; e < 48; e++) {
            float wv = wp[(size_t)e * DN];
            #pragma unroll
            for (int k = 0; k < KK; k++) acc[k] += snq[k][e] * wv;
        }
        #pragma unroll
        for (int k = 0; k < KK; k++) g_Qp[sl][k * DN + d] = acc[k];
    }
}

// ---------------- kQr: sum 16 partials + bq -> g_Q ------------------------
__global__ void kQr(const float* __restrict__ bq) {
    int i = blockIdx.x * 256 + threadIdx.x;   // 12288
    float s = bq[i % DN];
    #pragma unroll
    for (int sl = 0; sl < 16; sl++) s += g_Qp[sl][i];
    g_Q[i] = s;
}

// ---------------- kP: P -> fp16 g_Pth directly; c[k] ----------------------
__global__ void kP(const float* __restrict__ Wk, const float* __restrict__ bk) {
    __shared__ float sQ[KK][DN];   // 48 KB
    __shared__ float sPo[8][17];
    int tid = threadIdx.x;
    int lane = tid & 31, warp = tid >> 5;
    for (int idx = tid; idx < KK * DN; idx += 256)
        sQ[idx / DN][idx % DN] = g_Q[idx];
    __syncthreads();

    int j = blockIdx.x * 8 + warp;
    const float4* wr = (const float4*)(Wk + (size_t)j * DN);
    float acc[KK];
    #pragma unroll
    for (int k = 0; k < KK; k++) acc[k] = 0.f;
    #pragma unroll
    for (int it = 0; it < 6; it++) {
        int e = it * 128 + lane * 4;
        float4 wv = wr[it * 32 + lane];
        #pragma unroll
        for (int k = 0; k < KK; k++) {
            float4 qv = *(const float4*)&sQ[k][e];
            acc[k] += wv.x * qv.x + wv.y * qv.y + wv.z * qv.z + wv.w * qv.w;
        }
    }
    float out = 0.f;
    #pragma unroll
    for (int k = 0; k < KK; k++) {
        float v = acc[k];
        v += __shfl_xor_sync(0xFFFFFFFFu, v, 16);
        v += __shfl_xor_sync(0xFFFFFFFFu, v, 8);
        v += __shfl_xor_sync(0xFFFFFFFFu, v, 4);
        v += __shfl_xor_sync(0xFFFFFFFFu, v, 2);
        v += __shfl_xor_sync(0xFFFFFFFFu, v, 1);
        if (lane == k) out = v;
    }
    if (lane < KK) sPo[warp][lane] = out;   // sPo[jj][k]
    __syncthreads();
    // coalesced-ish fp16 write: k = tid>>3, jj = tid&7 -> 16B runs per k
    if (tid < 128) {
        int k = tid >> 3, jj = tid & 7;
        ((__half*)g_Pth)[k * DN + blockIdx.x * 8 + jj] = __float2half_rn(sPo[jj][k]);
    }

    if (blockIdx.x >= 94) {
        int k = (blockIdx.x - 94) * 8 + warp;
        float cc = 0.f;
        #pragma unroll
        for (int it = 0; it < 6; it++) {
            int e = it * 128 + lane * 4;
            float4 bv = *(const float4*)(bk + e);
            float4 qv = *(const float4*)&sQ[k][e];
            cc += bv.x * qv.x + bv.y * qv.y + bv.z * qv.z + bv.w * qv.w;
        }
        cc += __shfl_xor_sync(0xFFFFFFFFu, cc, 16);
        cc += __shfl_xor_sync(0xFFFFFFFFu, cc, 8);
        cc += __shfl_xor_sync(0xFFFFFFFFu, cc, 4);
        cc += __shfl_xor_sync(0xFFFFFFFFu, cc, 2);
        cc += __shfl_xor_sync(0xFFFFFFFFu, cc, 1);
        if (lane == 0) g_c[k] = cc;
    }
}

// ---------------- kScoreG: scores = wh @ Pth^T, tensor cores --------------
__global__ __launch_bounds__(256, 2) void kScoreG() {
    __shared__ __align__(1024) __half sB[16 * 768];
    __shared__ __align__(1024) __half sA[3][128 * 32];

    const __half* Ag = (const __half*)g_wh;
    const int m0 = blockIdx.x * 128;
    const int tid = threadIdx.x;
    const int lane = tid & 31, warp = tid >> 5;
    const uint32_t sAu = smem_u32(sA), sBu = smem_u32(sB);

    for (int idx = tid; idx < 16 * 96; idx += 256) {
        int r = idx / 96, u = idx % 96;
        uint4 v = g_Pth[r * 96 + u];
        *(uint4*)((char*)sB + r * 1536 + ((u ^ (r & 7)) << 4)) = v;
    }

    uint32_t soff[2];
    const __half* gA[2];
    #pragma unroll
    for (int i = 0; i < 2; i++) {
        int v = tid * 2 + i, row = v >> 2, q = v & 3;
        soff[i] = row * 64 + ((q ^ ((row >> 1) & 3)) << 4);
        gA[i] = Ag + (size_t)(m0 + row) * KH + q * 8;
    }

    const int r16 = lane & 15, hh = lane >> 4;
    uint32_t aoff[2];
    #pragma unroll
    for (int s = 0; s < 2; s++) {
        int quad = 2 * s + hh;
        int row = warp * 16 + r16;
        aoff[s] = row * 64 + ((quad ^ ((row >> 1) & 3)) << 4);
    }

    float acc[2][4];
    #pragma unroll
    for (int b = 0; b < 2; b++)
        #pragma unroll
        for (int r = 0; r < 4; r++) acc[b][r] = 0.f;

    #pragma unroll
    for (int st = 0; st < 2; st++) {
        uint32_t da = sAu + st * 8192;
        #pragma unroll
        for (int i = 0; i < 2; i++)
            asm volatile("cp.async.ca.shared.global [%0], [%1], 16;"
                         :: "r"(da + soff[i]), "l"(gA[i] + st * 32));
        asm volatile("cp.async.commit_group;");
    }
    __syncthreads();

    for (int c = 0; c < KCH; c++) {
        const int buf = c % 3;
        if (c + 1 < KCH) asm volatile("cp.async.wait_group 1;");
        else             asm volatile("cp.async.wait_group 0;");
        __syncthreads();
        if (c + 2 < KCH) {
            const uint32_t da = sAu + ((c + 2) % 3) * 8192;
            #pragma unroll
            for (int i = 0; i < 2; i++)
                asm volatile("cp.async.ca.shared.global [%0], [%1], 16;"
                             :: "r"(da + soff[i]), "l"(gA[i] + (c + 2) * 32));
            asm volatile("cp.async.commit_group;");
        }

        const uint32_t baseA = sAu + buf * 8192;
        #pragma unroll
        for (int s = 0; s < 2; s++) {
            uint32_t afr[4];
            asm volatile("ldmatrix.sync.aligned.m8n8.x4.shared.b16 "
                         "{%0,%1,%2,%3}, [%4];"
                         : "=r"(afr[0]), "=r"(afr[1]), "=r"(afr[2]), "=r"(afr[3])
                         : "r"(baseA + aoff[s]));
            int u = c * 4 + s * 2 + hh;
            uint32_t baddr = sBu + r16 * 1536 + (((u) ^ (r16 & 7)) << 4);
            uint32_t r0, r1, r2, r3;
            asm volatile("ldmatrix.sync.aligned.m8n8.x4.shared.b16 "
                         "{%0,%1,%2,%3}, [%4];"
                         : "=r"(r0), "=r"(r1), "=r"(r2), "=r"(r3) : "r"(baddr));
            uint32_t bfr[2][2];
            bfr[0][0] = r0; bfr[0][1] = r2;
            bfr[1][0] = r1; bfr[1][1] = r3;
            #pragma unroll
            for (int nt = 0; nt < 2; nt++) {
                asm volatile(
                    "mma.sync.aligned.m16n8k16.row.col.f32.f16.f16.f32 "
                    "{%0,%1,%2,%3}, {%4,%5,%6,%7}, {%8,%9}, {%0,%1,%2,%3};"
                    : "+f"(acc[nt][0]), "+f"(acc[nt][1]),
                      "+f"(acc[nt][2]), "+f"(acc[nt][3])
                    : "r"(afr[0]), "r"(afr[1]), "r"(afr[2]), "r"(afr[3]),
                      "r"(bfr[nt][0]), "r"(bfr[nt][1]));
            }
        }
    }

    #pragma unroll
    for (int half = 0; half < 2; half++) {
        int row = m0 + warp * 16 + (lane >> 2) + 8 * half;
        float* crow = g_Sc + (size_t)row * KK;
        #pragma unroll
        for (int nt = 0; nt < 2; nt++) {
            int col = nt * 8 + (lane & 3) * 2;
            crow[col]     = acc[nt][half * 2 + 0];
            crow[col + 1] = acc[nt][half * 2 + 1];
        }
    }
}

// ---------------- kU: softmax (from g_Sc) + U = S^T w, fp16 U out ---------
// grid (BB, 4), 96 threads; dh==0 also writes outS + rowsum
__global__ void kU(const int* __restrict__ mask, float* __restrict__ outS) {
    int b = blockIdx.x, dh = blockIdx.y;
    int tid = threadIdx.x;
    int d0 = dh * 192 + tid * 2;
    __shared__ float sS[NN * KK];
    __shared__ float sC[KK];
    if (tid < KK) sC[tid] = g_c[tid];
    __syncthreads();
    if (tid < NN) {
        int n = tid;
        float v[KK];
        const float4* src = (const float4*)(g_Sc + (size_t)(b * NN + n) * KK);
        #pragma unroll
        for (int q = 0; q < 4; q++) *(float4*)&v[q * 4] = src[q];
        if (mask[b * NN + n] == 0) {
            #pragma unroll
            for (int k = 0; k < KK; k++) sS[n * KK + k] = 1.0f / 16.0f;
        } else {
            float sc[KK]; float m = -3.4e38f;
            #pragma unroll
            for (int k = 0; k < KK; k++) { sc[k] = (v[k] + sC[k]) * SCALE; m = fmaxf(m, sc[k]); }
            float e[KK]; float s = 0.f;
            #pragma unroll
            for (int k = 0; k < KK; k++) { e[k] = __expf(sc[k] - m); s += e[k]; }
            float inv = 1.0f / s;
            #pragma unroll
            for (int k = 0; k < KK; k++) sS[n * KK + k] = e[k] * inv;
        }
        if (dh == 0) {
            float4* dst = (float4*)(outS + (size_t)(b * NN + n) * KK);
            #pragma unroll
            for (int q = 0; q < 4; q++) dst[q] = *(float4*)&sS[n * KK + q * 4];
        }
    }
    __syncthreads();
    if (dh == 0 && tid < KK) {
        float s = 0.f;
        for (int n = 0; n < NN; n++) s += sS[n * KK + tid];
        g_rowsum[b * KK + tid] = s;
    }

    float2 acc[KK];
    #pragma unroll
    for (int k = 0; k < KK; k++) { acc[k].x = 0.f; acc[k].y = 0.f; }
    const __half* wp = (const __half*)g_wh + (size_t)b * NN * DD + d0;
    #pragma unroll 4
    for (int n = 0; n < NN; n++) {
        __half2 hv = *(const __half2*)(wp + (size_t)n * DD);
        float2 wv = __half22float2(hv);
        const float* srow = sS + n * KK;
        #pragma unroll
        for (int k = 0; k < KK; k++) {
            float s = srow[k];
            acc[k].x += s * wv.x; acc[k].y += s * wv.y;
        }
    }
    #pragma unroll
    for (int k = 0; k < KK; k++) {
        __half* ur = (__half*)g_Abf + (size_t)(b * KK + k) * KH;
        *(unsigned*)(ur + d0) = packh2(acc[k].x, acc[k].y);
    }
}

// ---------------- kTGemm: mma.sync fp16 GEMM ------------------------------
__global__ __launch_bounds__(256, 2) void kTGemm(
    int asel, int wsel, int mode, const float* __restrict__ bias,
    const float* __restrict__ nq, const float* __restrict__ gatep)
{
    __shared__ __align__(1024) __half sA[3][128 * 32];
    __shared__ __align__(1024) __half sB[3][128 * 32];

    const __half* Ag = (const __half*)(asel ? g_Abf2 : g_Abf);
    const int m0 = blockIdx.x * 128;
    int n0 = blockIdx.y * 128;
    const __half* Bg;
    float* C; int Ncols; int emode = mode;
    if (mode == 3) {
        if (blockIdx.y < 8) {
            Bg = (const __half*)g_WbfE1; C = g_H; Ncols = 2 * HID; emode = 0;
        } else {
            n0 = (blockIdx.y - 8) * 128;
            Bg = (const __half*)g_WbfG0; C = g_M; Ncols = DN; emode = 2;
        }
    } else {
        const uint4* B4 = (wsel == 0) ? g_WbfV : (wsel == 1) ? g_WbfG0
                        : (wsel == 2) ? g_WbfG1 : g_WbfE1;
        Bg = (const __half*)B4;
        if (mode == 0)      { C = g_H; Ncols = 2 * HID; }
        else if (mode == 1) { C = g_V; Ncols = DN; }
        else                { C = g_M; Ncols = DN; }
    }

    const int tid = threadIdx.x;
    const int lane = tid & 31, warp = tid >> 5;
    const int wm = warp >> 1, wn = warp & 1;

    const uint32_t sAu = smem_u32(sA), sBu = smem_u32(sB);

    uint32_t soff[2];
    const __half* gA[2];
    const __half* gB[2];
    #pragma unroll
    for (int i = 0; i < 2; i++) {
        int v = tid * 2 + i, row = v >> 2, q = v & 3;
        soff[i] = row * 64 + ((q ^ ((row >> 1) & 3)) << 4);
        gA[i] = Ag + (size_t)(m0 + row) * KH + q * 8;
        gB[i] = Bg + (size_t)(n0 + row) * KH + q * 8;
    }

    const int r16 = lane & 15, hh = lane >> 4;
    uint32_t aoff[2][2], boff[2][4];
    #pragma unroll
    for (int s = 0; s < 2; s++) {
        int quad = 2 * s + hh;
        #pragma unroll
        for (int mt = 0; mt < 2; mt++) {
            int row = wm * 32 + mt * 16 + r16;
            aoff[s][mt] = row * 64 + ((quad ^ ((row >> 1) & 3)) << 4);
        }
        #pragma unroll
        for (int nb = 0; nb < 4; nb++) {
            int row = wn * 64 + nb * 16 + r16;
            boff[s][nb] = row * 64 + ((quad ^ ((row >> 1) & 3)) << 4);
        }
    }

    float acc[2][8][4];
    #pragma unroll
    for (int a = 0; a < 2; a++)
        #pragma unroll
        for (int b = 0; b < 8; b++)
            #pragma unroll
            for (int r = 0; r < 4; r++) acc[a][b][r] = 0.f;

    #pragma unroll
    for (int st = 0; st < 2; st++) {
        uint32_t da = sAu + st * 8192, db = sBu + st * 8192;
        #pragma unroll
        for (int i = 0; i < 2; i++) {
            asm volatile("cp.async.ca.shared.global [%0], [%1], 16;"
                         :: "r"(da + soff[i]), "l"(gA[i] + st * 32));
            asm volatile("cp.async.ca.shared.global [%0], [%1], 16;"
                         :: "r"(db + soff[i]), "l"(gB[i] + st * 32));
        }
        asm volatile("cp.async.commit_group;");
    }

    for (int c = 0; c < KCH; c++) {
        const int buf = c % 3;
        if (c + 1 < KCH) asm volatile("cp.async.wait_group 1;");
        else             asm volatile("cp.async.wait_group 0;");
        __syncthreads();
        if (c + 2 < KCH) {
            const int wb = (c + 2) % 3;
            const uint32_t da = sAu + wb * 8192, db = sBu + wb * 8192;
            #pragma unroll
            for (int i = 0; i < 2; i++) {
                asm volatile("cp.async.ca.shared.global [%0], [%1], 16;"
                             :: "r"(da + soff[i]), "l"(gA[i] + (c + 2) * 32));
                asm volatile("cp.async.ca.shared.global [%0], [%1], 16;"
                             :: "r"(db + soff[i]), "l"(gB[i] + (c + 2) * 32));
            }
            asm volatile("cp.async.commit_group;");
        }

        const uint32_t baseA = sAu + buf * 8192;
        const uint32_t baseB = sBu + buf * 8192;
        #pragma unroll
        for (int s = 0; s < 2; s++) {
            uint32_t afr[2][4];
            #pragma unroll
            for (int mt = 0; mt < 2; mt++) {
                asm volatile("ldmatrix.sync.aligned.m8n8.x4.shared.b16 "
                             "{%0,%1,%2,%3}, [%4];"
                             : "=r"(afr[mt][0]), "=r"(afr[mt][1]),
                               "=r"(afr[mt][2]), "=r"(afr[mt][3])
                             : "r"(baseA + aoff[s][mt]));
            }
            uint32_t bfr[8][2];
            #pragma unroll
            for (int nb = 0; nb < 4; nb++) {
                uint32_t r0, r1, r2, r3;
                asm volatile("ldmatrix.sync.aligned.m8n8.x4.shared.b16 "
                             "{%0,%1,%2,%3}, [%4];"
                             : "=r"(r0), "=r"(r1), "=r"(r2), "=r"(r3)
                             : "r"(baseB + boff[s][nb]));
                bfr[nb * 2][0] = r0;     bfr[nb * 2][1] = r2;
                bfr[nb * 2 + 1][0] = r1; bfr[nb * 2 + 1][1] = r3;
            }
            #pragma unroll
            for (int mt = 0; mt < 2; mt++)
                #pragma unroll
                for (int nt = 0; nt < 8; nt++) {
                    asm volatile(
                        "mma.sync.aligned.m16n8k16.row.col.f32.f16.f16.f32 "
                        "{%0,%1,%2,%3}, {%4,%5,%6,%7}, {%8,%9}, {%0,%1,%2,%3};"
                        : "+f"(acc[mt][nt][0]), "+f"(acc[mt][nt][1]),
                          "+f"(acc[mt][nt][2]), "+f"(acc[mt][nt][3])
                        : "r"(afr[mt][0]), "r"(afr[mt][1]),
                          "r"(afr[mt][2]), "r"(afr[mt][3]),
                          "r"(bfr[nt][0]), "r"(bfr[nt][1]));
                }
        }
    }

    float gate = 0.f, omg = 1.f;
    if (emode == 1) {
        gate = 1.0f / (1.0f + expf(-gatep[0]));
        omg = 1.0f - gate;
    }
    #pragma unroll
    for (int mt = 0; mt < 2; mt++) {
        #pragma unroll
        for (int half = 0; half < 2; half++) {
            int row = m0 + wm * 32 + mt * 16 + (lane >> 2) + 8 * half;
            float rsv = 0.f; const float* nqr = nullptr;
            __half* arow2 = nullptr;
            if (emode == 1) {
                rsv = g_rowsum[row];
                nqr = nq + (size_t)(row & 15) * DN;
                arow2 = (__half*)g_Abf2 + (size_t)row * KH;
            }
            float* crow = C + (size_t)row * Ncols;
            #pragma unroll
            for (int nt = 0; nt < 8; nt++) {
                int col = n0 + wn * 64 + nt * 8 + (lane & 3) * 2;
                float v0 = acc[mt][nt][half * 2 + 0];
                float v1 = acc[mt][nt][half * 2 + 1];
                if (emode == 1) {
                    v0 += rsv * __ldg(&bias[col]);
                    v1 += rsv * __ldg(&bias[col + 1]);
                    v0 = omg * v0 + gate * __ldg(&nqr[col]);
                    v1 = omg * v1 + gate * __ldg(&nqr[col + 1]);
                    *(unsigned*)(arow2 + col) = packh2(v0, v1);
                } else if (emode == 2) {
                    v0 += __ldg(&bias[col]);
                    v1 += __ldg(&bias[col + 1]);
                }
                float2 o; o.x = v0; o.y = v1;
                *(float2*)(crow + col) = o;
            }
        }
    }
}

// ---------------- kEdgeP: partial edge logits, float4 inner ---------------
__global__ void kEdgeP(const float* __restrict__ be1, const float* __restrict__ We2) {
    int b = blockIdx.x;
    int h0 = blockIdx.y * 256;
    int tid = threadIdx.x;
    int i = tid >> 4, j = tid & 15;
    __shared__ __align__(16) float sHi[KK * 260];
    __shared__ __align__(16) float sHj[KK * 260];
    __shared__ __align__(16) float sW2[256];

    for (int idx = tid; idx < KK * 256; idx += 256) {
        int r = idx >> 8, c = idx & 255;
        sHi[r * 260 + c] = g_H[(size_t)(b * KK + r) * (2 * HID) + h0 + c] + be1[h0 + c];
        sHj[r * 260 + c] = g_H[(size_t)(b * KK + r) * (2 * HID) + HID + h0 + c];
    }
    sW2[tid] = We2[h0 + tid];
    __syncthreads();
    const float* hi = sHi + i * 260;
    const float* hj = sHj + j * 260;
    float a0 = 0.f, a1 = 0.f, a2 = 0.f, a3 = 0.f;
    #pragma unroll 4
    for (int c = 0; c < 256; c += 4) {
        float4 h4 = *(const float4*)&hi[c];
        float4 g4 = *(const float4*)&hj[c];
        float4 w4 = *(const float4*)&sW2[c];
        a0 += fmaxf(h4.x + g4.x, 0.f) * w4.x;
        a1 += fmaxf(h4.y + g4.y, 0.f) * w4.y;
        a2 += fmaxf(h4.z + g4.z, 0.f) * w4.z;
        a3 += fmaxf(h4.w + g4.w, 0.f) * w4.w;
    }
    g_Ep[blockIdx.y][b * 256 + tid] = (a0 + a1) + (a2 + a3);
}

// ---------------- kEdgeR: combine partials -> outE (post only) ------------
__global__ void kEdgeR(const float* __restrict__ be2, float* __restrict__ outE) {
    int b = blockIdx.x;
    int tid = threadIdx.x;
    outE[b * 256 + tid] = g_Ep[0][b * 256 + tid] + g_Ep[1][b * 256 + tid] + be2[0];
}

// ---------------- kMsg: A-softmax from g_Ep, V += relu(A@M), fp16 V -------
// grid (BB, 3), 256 threads
__global__ void kMsg(const float* __restrict__ be2, float* __restrict__ outV) {
    int b = blockIdx.x, dh = blockIdx.y;
    int tid = threadIdx.x;
    int d = dh * 256 + tid;
    __shared__ float sE[KK * 17];
    __shared__ float sAm[KK * 17];
    int i = tid >> 4, j = tid & 15;
    float E = g_Ep[0][b * 256 + tid] + g_Ep[1][b * 256 + tid] + be2[0];
    sE[i * 17 + j] = E;
    __syncthreads();
    {
        float m = -3.4e38f;
        #pragma unroll
        for (int jj = 0; jj < KK; jj++) m = fmaxf(m, sE[i * 17 + jj]);
        float s = 0.f;
        #pragma unroll
        for (int jj = 0; jj < KK; jj++) s += __expf(sE[i * 17 + jj] - m);
        sAm[i * 17 + j] = __expf(E - m) / s;
    }
    __syncthreads();
    float mv[KK];
    #pragma unroll
    for (int jj = 0; jj < KK; jj++)
        mv[jj] = g_M[(size_t)(b * KK + jj) * DN + d];
    #pragma unroll
    for (int ii = 0; ii < KK; ii++) {
        const float* arow = sAm + ii * 17;
        float acc = 0.f;
        #pragma unroll
        for (int jj = 0; jj < KK; jj++) acc += arow[jj] * mv[jj];
        int row = b * KK + ii;
        float nv = g_V[(size_t)row * DN + d] + fmaxf(acc, 0.f);
        g_V[(size_t)row * DN + d] = nv;
        ((__half*)g_Abf2)[(size_t)row * KH + d] = __float2half_rn(nv);
        if (outV) outV[(size_t)row * DN + d] = nv;
    }
}

// ---------------- host ----------------------------------------------------
extern "C" void kernel_launch(void* const* d_in, const int* in_sizes, int n_in,
                              void* d_out, int out_size) {
    const float* w    = (const float*)d_in[0];
    const int*   mask = (const int*)  d_in[1];
    const float* nq   = (const float*)d_in[2];
    const float* Wq   = (const float*)d_in[3];
    const float* bq   = (const float*)d_in[4];
    const float* Wk   = (const float*)d_in[5];
    const float* bk   = (const float*)d_in[6];
    const float* Wv   = (const float*)d_in[7];
    const float* bv   = (const float*)d_in[8];
    const float* We1  = (const float*)d_in[9];
    const float* be1  = (const float*)d_in[10];
    const float* We2  = (const float*)d_in[11];
    const float* be2  = (const float*)d_in[12];
    const float* fg   = (const float*)d_in[13];
    const float* Wg   = (const float*)d_in[14];
    const float* bg   = (const float*)d_in[15];

    float* outS = (float*)d_out;
    float* outV = outS + (size_t)BB * NN * KK;
    float* outE = outV + (size_t)BB * KK * DN;

    kPrep<<<PREP_WH + PREP_SPLIT + PREP_KQ, 256>>>(w, Wv, Wg, We1, nq, Wq);
    kQr<<<48, 256>>>(bq);
    kP<<<96, 256>>>(Wk, bk);                                   // g_Pth fp16 + c
    kScoreG<<<154, 256>>>();                                   // scores via HMMA
    kU<<<dim3(BB, 4), 96>>>(mask, outS);                       // softmax + fp16 U

    kTGemm<<<dim3(32, 6), 256>>>(0, 0, 1, bv, nq, fg);         // V = U@Wv; fp16 V -> Abf2
    kTGemm<<<dim3(32, 14), 256>>>(1, 0, 3, bg, nullptr, nullptr);   // H = V@We1 AND M = V@Wg0+bg0
    kEdgeP<<<dim3(BB, 2), 256>>>(be1, We2);                    // partial E
    kMsg<<<dim3(BB, 3), 256>>>(be2, nullptr);                  // A inline; V += relu(A@M)
    kTGemm<<<dim3(32, 6), 256>>>(1, 2, 2, bg + DN, nullptr, nullptr); // M = V@Wg1+bg1
    kMsg<<<dim3(BB, 3), 256>>>(be2, outV);                     // final V; Abf2; outV
    kTGemm<<<dim3(32, 8), 256>>>(1, 3, 0, nullptr, nullptr, nullptr); // H on final V
    kEdgeP<<<dim3(BB, 2), 256>>>(be1, We2);                    // partial E (final V)
    kEdgeR<<<BB, 256>>>(be2, outE);                            // E -> out
}